// round 6
// baseline (speedup 1.0000x reference)
#include <cuda_runtime.h>
#include <math.h>

#define KDIM 4608
#define N0   512
#define WDC  0.0005f

// output layout (floats): new_e, new_s, L, hn, cn
#define O_E 0
#define O_S 16777216
#define O_L 19136512
#define O_H 40370176
#define O_C 40554496

// ---------------- scratch (device globals; no allocation allowed) ----------------
__device__ __align__(256) float g_M[KDIM * N0];      // M (4608x512)
__device__ __align__(256) float g_G[KDIM * N0];      // Mg -> G
__device__ __align__(256) float g_A[KDIM * N0];      // LG -> A = M+P -> Q1 -> Q2 (in place)
__device__ __align__(256) float g_S[N0 * N0];        // B = A^T A -> chol factor L (lower)
__device__ __align__(256) float g_Sym[N0 * N0];      // A_sym for projections
__device__ __align__(256) float g_part[4 * N0 * N0]; // split-K partials
__device__ __align__(256) float g_x[KDIM];
__device__ __align__(256) float g_lraw[KDIM];
__device__ float g_mean;

__device__ __forceinline__ float sigf(float z) { return 1.0f / (1.0f + expf(-z)); }

// ---------------- new_e = e - lr*(grad + wd*e) ----------------
__global__ void k_update_e(const float4* __restrict__ e, const float4* __restrict__ eg,
                           const float* __restrict__ e_lr, float4* __restrict__ out) {
    int i = blockIdx.x * 256 + threadIdx.x;
    float lr = *e_lr;
    float4 a = e[i], g = eg[i];
    float4 r;
    r.x = a.x - lr * (g.x + WDC * a.x);
    r.y = a.y - lr * (g.y + WDC * a.y);
    r.z = a.z - lr * (g.z + WDC * a.z);
    r.w = a.w - lr * (g.w + WDC * a.w);
    out[i] = r;
}

// ---------------- M = s.reshape(512,4608).T ; Mg = -s_lr * same(s_grad) ----------------
__global__ void k_make_MMg(const float* __restrict__ s, const float* __restrict__ sg,
                           const float* __restrict__ s_lr) {
    __shared__ float t0[32][33];
    __shared__ float t1[32][33];
    int iB = blockIdx.x * 32;  // over KDIM
    int jB = blockIdx.y * 32;  // over N0
    int tx = threadIdx.x, ty = threadIdx.y;
#pragma unroll
    for (int r = 0; r < 32; r += 8) {
        t0[ty + r][tx] = s [(jB + ty + r) * KDIM + iB + tx];
        t1[ty + r][tx] = sg[(jB + ty + r) * KDIM + iB + tx];
    }
    __syncthreads();
    float nslr = -(*s_lr);
#pragma unroll
    for (int r = 0; r < 32; r += 8) {
        int i = iB + ty + r;
        g_M[i * N0 + jB + tx] = t0[tx][ty + r];
        g_G[i * N0 + jB + tx] = nslr * t1[tx][ty + r];
    }
}

// ---------------- C(512x512) = A^T B (split-K=4 into g_part); sel: 0=g_M 1=g_A 2=g_G ----
__global__ void k_gemm_tn(int selA, int selB) {
    const float* A = (selA == 0) ? g_M : (selA == 1) ? g_A : g_G;
    const float* B = (selB == 0) ? g_M : (selB == 1) ? g_A : g_G;
    __shared__ __align__(16) float As[16][68];
    __shared__ __align__(16) float Bs[16][68];
    int a0 = blockIdx.x * 64, b0 = blockIdx.y * 64;
    int k0 = blockIdx.z * (KDIM / 4);
    int t = threadIdx.x, tx = t & 15, ty = t >> 4;
    int lr = t >> 4, lc = t & 15;
    float acc[4][4] = {};
    for (int kk = 0; kk < KDIM / 4; kk += 16) {
        float4 va = *(const float4*)&A[(k0 + kk + lr) * N0 + a0 + lc * 4];
        float4 vb = *(const float4*)&B[(k0 + kk + lr) * N0 + b0 + lc * 4];
        *(float4*)&As[lr][lc * 4] = va;
        *(float4*)&Bs[lr][lc * 4] = vb;
        __syncthreads();
#pragma unroll
        for (int k = 0; k < 16; k++) {
            float4 av = *(const float4*)&As[k][ty * 4];
            float4 bv = *(const float4*)&Bs[k][tx * 4];
            float a_[4] = {av.x, av.y, av.z, av.w};
            float b_[4] = {bv.x, bv.y, bv.z, bv.w};
#pragma unroll
            for (int u = 0; u < 4; u++)
#pragma unroll
                for (int v = 0; v < 4; v++) acc[u][v] += a_[u] * b_[v];
        }
        __syncthreads();
    }
    float* C = g_part + blockIdx.z * (N0 * N0);
#pragma unroll
    for (int u = 0; u < 4; u++)
#pragma unroll
        for (int v = 0; v < 4; v++)
            C[(a0 + ty * 4 + u) * N0 + (b0 + tx * 4 + v)] = acc[u][v];
}

// ---------------- reduce split-K + symmetrize: dst(0=g_Sym,1=g_S) = 0.5(C + C^T) --------
__global__ void k_reduce_sym(int dst) {
    int idx = blockIdx.x * 512 + threadIdx.x;
    int a = idx >> 9, b = idx & 511;
    float s1 = 0.f, s2 = 0.f;
#pragma unroll
    for (int z = 0; z < 4; z++) {
        s1 += g_part[z * N0 * N0 + idx];
        s2 += g_part[z * N0 * N0 + b * N0 + a];
    }
    float v = 0.5f * (s1 + s2);
    if (dst == 0) g_Sym[idx] = v; else g_S[idx] = v;
}

// ---------------- X = (addM? M:0) + X - M @ g_Sym ; xSel: 0=g_G 1=g_A ----------------
__global__ void k_proj_nn(int xSel, int addM) {
    float* X = xSel ? g_A : g_G;
    __shared__ __align__(16) float Ms[16][68];
    __shared__ __align__(16) float Ss[16][68];
    int i0 = blockIdx.x * 64, b0 = blockIdx.y * 64;
    int t = threadIdx.x, tx = t & 15, ty = t >> 4;
    int rr = t >> 2, c4 = t & 3;
    int r2 = t >> 4, c2 = t & 15;
    float acc[4][4] = {};
    for (int a0 = 0; a0 < N0; a0 += 16) {
        float4 v = *(const float4*)&g_M[(i0 + rr) * N0 + a0 + c4 * 4];
        Ms[c4 * 4 + 0][rr] = v.x; Ms[c4 * 4 + 1][rr] = v.y;
        Ms[c4 * 4 + 2][rr] = v.z; Ms[c4 * 4 + 3][rr] = v.w;
        *(float4*)&Ss[r2][c2 * 4] = *(const float4*)&g_Sym[(a0 + r2) * N0 + b0 + c2 * 4];
        __syncthreads();
#pragma unroll
        for (int k = 0; k < 16; k++) {
            float4 av = *(const float4*)&Ms[k][ty * 4];
            float4 bv = *(const float4*)&Ss[k][tx * 4];
            float a_[4] = {av.x, av.y, av.z, av.w};
            float b_[4] = {bv.x, bv.y, bv.z, bv.w};
#pragma unroll
            for (int u = 0; u < 4; u++)
#pragma unroll
                for (int v = 0; v < 4; v++) acc[u][v] += a_[u] * b_[v];
        }
        __syncthreads();
    }
#pragma unroll
    for (int u = 0; u < 4; u++)
#pragma unroll
        for (int v = 0; v < 4; v++) {
            int idx = (i0 + ty * 4 + u) * N0 + b0 + tx * 4 + v;
            float val = X[idx] - acc[u][v];
            if (addM) val += g_M[idx];
            X[idx] = val;
        }
}

// ---------------- x[i] = clip(log(|rowsumsq(G)|)/10, -1, 1) ----------------
__global__ void k_rowsq() {
    int gt = blockIdx.x * 256 + threadIdx.x;
    int row = gt >> 5, lane = gt & 31;
    const float4* rp = (const float4*)&g_G[row * N0];
    float s = 0.f;
#pragma unroll 4
    for (int c = lane; c < 128; c += 32) {
        float4 v = rp[c];
        s += v.x * v.x + v.y * v.y + v.z * v.z + v.w * v.w;
    }
#pragma unroll
    for (int o = 16; o; o >>= 1) s += __shfl_xor_sync(0xffffffffu, s, o);
    if (lane == 0) {
        float x = logf(fabsf(s)) * 0.1f;
        g_x[row] = fminf(1.0f, fmaxf(-1.0f, x));
    }
}

// ---------------- 2-layer LSTM (one step, batch=4608) + l_raw ----------------
__global__ void k_lstm(const float* __restrict__ Lh0, const float* __restrict__ Lc0,
                       const float* __restrict__ Wih0, const float* __restrict__ Whh0,
                       const float* __restrict__ bih0, const float* __restrict__ bhh0,
                       const float* __restrict__ Wih1, const float* __restrict__ Whh1,
                       const float* __restrict__ bih1, const float* __restrict__ bhh1,
                       const float* __restrict__ Wl, const float* __restrict__ bl,
                       float* __restrict__ out) {
    __shared__ float sWih0[80], sWhh0[1600], sb0[80];
    __shared__ float sWih1[1600], sWhh1[1600], sb1[80];
    __shared__ float sWl[20], sbl[1];
    int t = threadIdx.x;
    for (int i = t; i < 80; i += 256) {
        sWih0[i] = Wih0[i];
        sb0[i] = bih0[i] + bhh0[i];
        sb1[i] = bih1[i] + bhh1[i];
    }
    for (int i = t; i < 1600; i += 256) {
        sWhh0[i] = Whh0[i];
        sWih1[i] = Wih1[i];
        sWhh1[i] = Whh1[i];
    }
    if (t < 20) sWl[t] = Wl[t];
    if (t == 0) sbl[0] = bl[0];
    __syncthreads();

    int i = blockIdx.x * 256 + t;
    float x = g_x[i];
    float h0p[20], h1p[20], h0n[20];
#pragma unroll
    for (int h = 0; h < 20; h++) {
        h0p[h] = Lh0[i * 20 + h];
        h1p[h] = Lh0[92160 + i * 20 + h];
    }
    // layer 0
#pragma unroll
    for (int h = 0; h < 20; h++) {
        float pi = sb0[h]      + x * sWih0[h];
        float pf = sb0[20 + h] + x * sWih0[20 + h];
        float pg = sb0[40 + h] + x * sWih0[40 + h];
        float po = sb0[60 + h] + x * sWih0[60 + h];
#pragma unroll
        for (int m = 0; m < 20; m++) {
            float hm = h0p[m];
            pi += hm * sWhh0[h * 20 + m];
            pf += hm * sWhh0[(20 + h) * 20 + m];
            pg += hm * sWhh0[(40 + h) * 20 + m];
            po += hm * sWhh0[(60 + h) * 20 + m];
        }
        float c0 = Lc0[i * 20 + h];
        float c = sigf(pf) * c0 + sigf(pi) * tanhf(pg);
        float hh = sigf(po) * tanhf(c);
        h0n[h] = hh;
        out[O_H + i * 20 + h] = hh;
        out[O_C + i * 20 + h] = c;
    }
    // layer 1
    float lacc = sbl[0];
#pragma unroll
    for (int h = 0; h < 20; h++) {
        float pi = sb1[h], pf = sb1[20 + h], pg = sb1[40 + h], po = sb1[60 + h];
#pragma unroll
        for (int m = 0; m < 20; m++) {
            float a = h0n[m], b = h1p[m];
            pi += a * sWih1[h * 20 + m]        + b * sWhh1[h * 20 + m];
            pf += a * sWih1[(20 + h) * 20 + m] + b * sWhh1[(20 + h) * 20 + m];
            pg += a * sWih1[(40 + h) * 20 + m] + b * sWhh1[(40 + h) * 20 + m];
            po += a * sWih1[(60 + h) * 20 + m] + b * sWhh1[(60 + h) * 20 + m];
        }
        float c1 = Lc0[92160 + i * 20 + h];
        float c = sigf(pf) * c1 + sigf(pi) * tanhf(pg);
        float hh = sigf(po) * tanhf(c);
        out[O_H + 92160 + i * 20 + h] = hh;
        out[O_C + 92160 + i * 20 + h] = c;
        lacc += hh * sWl[h];
    }
    g_lraw[i] = lacc * 0.1f;
}

__global__ void k_mean() {
    __shared__ float sm[256];
    int t = threadIdx.x;
    float s = 0.f;
    for (int i = t; i < KDIM; i += 256) s += g_lraw[i];
    sm[t] = s;
    __syncthreads();
    for (int o = 128; o; o >>= 1) {
        if (t < o) sm[t] += sm[t + o];
        __syncthreads();
    }
    if (t == 0) g_mean = sm[0] * (1.0f / KDIM);
}

// ---------------- L[i][j] = max( (i==j)? l_i : 0 , L_before[i][j] ) ----------------
__global__ void k_build_L(const float4* __restrict__ Lb, float4* __restrict__ outL) {
    int gid = blockIdx.x * 256 + threadIdx.x;
    int base = gid * 4;
    int i = base / KDIM;
    int j0 = base - i * KDIM;
    float dv = g_lraw[i] - g_mean + 1.0f;
    float4 lb = Lb[gid];
    float4 r;
    r.x = fmaxf((j0 + 0 == i) ? dv : 0.0f, lb.x);
    r.y = fmaxf((j0 + 1 == i) ? dv : 0.0f, lb.y);
    r.z = fmaxf((j0 + 2 == i) ? dv : 0.0f, lb.z);
    r.w = fmaxf((j0 + 3 == i) ? dv : 0.0f, lb.w);
    outL[gid] = r;
}

// ---------------- g_A = L(4608x4608) @ G(4608x512) ----------------
__global__ void k_gemm_LG(const float* __restrict__ Lm) {
    __shared__ __align__(16) float Ls[16][68];
    __shared__ __align__(16) float Gs[16][68];
    int i0 = blockIdx.x * 64, b0 = blockIdx.y * 64;
    int t = threadIdx.x, tx = t & 15, ty = t >> 4;
    int rr = t >> 2, c4 = t & 3;
    int r2 = t >> 4, c2 = t & 15;
    float acc[4][4] = {};
    for (int k0 = 0; k0 < KDIM; k0 += 16) {
        float4 v = *(const float4*)&Lm[(i0 + rr) * KDIM + k0 + c4 * 4];
        Ls[c4 * 4 + 0][rr] = v.x; Ls[c4 * 4 + 1][rr] = v.y;
        Ls[c4 * 4 + 2][rr] = v.z; Ls[c4 * 4 + 3][rr] = v.w;
        *(float4*)&Gs[r2][c2 * 4] = *(const float4*)&g_G[(k0 + r2) * N0 + b0 + c2 * 4];
        __syncthreads();
#pragma unroll
        for (int k = 0; k < 16; k++) {
            float4 av = *(const float4*)&Ls[k][ty * 4];
            float4 bv = *(const float4*)&Gs[k][tx * 4];
            float a_[4] = {av.x, av.y, av.z, av.w};
            float b_[4] = {bv.x, bv.y, bv.z, bv.w};
#pragma unroll
            for (int u = 0; u < 4; u++)
#pragma unroll
                for (int v2 = 0; v2 < 4; v2++) acc[u][v2] += a_[u] * b_[v2];
        }
        __syncthreads();
    }
#pragma unroll
    for (int u = 0; u < 4; u++)
#pragma unroll
        for (int v2 = 0; v2 < 4; v2++)
            g_A[(i0 + ty * 4 + u) * N0 + b0 + tx * 4 + v2] = acc[u][v2];
}

// ---------------- blocked Cholesky of g_S (512, lower), panel 64 ----------------
__global__ void k_chol_diag(int p) {
    __shared__ float D[64][65];
    int t = threadIdx.x;
    for (int idx = t; idx < 4096; idx += 256) {
        int i = idx >> 6, j = idx & 63;
        D[i][j] = g_S[(p * 64 + i) * N0 + p * 64 + j];
    }
    __syncthreads();
    for (int j = 0; j < 64; j++) {
        if (t == 0) D[j][j] = sqrtf(D[j][j]);
        __syncthreads();
        float dj = D[j][j];
        for (int i = j + 1 + t; i < 64; i += 256) D[i][j] /= dj;
        __syncthreads();
        for (int idx = t; idx < 4096; idx += 256) {
            int i = idx >> 6, kc = idx & 63;
            if (kc > j && i >= kc) D[i][kc] -= D[i][j] * D[kc][j];
        }
        __syncthreads();
    }
    for (int idx = t; idx < 4096; idx += 256) {
        int i = idx >> 6, j = idx & 63;
        g_S[(p * 64 + i) * N0 + p * 64 + j] = D[i][j];
    }
}

__global__ void k_chol_offdiag(int p) {
    __shared__ float C[64][65];
    __shared__ float Dg[64][65];
    int rb = p + 1 + blockIdx.x;
    int t = threadIdx.x;
    for (int idx = t; idx < 4096; idx += 256) {
        int i = idx >> 6, j = idx & 63;
        C[i][j]  = g_S[(rb * 64 + i) * N0 + p * 64 + j];
        Dg[i][j] = g_S[(p * 64 + i) * N0 + p * 64 + j];
    }
    __syncthreads();
    for (int j = 0; j < 64; j++) {
        float inv = 1.0f / Dg[j][j];
        if (t < 64) C[t][j] *= inv;
        __syncthreads();
        for (int idx = t; idx < 4096; idx += 256) {
            int i = idx >> 6, jj = idx & 63;
            if (jj > j) C[i][jj] -= C[i][j] * Dg[jj][j];
        }
        __syncthreads();
    }
    for (int idx = t; idx < 4096; idx += 256) {
        int i = idx >> 6, j = idx & 63;
        g_S[(rb * 64 + i) * N0 + p * 64 + j] = C[i][j];
    }
}

__global__ void k_chol_syrk(int p) {
    __shared__ float Li[64][65];
    __shared__ float Lj[64][65];
    int t7 = 7 - p;
    int q = blockIdx.x, bj = 0;
    while (q >= t7 - bj) { q -= t7 - bj; bj++; }
    int bi = bj + q;
    int gi = p + 1 + bi, gj = p + 1 + bj;
    int t = threadIdx.x;
    for (int idx = t; idx < 4096; idx += 256) {
        int i = idx >> 6, k = idx & 63;
        Li[i][k] = g_S[(gi * 64 + i) * N0 + p * 64 + k];
        Lj[i][k] = g_S[(gj * 64 + i) * N0 + p * 64 + k];
    }
    __syncthreads();
    int ty = t >> 4, tx = t & 15;
#pragma unroll
    for (int u = 0; u < 4; u++)
#pragma unroll
        for (int v = 0; v < 4; v++) {
            float acc = 0.f;
#pragma unroll 8
            for (int k = 0; k < 64; k++) acc += Li[ty * 4 + u][k] * Lj[tx * 4 + v][k];
            g_S[(gi * 64 + ty * 4 + u) * N0 + gj * 64 + tx * 4 + v] -= acc;
        }
}

// ---------------- Q = A R^{-1} (R = L^T), blocked forward TRSM, in place on g_A -------
__global__ void k_qpanel(int p) {
    __shared__ __align__(16) float Qs[16][68];
    __shared__ __align__(16) float Rs[16][68];
    __shared__ float Cs[64][68];
    __shared__ float Ds[64][65];
    int i0 = blockIdx.x * 64;
    int t = threadIdx.x, tx = t & 15, ty = t >> 4;
    int rr = t >> 2, c4 = t & 3;
    float acc[4][4];
#pragma unroll
    for (int u = 0; u < 4; u++)
#pragma unroll
        for (int v = 0; v < 4; v++)
            acc[u][v] = g_A[(i0 + ty * 4 + u) * N0 + p * 64 + tx * 4 + v];
    for (int kb = 0; kb < p * 64; kb += 16) {
        float4 v = *(const float4*)&g_A[(i0 + rr) * N0 + kb + c4 * 4];
        Qs[c4 * 4 + 0][rr] = v.x; Qs[c4 * 4 + 1][rr] = v.y;
        Qs[c4 * 4 + 2][rr] = v.z; Qs[c4 * 4 + 3][rr] = v.w;
        float4 w = *(const float4*)&g_S[(p * 64 + rr) * N0 + kb + c4 * 4];
        Rs[c4 * 4 + 0][rr] = w.x; Rs[c4 * 4 + 1][rr] = w.y;
        Rs[c4 * 4 + 2][rr] = w.z; Rs[c4 * 4 + 3][rr] = w.w;
        __syncthreads();
#pragma unroll
        for (int k = 0; k < 16; k++) {
            float4 av = *(const float4*)&Qs[k][ty * 4];
            float4 bv = *(const float4*)&Rs[k][tx * 4];
            float a_[4] = {av.x, av.y, av.z, av.w};
            float b_[4] = {bv.x, bv.y, bv.z, bv.w};
#pragma unroll
            for (int u = 0; u < 4; u++)
#pragma unroll
                for (int v2 = 0; v2 < 4; v2++) acc[u][v2] -= a_[u] * b_[v2];
        }
        __syncthreads();
    }
#pragma unroll
    for (int u = 0; u < 4; u++)
#pragma unroll
        for (int v = 0; v < 4; v++)
            Cs[ty * 4 + u][tx * 4 + v] = acc[u][v];
    for (int idx = t; idx < 4096; idx += 256) {
        int m = idx >> 6, j = idx & 63;
        Ds[m][j] = g_S[(p * 64 + j) * N0 + p * 64 + m];  // R[m][j] = L[j][m]
    }
    __syncthreads();
    for (int j = 0; j < 64; j++) {
        float inv = 1.0f / Ds[j][j];
        if (t < 64) Cs[t][j] *= inv;
        __syncthreads();
        for (int idx = t; idx < 4096; idx += 256) {
            int i = idx >> 6, jj = idx & 63;
            if (jj > j) Cs[i][jj] -= Cs[i][j] * Ds[j][jj];
        }
        __syncthreads();
    }
    for (int idx = t; idx < 4096; idx += 256) {
        int i = idx >> 6, j = idx & 63;
        g_A[(i0 + i) * N0 + p * 64 + j] = Cs[i][j];
    }
}

// ---------------- new_s = Q^T reshaped (transpose 4608x512 -> 512x4608) ----------------
__global__ void k_write_s(float* __restrict__ outS) {
    __shared__ float tile[32][33];
    int kB = blockIdx.x * 32, nB = blockIdx.y * 32;
    int tx = threadIdx.x, ty = threadIdx.y;
#pragma unroll
    for (int r = 0; r < 32; r += 8)
        tile[ty + r][tx] = g_A[(kB + ty + r) * N0 + nB + tx];
    __syncthreads();
#pragma unroll
    for (int r = 0; r < 32; r += 8)
        outS[(nB + ty + r) * KDIM + kB + tx] = tile[tx][ty + r];
}

static void run_cholqr_pass() {
    // Gram: g_S = sym(A^T A)
    k_gemm_tn<<<dim3(8, 8, 4), 256>>>(1, 1);
    k_reduce_sym<<<512, 512>>>(1);
    // Cholesky g_S = L L^T (lower), blocked
    for (int p = 0; p < 8; p++) {
        k_chol_diag<<<1, 256>>>(p);
        if (p < 7) {
            k_chol_offdiag<<<7 - p, 256>>>(p);
            int t7 = 7 - p;
            k_chol_syrk<<<t7 * (t7 + 1) / 2, 256>>>(p);
        }
    }
    // A <- A R^{-1}, panel forward substitution (in place on g_A)
    for (int p = 0; p < 8; p++) k_qpanel<<<72, 256>>>(p);
}

extern "C" void kernel_launch(void* const* d_in, const int* in_sizes, int n_in,
                              void* d_out, int out_size) {
    const float* e    = (const float*)d_in[0];
    const float* eg   = (const float*)d_in[1];
    const float* s    = (const float*)d_in[2];
    const float* sg   = (const float*)d_in[3];
    const float* Lh0  = (const float*)d_in[4];
    const float* Lc0  = (const float*)d_in[5];
    const float* Lb   = (const float*)d_in[6];
    const float* Wih0 = (const float*)d_in[7];
    const float* Whh0 = (const float*)d_in[8];
    const float* bih0 = (const float*)d_in[9];
    const float* bhh0 = (const float*)d_in[10];
    const float* Wih1 = (const float*)d_in[11];
    const float* Whh1 = (const float*)d_in[12];
    const float* bih1 = (const float*)d_in[13];
    const float* bhh1 = (const float*)d_in[14];
    const float* Wl   = (const float*)d_in[15];
    const float* bl   = (const float*)d_in[16];
    const float* e_lr = (const float*)d_in[17];
    const float* s_lr = (const float*)d_in[18];
    float* out = (float*)d_out;

    // new_e (independent)
    k_update_e<<<16384, 256>>>((const float4*)e, (const float4*)eg, e_lr,
                               (float4*)(out + O_E));
    // build M, Mg
    k_make_MMg<<<dim3(144, 16), dim3(32, 8)>>>(s, sg, s_lr);
    // G = Mg - M @ sym(M^T Mg)
    k_gemm_tn<<<dim3(8, 8, 4), 256>>>(0, 2);
    k_reduce_sym<<<512, 512>>>(0);
    k_proj_nn<<<dim3(72, 8), 256>>>(0, 0);
    // LogAndSign input
    k_rowsq<<<576, 256>>>();
    // LSTM + l + mean + L
    k_lstm<<<18, 256>>>(Lh0, Lc0, Wih0, Whh0, bih0, bhh0,
                        Wih1, Whh1, bih1, bhh1, Wl, bl, out);
    k_mean<<<1, 256>>>();
    k_build_L<<<20736, 256>>>((const float4*)Lb, (float4*)(out + O_L));
    // LG, then A = M + proj(M, LG)
    k_gemm_LG<<<dim3(72, 8), 256>>>(out + O_L);
    k_gemm_tn<<<dim3(8, 8, 4), 256>>>(0, 1);
    k_reduce_sym<<<512, 512>>>(0);
    k_proj_nn<<<dim3(72, 8), 256>>>(1, 1);
    // CholeskyQR2: two passes of (Gram -> Cholesky -> TRSM)
    run_cholqr_pass();   // Q1 = A R1^{-1}
    run_cholqr_pass();   // Q2 = Q1 R2^{-1}  (Householder-level accuracy)
    // new_s
    k_write_s<<<dim3(144, 16), dim3(32, 8)>>>(out + O_S);
}

// round 10
// speedup vs baseline: 1.0952x; 1.0952x over previous
#include <cuda_runtime.h>
#include <cuda_bf16.h>
#include <math.h>
#include <stdint.h>

#define KDIM 4608
#define N0   512
#define WDC  0.0005f

// output layout (floats): new_e, new_s, L, hn, cn
#define O_E 0
#define O_S 16777216
#define O_L 19136512
#define O_H 40370176
#define O_C 40554496

// ---------------- scratch (device globals; no allocation allowed) ----------------
__device__ __align__(256) float g_M[KDIM * N0];      // M (4608x512)
__device__ __align__(256) float g_G[KDIM * N0];      // Mg -> G
__device__ __align__(256) float g_A[KDIM * N0];      // LG -> A = M+P -> Q1 -> Q2 (in place)
__device__ __align__(256) float g_S[N0 * N0];        // Gram -> chol factor L (lower)
__device__ __align__(256) float g_Sym[N0 * N0];      // A_sym for projections
__device__ __align__(256) float g_part[4 * N0 * N0]; // split-K partials
__device__ __align__(256) float g_x[KDIM];
__device__ __align__(256) float g_lraw[KDIM];
__device__ float g_mean;
__device__ __align__(256) __nv_bfloat16 g_Lhi[(size_t)KDIM * KDIM];  // L hi bf16
__device__ __align__(256) __nv_bfloat16 g_Llo[(size_t)KDIM * KDIM];  // L lo bf16
__device__ __align__(256) __nv_bfloat16 g_Gthi[(size_t)N0 * KDIM];   // G^T hi
__device__ __align__(256) __nv_bfloat16 g_Gtlo[(size_t)N0 * KDIM];   // G^T lo

__device__ __forceinline__ float sigf(float z) { return 1.0f / (1.0f + expf(-z)); }

// ---------------- new_e = e - lr*(grad + wd*e) ----------------
__global__ void k_update_e(const float4* __restrict__ e, const float4* __restrict__ eg,
                           const float* __restrict__ e_lr, float4* __restrict__ out) {
    int i = blockIdx.x * 256 + threadIdx.x;
    float lr = *e_lr;
    float4 a = e[i], g = eg[i];
    float4 r;
    r.x = a.x - lr * (g.x + WDC * a.x);
    r.y = a.y - lr * (g.y + WDC * a.y);
    r.z = a.z - lr * (g.z + WDC * a.z);
    r.w = a.w - lr * (g.w + WDC * a.w);
    out[i] = r;
}

// ---------------- M = s.reshape(512,4608).T ; Mg = -s_lr * same(s_grad) ----------------
__global__ void k_make_MMg(const float* __restrict__ s, const float* __restrict__ sg,
                           const float* __restrict__ s_lr) {
    __shared__ float t0[32][33];
    __shared__ float t1[32][33];
    int iB = blockIdx.x * 32, jB = blockIdx.y * 32;
    int tx = threadIdx.x, ty = threadIdx.y;
#pragma unroll
    for (int r = 0; r < 32; r += 8) {
        t0[ty + r][tx] = s [(jB + ty + r) * KDIM + iB + tx];
        t1[ty + r][tx] = sg[(jB + ty + r) * KDIM + iB + tx];
    }
    __syncthreads();
    float nslr = -(*s_lr);
#pragma unroll
    for (int r = 0; r < 32; r += 8) {
        int i = iB + ty + r;
        g_M[i * N0 + jB + tx] = t0[tx][ty + r];
        g_G[i * N0 + jB + tx] = nslr * t1[tx][ty + r];
    }
}

// ---------------- C(512x512) = A^T B (split-K=4); sel: 0=g_M 1=g_A 2=g_G ----------------
__global__ void k_gemm_tn(int selA, int selB) {
    const float* A = (selA == 0) ? g_M : (selA == 1) ? g_A : g_G;
    const float* B = (selB == 0) ? g_M : (selB == 1) ? g_A : g_G;
    __shared__ __align__(16) float As[16][68];
    __shared__ __align__(16) float Bs[16][68];
    int a0 = blockIdx.x * 64, b0 = blockIdx.y * 64;
    int k0 = blockIdx.z * (KDIM / 4);
    int t = threadIdx.x, tx = t & 15, ty = t >> 4;
    int lr = t >> 4, lc = t & 15;
    float acc[4][4] = {};
    for (int kk = 0; kk < KDIM / 4; kk += 16) {
        float4 va = *(const float4*)&A[(k0 + kk + lr) * N0 + a0 + lc * 4];
        float4 vb = *(const float4*)&B[(k0 + kk + lr) * N0 + b0 + lc * 4];
        *(float4*)&As[lr][lc * 4] = va;
        *(float4*)&Bs[lr][lc * 4] = vb;
        __syncthreads();
#pragma unroll
        for (int k = 0; k < 16; k++) {
            float4 av = *(const float4*)&As[k][ty * 4];
            float4 bv = *(const float4*)&Bs[k][tx * 4];
            float a_[4] = {av.x, av.y, av.z, av.w};
            float b_[4] = {bv.x, bv.y, bv.z, bv.w};
#pragma unroll
            for (int u = 0; u < 4; u++)
#pragma unroll
                for (int v = 0; v < 4; v++) acc[u][v] += a_[u] * b_[v];
        }
        __syncthreads();
    }
    float* C = g_part + blockIdx.z * (N0 * N0);
#pragma unroll
    for (int u = 0; u < 4; u++)
#pragma unroll
        for (int v = 0; v < 4; v++)
            C[(a0 + ty * 4 + u) * N0 + (b0 + tx * 4 + v)] = acc[u][v];
}

// ---------------- reduce split-K + symmetrize: dst(0=g_Sym,1=g_S) ----------------
__global__ void k_reduce_sym(int dst) {
    int idx = blockIdx.x * 512 + threadIdx.x;
    int a = idx >> 9, b = idx & 511;
    float s1 = 0.f, s2 = 0.f;
#pragma unroll
    for (int z = 0; z < 4; z++) {
        s1 += g_part[z * N0 * N0 + idx];
        s2 += g_part[z * N0 * N0 + b * N0 + a];
    }
    float v = 0.5f * (s1 + s2);
    if (dst == 0) g_Sym[idx] = v; else g_S[idx] = v;
}

// ---------------- X = (addM? M:0) + X - M @ g_Sym ; xSel: 0=g_G 1=g_A ----------------
__global__ void k_proj_nn(int xSel, int addM) {
    float* X = xSel ? g_A : g_G;
    __shared__ __align__(16) float Ms[16][68];
    __shared__ __align__(16) float Ss[16][68];
    int i0 = blockIdx.x * 64, b0 = blockIdx.y * 64;
    int t = threadIdx.x, tx = t & 15, ty = t >> 4;
    int rr = t >> 2, c4 = t & 3;
    int r2 = t >> 4, c2 = t & 15;
    float acc[4][4] = {};
    for (int a0 = 0; a0 < N0; a0 += 16) {
        float4 v = *(const float4*)&g_M[(i0 + rr) * N0 + a0 + c4 * 4];
        Ms[c4 * 4 + 0][rr] = v.x; Ms[c4 * 4 + 1][rr] = v.y;
        Ms[c4 * 4 + 2][rr] = v.z; Ms[c4 * 4 + 3][rr] = v.w;
        *(float4*)&Ss[r2][c2 * 4] = *(const float4*)&g_Sym[(a0 + r2) * N0 + b0 + c2 * 4];
        __syncthreads();
#pragma unroll
        for (int k = 0; k < 16; k++) {
            float4 av = *(const float4*)&Ms[k][ty * 4];
            float4 bv = *(const float4*)&Ss[k][tx * 4];
            float a_[4] = {av.x, av.y, av.z, av.w};
            float b_[4] = {bv.x, bv.y, bv.z, bv.w};
#pragma unroll
            for (int u = 0; u < 4; u++)
#pragma unroll
                for (int v = 0; v < 4; v++) acc[u][v] += a_[u] * b_[v];
        }
        __syncthreads();
    }
#pragma unroll
    for (int u = 0; u < 4; u++)
#pragma unroll
        for (int v = 0; v < 4; v++) {
            int idx = (i0 + ty * 4 + u) * N0 + b0 + tx * 4 + v;
            float val = X[idx] - acc[u][v];
            if (addM) val += g_M[idx];
            X[idx] = val;
        }
}

// ---------------- x[i] = clip(log(|rowsumsq(G)|)/10, -1, 1) ----------------
__global__ void k_rowsq() {
    int gt = blockIdx.x * 256 + threadIdx.x;
    int row = gt >> 5, lane = gt & 31;
    const float4* rp = (const float4*)&g_G[row * N0];
    float s = 0.f;
#pragma unroll 4
    for (int c = lane; c < 128; c += 32) {
        float4 v = rp[c];
        s += v.x * v.x + v.y * v.y + v.z * v.z + v.w * v.w;
    }
#pragma unroll
    for (int o = 16; o; o >>= 1) s += __shfl_xor_sync(0xffffffffu, s, o);
    if (lane == 0) {
        float x = logf(fabsf(s)) * 0.1f;
        g_x[row] = fminf(1.0f, fmaxf(-1.0f, x));
    }
}

// ---------------- 2-layer LSTM (one step, batch=4608) + l_raw ----------------
__global__ void k_lstm(const float* __restrict__ Lh0, const float* __restrict__ Lc0,
                       const float* __restrict__ Wih0, const float* __restrict__ Whh0,
                       const float* __restrict__ bih0, const float* __restrict__ bhh0,
                       const float* __restrict__ Wih1, const float* __restrict__ Whh1,
                       const float* __restrict__ bih1, const float* __restrict__ bhh1,
                       const float* __restrict__ Wl, const float* __restrict__ bl,
                       float* __restrict__ out) {
    __shared__ float sWih0[80], sWhh0[1600], sb0[80];
    __shared__ float sWih1[1600], sWhh1[1600], sb1[80];
    __shared__ float sWl[20], sbl[1];
    int t = threadIdx.x;
    for (int i = t; i < 80; i += 256) {
        sWih0[i] = Wih0[i];
        sb0[i] = bih0[i] + bhh0[i];
        sb1[i] = bih1[i] + bhh1[i];
    }
    for (int i = t; i < 1600; i += 256) {
        sWhh0[i] = Whh0[i];
        sWih1[i] = Wih1[i];
        sWhh1[i] = Whh1[i];
    }
    if (t < 20) sWl[t] = Wl[t];
    if (t == 0) sbl[0] = bl[0];
    __syncthreads();

    int i = blockIdx.x * 256 + t;
    float x = g_x[i];
    float h0p[20], h1p[20], h0n[20];
#pragma unroll
    for (int h = 0; h < 20; h++) {
        h0p[h] = Lh0[i * 20 + h];
        h1p[h] = Lh0[92160 + i * 20 + h];
    }
#pragma unroll
    for (int h = 0; h < 20; h++) {
        float pi = sb0[h]      + x * sWih0[h];
        float pf = sb0[20 + h] + x * sWih0[20 + h];
        float pg = sb0[40 + h] + x * sWih0[40 + h];
        float po = sb0[60 + h] + x * sWih0[60 + h];
#pragma unroll
        for (int m = 0; m < 20; m++) {
            float hm = h0p[m];
            pi += hm * sWhh0[h * 20 + m];
            pf += hm * sWhh0[(20 + h) * 20 + m];
            pg += hm * sWhh0[(40 + h) * 20 + m];
            po += hm * sWhh0[(60 + h) * 20 + m];
        }
        float c0 = Lc0[i * 20 + h];
        float c = sigf(pf) * c0 + sigf(pi) * tanhf(pg);
        float hh = sigf(po) * tanhf(c);
        h0n[h] = hh;
        out[O_H + i * 20 + h] = hh;
        out[O_C + i * 20 + h] = c;
    }
    float lacc = sbl[0];
#pragma unroll
    for (int h = 0; h < 20; h++) {
        float pi = sb1[h], pf = sb1[20 + h], pg = sb1[40 + h], po = sb1[60 + h];
#pragma unroll
        for (int m = 0; m < 20; m++) {
            float a = h0n[m], b = h1p[m];
            pi += a * sWih1[h * 20 + m]        + b * sWhh1[h * 20 + m];
            pf += a * sWih1[(20 + h) * 20 + m] + b * sWhh1[(20 + h) * 20 + m];
            pg += a * sWih1[(40 + h) * 20 + m] + b * sWhh1[(40 + h) * 20 + m];
            po += a * sWih1[(60 + h) * 20 + m] + b * sWhh1[(60 + h) * 20 + m];
        }
        float c1 = Lc0[92160 + i * 20 + h];
        float c = sigf(pf) * c1 + sigf(pi) * tanhf(pg);
        float hh = sigf(po) * tanhf(c);
        out[O_H + 92160 + i * 20 + h] = hh;
        out[O_C + 92160 + i * 20 + h] = c;
        lacc += hh * sWl[h];
    }
    g_lraw[i] = lacc * 0.1f;
}

__global__ void k_mean() {
    __shared__ float sm[256];
    int t = threadIdx.x;
    float s = 0.f;
    for (int i = t; i < KDIM; i += 256) s += g_lraw[i];
    sm[t] = s;
    __syncthreads();
    for (int o = 128; o; o >>= 1) {
        if (t < o) sm[t] += sm[t + o];
        __syncthreads();
    }
    if (t == 0) g_mean = sm[0] * (1.0f / KDIM);
}

// ---------------- L (fp32 out + split-bf16 hi/lo copies for MMA) ----------------
__global__ void k_build_L(const float4* __restrict__ Lb, float4* __restrict__ outL) {
    int gid = blockIdx.x * 256 + threadIdx.x;
    int base = gid * 4;
    int i = base / KDIM;
    int j0 = base - i * KDIM;
    float dv = g_lraw[i] - g_mean + 1.0f;
    float4 lb = Lb[gid];
    float4 r;
    r.x = fmaxf((j0 + 0 == i) ? dv : 0.0f, lb.x);
    r.y = fmaxf((j0 + 1 == i) ? dv : 0.0f, lb.y);
    r.z = fmaxf((j0 + 2 == i) ? dv : 0.0f, lb.z);
    r.w = fmaxf((j0 + 3 == i) ? dv : 0.0f, lb.w);
    outL[gid] = r;
    __nv_bfloat16 hx = __float2bfloat16(r.x), hy = __float2bfloat16(r.y);
    __nv_bfloat16 hz = __float2bfloat16(r.z), hw = __float2bfloat16(r.w);
    __nv_bfloat162* ph = (__nv_bfloat162*)g_Lhi;
    __nv_bfloat162* pl = (__nv_bfloat162*)g_Llo;
    ph[2 * gid]     = __nv_bfloat162(hx, hy);
    ph[2 * gid + 1] = __nv_bfloat162(hz, hw);
    pl[2 * gid]     = __nv_bfloat162(__float2bfloat16(r.x - __bfloat162float(hx)),
                                     __float2bfloat16(r.y - __bfloat162float(hy)));
    pl[2 * gid + 1] = __nv_bfloat162(__float2bfloat16(r.z - __bfloat162float(hz)),
                                     __float2bfloat16(r.w - __bfloat162float(hw)));
}

// ---------------- Gt hi/lo [n][k] = split-bf16(G[k][n]) ----------------
__global__ void k_gt() {
    __shared__ float tile[32][33];
    int kB = blockIdx.x * 32, nB = blockIdx.y * 32;
    int tx = threadIdx.x, ty = threadIdx.y;
#pragma unroll
    for (int r = 0; r < 32; r += 8)
        tile[ty + r][tx] = g_G[(kB + ty + r) * N0 + nB + tx];
    __syncthreads();
#pragma unroll
    for (int r = 0; r < 32; r += 8) {
        float v = tile[tx][ty + r];
        __nv_bfloat16 h = __float2bfloat16(v);
        size_t idx = (size_t)(nB + ty + r) * KDIM + kB + tx;
        g_Gthi[idx] = h;
        g_Gtlo[idx] = __float2bfloat16(v - __bfloat162float(h));
    }
}

// ---- g_A = L @ G via split-bf16 HMMA: Lhi*Ghi + Lhi*Glo + Llo*Ghi (128x64/CTA) ----
__global__ void __launch_bounds__(256) k_lg_mma() {
    __shared__ __align__(16) __nv_bfloat16 Ah[128][40];
    __shared__ __align__(16) __nv_bfloat16 Al[128][40];
    __shared__ __align__(16) __nv_bfloat16 Bh[64][40];
    __shared__ __align__(16) __nv_bfloat16 Bl[64][40];
    int t = threadIdx.x, wid = t >> 5, lane = t & 31;
    int i0 = blockIdx.x * 128, n0t = blockIdx.y * 64;
    int wy = wid >> 1, wx = wid & 1;  // warp tile: 32 rows x 32 cols
    float acc[2][4][4];
#pragma unroll
    for (int mb = 0; mb < 2; mb++)
#pragma unroll
        for (int nb = 0; nb < 4; nb++)
#pragma unroll
            for (int q = 0; q < 4; q++) acc[mb][nb][q] = 0.f;

    int ar0 = t >> 2, ac0 = (t & 3) * 8;   // rows 0..63
    int ar1 = ar0 + 64;                    // rows 64..127
    uint4 vAh0 = *(const uint4*)(g_Lhi + (size_t)(i0 + ar0) * KDIM + ac0);
    uint4 vAh1 = *(const uint4*)(g_Lhi + (size_t)(i0 + ar1) * KDIM + ac0);
    uint4 vAl0 = *(const uint4*)(g_Llo + (size_t)(i0 + ar0) * KDIM + ac0);
    uint4 vAl1 = *(const uint4*)(g_Llo + (size_t)(i0 + ar1) * KDIM + ac0);
    uint4 vBh  = *(const uint4*)(g_Gthi + (size_t)(n0t + ar0) * KDIM + ac0);
    uint4 vBl  = *(const uint4*)(g_Gtlo + (size_t)(n0t + ar0) * KDIM + ac0);

    int gr = lane >> 2, lc2 = (lane & 3) * 2;
    for (int k0 = 0; k0 < KDIM; k0 += 32) {
        *(uint4*)&Ah[ar0][ac0] = vAh0;
        *(uint4*)&Ah[ar1][ac0] = vAh1;
        *(uint4*)&Al[ar0][ac0] = vAl0;
        *(uint4*)&Al[ar1][ac0] = vAl1;
        *(uint4*)&Bh[ar0][ac0] = vBh;
        *(uint4*)&Bl[ar0][ac0] = vBl;
        __syncthreads();
        if (k0 + 32 < KDIM) {
            size_t koff = (size_t)(k0 + 32 + ac0);
            vAh0 = *(const uint4*)(g_Lhi + (size_t)(i0 + ar0) * KDIM + koff);
            vAh1 = *(const uint4*)(g_Lhi + (size_t)(i0 + ar1) * KDIM + koff);
            vAl0 = *(const uint4*)(g_Llo + (size_t)(i0 + ar0) * KDIM + koff);
            vAl1 = *(const uint4*)(g_Llo + (size_t)(i0 + ar1) * KDIM + koff);
            vBh  = *(const uint4*)(g_Gthi + (size_t)(n0t + ar0) * KDIM + koff);
            vBl  = *(const uint4*)(g_Gtlo + (size_t)(n0t + ar0) * KDIM + koff);
        }
#pragma unroll
        for (int kk = 0; kk < 32; kk += 16) {
            uint32_t ah[2][4], al[2][4], bh[4][2], bl[4][2];
#pragma unroll
            for (int mb = 0; mb < 2; mb++) {
                int r = wy * 32 + mb * 16 + gr;
                ah[mb][0] = *(const uint32_t*)&Ah[r][kk + lc2];
                ah[mb][1] = *(const uint32_t*)&Ah[r + 8][kk + lc2];
                ah[mb][2] = *(const uint32_t*)&Ah[r][kk + lc2 + 8];
                ah[mb][3] = *(const uint32_t*)&Ah[r + 8][kk + lc2 + 8];
                al[mb][0] = *(const uint32_t*)&Al[r][kk + lc2];
                al[mb][1] = *(const uint32_t*)&Al[r + 8][kk + lc2];
                al[mb][2] = *(const uint32_t*)&Al[r][kk + lc2 + 8];
                al[mb][3] = *(const uint32_t*)&Al[r + 8][kk + lc2 + 8];
            }
#pragma unroll
            for (int nb = 0; nb < 4; nb++) {
                int bn = wx * 32 + nb * 8 + gr;
                bh[nb][0] = *(const uint32_t*)&Bh[bn][kk + lc2];
                bh[nb][1] = *(const uint32_t*)&Bh[bn][kk + lc2 + 8];
                bl[nb][0] = *(const uint32_t*)&Bl[bn][kk + lc2];
                bl[nb][1] = *(const uint32_t*)&Bl[bn][kk + lc2 + 8];
            }
#define MMA16(ACC, AV, BV)                                                       \
    asm volatile("mma.sync.aligned.m16n8k16.row.col.f32.bf16.bf16.f32 "          \
                 "{%0,%1,%2,%3}, {%4,%5,%6,%7}, {%8,%9}, {%0,%1,%2,%3};"         \
                 : "+f"((ACC)[0]), "+f"((ACC)[1]), "+f"((ACC)[2]), "+f"((ACC)[3])\
                 : "r"((AV)[0]), "r"((AV)[1]), "r"((AV)[2]), "r"((AV)[3]),       \
                   "r"((BV)[0]), "r"((BV)[1]))
#pragma unroll
            for (int mb = 0; mb < 2; mb++)
#pragma unroll
                for (int nb = 0; nb < 4; nb++) {
                    MMA16(acc[mb][nb], ah[mb], bh[nb]);
                    MMA16(acc[mb][nb], ah[mb], bl[nb]);
                    MMA16(acc[mb][nb], al[mb], bh[nb]);
                }
#undef MMA16
        }
        __syncthreads();
    }
#pragma unroll
    for (int mb = 0; mb < 2; mb++)
#pragma unroll
        for (int nb = 0; nb < 4; nb++) {
            int row = i0 + wy * 32 + mb * 16 + gr;
            int col = n0t + wx * 32 + nb * 8 + lc2;
            g_A[(size_t)row * N0 + col]           = acc[mb][nb][0];
            g_A[(size_t)row * N0 + col + 1]       = acc[mb][nb][1];
            g_A[(size_t)(row + 8) * N0 + col]     = acc[mb][nb][2];
            g_A[(size_t)(row + 8) * N0 + col + 1] = acc[mb][nb][3];
        }
}

// ---------------- blocked Cholesky of g_S (512, lower), panel 64 ----------------
__global__ void k_chol_diag(int p) {
    __shared__ float D[64][65];
    int t = threadIdx.x;
    for (int idx = t; idx < 4096; idx += 256) {
        int i = idx >> 6, j = idx & 63;
        D[i][j] = g_S[(p * 64 + i) * N0 + p * 64 + j];
    }
    __syncthreads();
    for (int j = 0; j < 64; j++) {
        if (t == 0) D[j][j] = sqrtf(D[j][j]);
        __syncthreads();
        float dj = D[j][j];
        for (int i = j + 1 + t; i < 64; i += 256) D[i][j] /= dj;
        __syncthreads();
        for (int idx = t; idx < 4096; idx += 256) {
            int i = idx >> 6, kc = idx & 63;
            if (kc > j && i >= kc) D[i][kc] -= D[i][j] * D[kc][j];
        }
        __syncthreads();
    }
    for (int idx = t; idx < 4096; idx += 256) {
        int i = idx >> 6, j = idx & 63;
        g_S[(p * 64 + i) * N0 + p * 64 + j] = D[i][j];
    }
}

__global__ void k_chol_offdiag(int p) {
    __shared__ float C[64][65];
    __shared__ float Dg[64][65];
    int rb = p + 1 + blockIdx.x;
    int t = threadIdx.x;
    for (int idx = t; idx < 4096; idx += 256) {
        int i = idx >> 6, j = idx & 63;
        C[i][j]  = g_S[(rb * 64 + i) * N0 + p * 64 + j];
        Dg[i][j] = g_S[(p * 64 + i) * N0 + p * 64 + j];
    }
    __syncthreads();
    for (int j = 0; j < 64; j++) {
        float inv = 1.0f / Dg[j][j];
        if (t < 64) C[t][j] *= inv;
        __syncthreads();
        for (int idx = t; idx < 4096; idx += 256) {
            int i = idx >> 6, jj = idx & 63;
            if (jj > j) C[i][jj] -= C[i][j] * Dg[jj][j];
        }
        __syncthreads();
    }
    for (int idx = t; idx < 4096; idx += 256) {
        int i = idx >> 6, j = idx & 63;
        g_S[(rb * 64 + i) * N0 + p * 64 + j] = C[i][j];
    }
}

__global__ void k_chol_syrk(int p) {
    __shared__ float Li[64][65];
    __shared__ float Lj[64][65];
    int t7 = 7 - p;
    int q = blockIdx.x, bj = 0;
    while (q >= t7 - bj) { q -= t7 - bj; bj++; }
    int bi = bj + q;
    int gi = p + 1 + bi, gj = p + 1 + bj;
    int t = threadIdx.x;
    for (int idx = t; idx < 4096; idx += 256) {
        int i = idx >> 6, k = idx & 63;
        Li[i][k] = g_S[(gi * 64 + i) * N0 + p * 64 + k];
        Lj[i][k] = g_S[(gj * 64 + i) * N0 + p * 64 + k];
    }
    __syncthreads();
    int ty = t >> 4, tx = t & 15;
#pragma unroll
    for (int u = 0; u < 4; u++)
#pragma unroll
        for (int v = 0; v < 4; v++) {
            float acc = 0.f;
#pragma unroll 8
            for (int k = 0; k < 64; k++) acc += Li[ty * 4 + u][k] * Lj[tx * 4 + v][k];
            g_S[(gi * 64 + ty * 4 + u) * N0 + gj * 64 + tx * 4 + v] -= acc;
        }
}

// ---------------- Q = A R^{-1}, blocked forward TRSM (in place on g_A) ----------------
__global__ void k_qpanel(int p) {
    __shared__ __align__(16) float Qs[16][68];
    __shared__ __align__(16) float Rs[16][68];
    __shared__ float Cs[64][68];
    __shared__ float Ds[64][65];
    int i0 = blockIdx.x * 64;
    int t = threadIdx.x, tx = t & 15, ty = t >> 4;
    int rr = t >> 2, c4 = t & 3;
    float acc[4][4];
#pragma unroll
    for (int u = 0; u < 4; u++)
#pragma unroll
        for (int v = 0; v < 4; v++)
            acc[u][v] = g_A[(i0 + ty * 4 + u) * N0 + p * 64 + tx * 4 + v];
    for (int kb = 0; kb < p * 64; kb += 16) {
        float4 v = *(const float4*)&g_A[(i0 + rr) * N0 + kb + c4 * 4];
        Qs[c4 * 4 + 0][rr] = v.x; Qs[c4 * 4 + 1][rr] = v.y;
        Qs[c4 * 4 + 2][rr] = v.z; Qs[c4 * 4 + 3][rr] = v.w;
        float4 w = *(const float4*)&g_S[(p * 64 + rr) * N0 + kb + c4 * 4];
        Rs[c4 * 4 + 0][rr] = w.x; Rs[c4 * 4 + 1][rr] = w.y;
        Rs[c4 * 4 + 2][rr] = w.z; Rs[c4 * 4 + 3][rr] = w.w;
        __syncthreads();
#pragma unroll
        for (int k = 0; k < 16; k++) {
            float4 av = *(const float4*)&Qs[k][ty * 4];
            float4 bv = *(const float4*)&Rs[k][tx * 4];
            float a_[4] = {av.x, av.y, av.z, av.w};
            float b_[4] = {bv.x, bv.y, bv.z, bv.w};
#pragma unroll
            for (int u = 0; u < 4; u++)
#pragma unroll
                for (int v2 = 0; v2 < 4; v2++) acc[u][v2] -= a_[u] * b_[v2];
        }
        __syncthreads();
    }
#pragma unroll
    for (int u = 0; u < 4; u++)
#pragma unroll
        for (int v = 0; v < 4; v++)
            Cs[ty * 4 + u][tx * 4 + v] = acc[u][v];
    for (int idx = t; idx < 4096; idx += 256) {
        int m = idx >> 6, j = idx & 63;
        Ds[m][j] = g_S[(p * 64 + j) * N0 + p * 64 + m];
    }
    __syncthreads();
    for (int j = 0; j < 64; j++) {
        float inv = 1.0f / Ds[j][j];
        if (t < 64) Cs[t][j] *= inv;
        __syncthreads();
        for (int idx = t; idx < 4096; idx += 256) {
            int i = idx >> 6, jj = idx & 63;
            if (jj > j) Cs[i][jj] -= Cs[i][j] * Ds[j][jj];
        }
        __syncthreads();
    }
    for (int idx = t; idx < 4096; idx += 256) {
        int i = idx >> 6, j = idx & 63;
        g_A[(i0 + i) * N0 + p * 64 + j] = Cs[i][j];
    }
}

// ---------------- new_s = Q^T (transpose g_A 4608x512 -> 512x4608) ----------------
__global__ void k_write_s(float* __restrict__ outS) {
    __shared__ float tile[32][33];
    int kB = blockIdx.x * 32, nB = blockIdx.y * 32;
    int tx = threadIdx.x, ty = threadIdx.y;
#pragma unroll
    for (int r = 0; r < 32; r += 8)
        tile[ty + r][tx] = g_A[(kB + ty + r) * N0 + nB + tx];
    __syncthreads();
#pragma unroll
    for (int r = 0; r < 32; r += 8)
        outS[(nB + ty + r) * KDIM + kB + tx] = tile[tx][ty + r];
}

static void run_cholqr_pass() {
    k_gemm_tn<<<dim3(8, 8, 4), 256>>>(1, 1);
    k_reduce_sym<<<512, 512>>>(1);
    for (int p = 0; p < 8; p++) {
        k_chol_diag<<<1, 256>>>(p);
        if (p < 7) {
            k_chol_offdiag<<<7 - p, 256>>>(p);
            int t7 = 7 - p;
            k_chol_syrk<<<t7 * (t7 + 1) / 2, 256>>>(p);
        }
    }
    for (int p = 0; p < 8; p++) k_qpanel<<<72, 256>>>(p);
}

extern "C" void kernel_launch(void* const* d_in, const int* in_sizes, int n_in,
                              void* d_out, int out_size) {
    const float* e    = (const float*)d_in[0];
    const float* eg   = (const float*)d_in[1];
    const float* s    = (const float*)d_in[2];
    const float* sg   = (const float*)d_in[3];
    const float* Lh0  = (const float*)d_in[4];
    const float* Lc0  = (const float*)d_in[5];
    const float* Lb   = (const float*)d_in[6];
    const float* Wih0 = (const float*)d_in[7];
    const float* Whh0 = (const float*)d_in[8];
    const float* bih0 = (const float*)d_in[9];
    const float* bhh0 = (const float*)d_in[10];
    const float* Wih1 = (const float*)d_in[11];
    const float* Whh1 = (const float*)d_in[12];
    const float* bih1 = (const float*)d_in[13];
    const float* bhh1 = (const float*)d_in[14];
    const float* Wl   = (const float*)d_in[15];
    const float* bl   = (const float*)d_in[16];
    const float* e_lr = (const float*)d_in[17];
    const float* s_lr = (const float*)d_in[18];
    float* out = (float*)d_out;

    k_update_e<<<16384, 256>>>((const float4*)e, (const float4*)eg, e_lr,
                               (float4*)(out + O_E));
    k_make_MMg<<<dim3(144, 16), dim3(32, 8)>>>(s, sg, s_lr);
    // G = Mg - M @ sym(M^T Mg)
    k_gemm_tn<<<dim3(8, 8, 4), 256>>>(0, 2);
    k_reduce_sym<<<512, 512>>>(0);
    k_proj_nn<<<dim3(72, 8), 256>>>(0, 0);
    // LogAndSign -> LSTM -> L (fp32 + split-bf16)
    k_rowsq<<<576, 256>>>();
    k_lstm<<<18, 256>>>(Lh0, Lc0, Wih0, Whh0, bih0, bhh0,
                        Wih1, Whh1, bih1, bhh1, Wl, bl, out);
    k_mean<<<1, 256>>>();
    k_build_L<<<20736, 256>>>((const float4*)Lb, (float4*)(out + O_L));
    // split-bf16 G^T, then LG on tensor cores (3-term compensated HMMA)
    k_gt<<<dim3(144, 16), dim3(32, 8)>>>();
    k_lg_mma<<<dim3(36, 8), 256>>>();
    // A = M + proj(M, LG)
    k_gemm_tn<<<dim3(8, 8, 4), 256>>>(0, 1);
    k_reduce_sym<<<512, 512>>>(0);
    k_proj_nn<<<dim3(72, 8), 256>>>(1, 1);
    // CholeskyQR2
    run_cholqr_pass();   // Q1 = A R1^{-1}
    run_cholqr_pass();   // Q2 = Q1 R2^{-1}
    // new_s
    k_write_s<<<dim3(144, 16), dim3(32, 8)>>>(out + O_S);
}

// round 11
// speedup vs baseline: 1.6592x; 1.5150x over previous
#include <cuda_runtime.h>
#include <cuda_bf16.h>
#include <math.h>
#include <stdint.h>

#define KDIM 4608
#define N0   512
#define WDC  0.0005f

// output layout (floats): new_e, new_s, L, hn, cn
#define O_E 0
#define O_S 16777216
#define O_L 19136512
#define O_H 40370176
#define O_C 40554496

// ---------------- scratch (device globals; no allocation allowed) ----------------
__device__ __align__(256) float g_M[KDIM * N0];      // M (4608x512)
__device__ __align__(256) float g_G[KDIM * N0];      // Mg -> G -> Q2 (final)
__device__ __align__(256) float g_A[KDIM * N0];      // LG -> A = M+P -> Q1 (in place)
__device__ __align__(256) float g_S[N0 * N0];        // Gram -> chol factor L (lower)
__device__ __align__(256) float g_Sym[N0 * N0];      // A_sym / Q1^T Q1
__device__ __align__(256) float g_part[4 * N0 * N0]; // split-K partials
__device__ __align__(256) float g_x[KDIM];
__device__ __align__(256) float g_lraw[KDIM];
__device__ float g_mean;
__device__ __align__(256) __nv_bfloat16 g_Lhi[(size_t)KDIM * KDIM];  // L hi bf16
__device__ __align__(256) __nv_bfloat16 g_Llo[(size_t)KDIM * KDIM];  // L lo bf16
__device__ __align__(256) __nv_bfloat16 g_Gthi[(size_t)N0 * KDIM];   // G^T hi
__device__ __align__(256) __nv_bfloat16 g_Gtlo[(size_t)N0 * KDIM];   // G^T lo

__device__ __forceinline__ float sigf(float z) { return 1.0f / (1.0f + expf(-z)); }

// ---------------- new_e = e - lr*(grad + wd*e) ----------------
__global__ void k_update_e(const float4* __restrict__ e, const float4* __restrict__ eg,
                           const float* __restrict__ e_lr, float4* __restrict__ out) {
    int i = blockIdx.x * 256 + threadIdx.x;
    float lr = *e_lr;
    float4 a = e[i], g = eg[i];
    float4 r;
    r.x = a.x - lr * (g.x + WDC * a.x);
    r.y = a.y - lr * (g.y + WDC * a.y);
    r.z = a.z - lr * (g.z + WDC * a.z);
    r.w = a.w - lr * (g.w + WDC * a.w);
    out[i] = r;
}

// ---------------- M = s.reshape(512,4608).T ; Mg = -s_lr * same(s_grad) ----------------
__global__ void k_make_MMg(const float* __restrict__ s, const float* __restrict__ sg,
                           const float* __restrict__ s_lr) {
    __shared__ float t0[32][33];
    __shared__ float t1[32][33];
    int iB = blockIdx.x * 32, jB = blockIdx.y * 32;
    int tx = threadIdx.x, ty = threadIdx.y;
#pragma unroll
    for (int r = 0; r < 32; r += 8) {
        t0[ty + r][tx] = s [(jB + ty + r) * KDIM + iB + tx];
        t1[ty + r][tx] = sg[(jB + ty + r) * KDIM + iB + tx];
    }
    __syncthreads();
    float nslr = -(*s_lr);
#pragma unroll
    for (int r = 0; r < 32; r += 8) {
        int i = iB + ty + r;
        g_M[i * N0 + jB + tx] = t0[tx][ty + r];
        g_G[i * N0 + jB + tx] = nslr * t1[tx][ty + r];
    }
}

// ---------------- C(512x512) = A^T B (split-K=4); sel: 0=g_M 1=g_A 2=g_G ----------------
__global__ void k_gemm_tn(int selA, int selB) {
    const float* A = (selA == 0) ? g_M : (selA == 1) ? g_A : g_G;
    const float* B = (selB == 0) ? g_M : (selB == 1) ? g_A : g_G;
    __shared__ __align__(16) float As[16][68];
    __shared__ __align__(16) float Bs[16][68];
    int a0 = blockIdx.x * 64, b0 = blockIdx.y * 64;
    int k0 = blockIdx.z * (KDIM / 4);
    int t = threadIdx.x, tx = t & 15, ty = t >> 4;
    int lr = t >> 4, lc = t & 15;
    float acc[4][4] = {};
    for (int kk = 0; kk < KDIM / 4; kk += 16) {
        float4 va = *(const float4*)&A[(k0 + kk + lr) * N0 + a0 + lc * 4];
        float4 vb = *(const float4*)&B[(k0 + kk + lr) * N0 + b0 + lc * 4];
        *(float4*)&As[lr][lc * 4] = va;
        *(float4*)&Bs[lr][lc * 4] = vb;
        __syncthreads();
#pragma unroll
        for (int k = 0; k < 16; k++) {
            float4 av = *(const float4*)&As[k][ty * 4];
            float4 bv = *(const float4*)&Bs[k][tx * 4];
            float a_[4] = {av.x, av.y, av.z, av.w};
            float b_[4] = {bv.x, bv.y, bv.z, bv.w};
#pragma unroll
            for (int u = 0; u < 4; u++)
#pragma unroll
                for (int v = 0; v < 4; v++) acc[u][v] += a_[u] * b_[v];
        }
        __syncthreads();
    }
    float* C = g_part + blockIdx.z * (N0 * N0);
#pragma unroll
    for (int u = 0; u < 4; u++)
#pragma unroll
        for (int v = 0; v < 4; v++)
            C[(a0 + ty * 4 + u) * N0 + (b0 + tx * 4 + v)] = acc[u][v];
}

// ---------------- reduce split-K + symmetrize: dst(0=g_Sym,1=g_S) ----------------
__global__ void k_reduce_sym(int dst) {
    int idx = blockIdx.x * 512 + threadIdx.x;
    int a = idx >> 9, b = idx & 511;
    float s1 = 0.f, s2 = 0.f;
#pragma unroll
    for (int z = 0; z < 4; z++) {
        s1 += g_part[z * N0 * N0 + idx];
        s2 += g_part[z * N0 * N0 + b * N0 + a];
    }
    float v = 0.5f * (s1 + s2);
    if (dst == 0) g_Sym[idx] = v; else g_S[idx] = v;
}

// ---------------- X = (addM? M:0) + X - M @ g_Sym ; xSel: 0=g_G 1=g_A ----------------
__global__ void k_proj_nn(int xSel, int addM) {
    float* X = xSel ? g_A : g_G;
    __shared__ __align__(16) float Ms[16][68];
    __shared__ __align__(16) float Ss[16][68];
    int i0 = blockIdx.x * 64, b0 = blockIdx.y * 64;
    int t = threadIdx.x, tx = t & 15, ty = t >> 4;
    int rr = t >> 2, c4 = t & 3;
    int r2 = t >> 4, c2 = t & 15;
    float acc[4][4] = {};
    for (int a0 = 0; a0 < N0; a0 += 16) {
        float4 v = *(const float4*)&g_M[(i0 + rr) * N0 + a0 + c4 * 4];
        Ms[c4 * 4 + 0][rr] = v.x; Ms[c4 * 4 + 1][rr] = v.y;
        Ms[c4 * 4 + 2][rr] = v.z; Ms[c4 * 4 + 3][rr] = v.w;
        *(float4*)&Ss[r2][c2 * 4] = *(const float4*)&g_Sym[(a0 + r2) * N0 + b0 + c2 * 4];
        __syncthreads();
#pragma unroll
        for (int k = 0; k < 16; k++) {
            float4 av = *(const float4*)&Ms[k][ty * 4];
            float4 bv = *(const float4*)&Ss[k][tx * 4];
            float a_[4] = {av.x, av.y, av.z, av.w};
            float b_[4] = {bv.x, bv.y, bv.z, bv.w};
#pragma unroll
            for (int u = 0; u < 4; u++)
#pragma unroll
                for (int v = 0; v < 4; v++) acc[u][v] += a_[u] * b_[v];
        }
        __syncthreads();
    }
#pragma unroll
    for (int u = 0; u < 4; u++)
#pragma unroll
        for (int v = 0; v < 4; v++) {
            int idx = (i0 + ty * 4 + u) * N0 + b0 + tx * 4 + v;
            float val = X[idx] - acc[u][v];
            if (addM) val += g_M[idx];
            X[idx] = val;
        }
}

// ---- Newton orthogonality step: g_G = Q1 - Q1 @ U, U = triu(E) + diag(E)/2 ----
__global__ void k_newton() {
    __shared__ __align__(16) float Ms[16][68];
    __shared__ __align__(16) float Ss[16][68];
    int i0 = blockIdx.x * 64, b0 = blockIdx.y * 64;
    int t = threadIdx.x, tx = t & 15, ty = t >> 4;
    int rr = t >> 2, c4 = t & 3;
    int r2 = t >> 4, c2 = t & 15;
    float acc[4][4] = {};
    for (int a0 = 0; a0 < N0; a0 += 16) {
        float4 v = *(const float4*)&g_A[(i0 + rr) * N0 + a0 + c4 * 4];
        Ms[c4 * 4 + 0][rr] = v.x; Ms[c4 * 4 + 1][rr] = v.y;
        Ms[c4 * 4 + 2][rr] = v.z; Ms[c4 * 4 + 3][rr] = v.w;
        {
            float4 w = *(const float4*)&g_Sym[(a0 + r2) * N0 + b0 + c2 * 4];
            int a = a0 + r2, bb = b0 + c2 * 4;
            float4 u;
            u.x = (a < bb    ) ? w.x : ((a == bb    ) ? 0.5f * (w.x - 1.0f) : 0.0f);
            u.y = (a < bb + 1) ? w.y : ((a == bb + 1) ? 0.5f * (w.y - 1.0f) : 0.0f);
            u.z = (a < bb + 2) ? w.z : ((a == bb + 2) ? 0.5f * (w.z - 1.0f) : 0.0f);
            u.w = (a < bb + 3) ? w.w : ((a == bb + 3) ? 0.5f * (w.w - 1.0f) : 0.0f);
            *(float4*)&Ss[r2][c2 * 4] = u;
        }
        __syncthreads();
#pragma unroll
        for (int k = 0; k < 16; k++) {
            float4 av = *(const float4*)&Ms[k][ty * 4];
            float4 bv = *(const float4*)&Ss[k][tx * 4];
            float a_[4] = {av.x, av.y, av.z, av.w};
            float b_[4] = {bv.x, bv.y, bv.z, bv.w};
#pragma unroll
            for (int u = 0; u < 4; u++)
#pragma unroll
                for (int v = 0; v < 4; v++) acc[u][v] += a_[u] * b_[v];
        }
        __syncthreads();
    }
#pragma unroll
    for (int u = 0; u < 4; u++)
#pragma unroll
        for (int v = 0; v < 4; v++) {
            int idx = (i0 + ty * 4 + u) * N0 + b0 + tx * 4 + v;
            g_G[idx] = g_A[idx] - acc[u][v];
        }
}

// ---------------- x[i] = clip(log(|rowsumsq(G)|)/10, -1, 1) ----------------
__global__ void k_rowsq() {
    int gt = blockIdx.x * 256 + threadIdx.x;
    int row = gt >> 5, lane = gt & 31;
    const float4* rp = (const float4*)&g_G[row * N0];
    float s = 0.f;
#pragma unroll 4
    for (int c = lane; c < 128; c += 32) {
        float4 v = rp[c];
        s += v.x * v.x + v.y * v.y + v.z * v.z + v.w * v.w;
    }
#pragma unroll
    for (int o = 16; o; o >>= 1) s += __shfl_xor_sync(0xffffffffu, s, o);
    if (lane == 0) {
        float x = logf(fabsf(s)) * 0.1f;
        g_x[row] = fminf(1.0f, fmaxf(-1.0f, x));
    }
}

// ---------------- 2-layer LSTM (one step, batch=4608) + l_raw ----------------
__global__ void k_lstm(const float* __restrict__ Lh0, const float* __restrict__ Lc0,
                       const float* __restrict__ Wih0, const float* __restrict__ Whh0,
                       const float* __restrict__ bih0, const float* __restrict__ bhh0,
                       const float* __restrict__ Wih1, const float* __restrict__ Whh1,
                       const float* __restrict__ bih1, const float* __restrict__ bhh1,
                       const float* __restrict__ Wl, const float* __restrict__ bl,
                       float* __restrict__ out) {
    __shared__ float sWih0[80], sWhh0[1600], sb0[80];
    __shared__ float sWih1[1600], sWhh1[1600], sb1[80];
    __shared__ float sWl[20], sbl[1];
    int t = threadIdx.x;
    for (int i = t; i < 80; i += 256) {
        sWih0[i] = Wih0[i];
        sb0[i] = bih0[i] + bhh0[i];
        sb1[i] = bih1[i] + bhh1[i];
    }
    for (int i = t; i < 1600; i += 256) {
        sWhh0[i] = Whh0[i];
        sWih1[i] = Wih1[i];
        sWhh1[i] = Whh1[i];
    }
    if (t < 20) sWl[t] = Wl[t];
    if (t == 0) sbl[0] = bl[0];
    __syncthreads();

    int i = blockIdx.x * 256 + t;
    float x = g_x[i];
    float h0p[20], h1p[20], h0n[20];
#pragma unroll
    for (int h = 0; h < 20; h++) {
        h0p[h] = Lh0[i * 20 + h];
        h1p[h] = Lh0[92160 + i * 20 + h];
    }
#pragma unroll
    for (int h = 0; h < 20; h++) {
        float pi = sb0[h]      + x * sWih0[h];
        float pf = sb0[20 + h] + x * sWih0[20 + h];
        float pg = sb0[40 + h] + x * sWih0[40 + h];
        float po = sb0[60 + h] + x * sWih0[60 + h];
#pragma unroll
        for (int m = 0; m < 20; m++) {
            float hm = h0p[m];
            pi += hm * sWhh0[h * 20 + m];
            pf += hm * sWhh0[(20 + h) * 20 + m];
            pg += hm * sWhh0[(40 + h) * 20 + m];
            po += hm * sWhh0[(60 + h) * 20 + m];
        }
        float c0 = Lc0[i * 20 + h];
        float c = sigf(pf) * c0 + sigf(pi) * tanhf(pg);
        float hh = sigf(po) * tanhf(c);
        h0n[h] = hh;
        out[O_H + i * 20 + h] = hh;
        out[O_C + i * 20 + h] = c;
    }
    float lacc = sbl[0];
#pragma unroll
    for (int h = 0; h < 20; h++) {
        float pi = sb1[h], pf = sb1[20 + h], pg = sb1[40 + h], po = sb1[60 + h];
#pragma unroll
        for (int m = 0; m < 20; m++) {
            float a = h0n[m], b = h1p[m];
            pi += a * sWih1[h * 20 + m]        + b * sWhh1[h * 20 + m];
            pf += a * sWih1[(20 + h) * 20 + m] + b * sWhh1[(20 + h) * 20 + m];
            pg += a * sWih1[(40 + h) * 20 + m] + b * sWhh1[(40 + h) * 20 + m];
            po += a * sWih1[(60 + h) * 20 + m] + b * sWhh1[(60 + h) * 20 + m];
        }
        float c1 = Lc0[92160 + i * 20 + h];
        float c = sigf(pf) * c1 + sigf(pi) * tanhf(pg);
        float hh = sigf(po) * tanhf(c);
        out[O_H + 92160 + i * 20 + h] = hh;
        out[O_C + 92160 + i * 20 + h] = c;
        lacc += hh * sWl[h];
    }
    g_lraw[i] = lacc * 0.1f;
}

__global__ void k_mean() {
    __shared__ float sm[256];
    int t = threadIdx.x;
    float s = 0.f;
    for (int i = t; i < KDIM; i += 256) s += g_lraw[i];
    sm[t] = s;
    __syncthreads();
    for (int o = 128; o; o >>= 1) {
        if (t < o) sm[t] += sm[t + o];
        __syncthreads();
    }
    if (t == 0) g_mean = sm[0] * (1.0f / KDIM);
}

// ---------------- L (fp32 out + split-bf16 hi/lo copies for MMA) ----------------
__global__ void k_build_L(const float4* __restrict__ Lb, float4* __restrict__ outL) {
    int gid = blockIdx.x * 256 + threadIdx.x;
    int base = gid * 4;
    int i = base / KDIM;
    int j0 = base - i * KDIM;
    float dv = g_lraw[i] - g_mean + 1.0f;
    float4 lb = Lb[gid];
    float4 r;
    r.x = fmaxf((j0 + 0 == i) ? dv : 0.0f, lb.x);
    r.y = fmaxf((j0 + 1 == i) ? dv : 0.0f, lb.y);
    r.z = fmaxf((j0 + 2 == i) ? dv : 0.0f, lb.z);
    r.w = fmaxf((j0 + 3 == i) ? dv : 0.0f, lb.w);
    outL[gid] = r;
    __nv_bfloat16 hx = __float2bfloat16(r.x), hy = __float2bfloat16(r.y);
    __nv_bfloat16 hz = __float2bfloat16(r.z), hw = __float2bfloat16(r.w);
    __nv_bfloat162* ph = (__nv_bfloat162*)g_Lhi;
    __nv_bfloat162* pl = (__nv_bfloat162*)g_Llo;
    ph[2 * gid]     = __nv_bfloat162(hx, hy);
    ph[2 * gid + 1] = __nv_bfloat162(hz, hw);
    pl[2 * gid]     = __nv_bfloat162(__float2bfloat16(r.x - __bfloat162float(hx)),
                                     __float2bfloat16(r.y - __bfloat162float(hy)));
    pl[2 * gid + 1] = __nv_bfloat162(__float2bfloat16(r.z - __bfloat162float(hz)),
                                     __float2bfloat16(r.w - __bfloat162float(hw)));
}

// ---------------- Gt hi/lo [n][k] = split-bf16(G[k][n]) ----------------
__global__ void k_gt() {
    __shared__ float tile[32][33];
    int kB = blockIdx.x * 32, nB = blockIdx.y * 32;
    int tx = threadIdx.x, ty = threadIdx.y;
#pragma unroll
    for (int r = 0; r < 32; r += 8)
        tile[ty + r][tx] = g_G[(kB + ty + r) * N0 + nB + tx];
    __syncthreads();
#pragma unroll
    for (int r = 0; r < 32; r += 8) {
        float v = tile[tx][ty + r];
        __nv_bfloat16 h = __float2bfloat16(v);
        size_t idx = (size_t)(nB + ty + r) * KDIM + kB + tx;
        g_Gthi[idx] = h;
        g_Gtlo[idx] = __float2bfloat16(v - __bfloat162float(h));
    }
}

// ---- g_A = L @ G via split-bf16 HMMA: Lhi*Ghi + Lhi*Glo + Llo*Ghi (128x64/CTA) ----
__global__ void __launch_bounds__(256) k_lg_mma() {
    __shared__ __align__(16) __nv_bfloat16 Ah[128][40];
    __shared__ __align__(16) __nv_bfloat16 Al[128][40];
    __shared__ __align__(16) __nv_bfloat16 Bh[64][40];
    __shared__ __align__(16) __nv_bfloat16 Bl[64][40];
    int t = threadIdx.x, wid = t >> 5, lane = t & 31;
    int i0 = blockIdx.x * 128, n0t = blockIdx.y * 64;
    int wy = wid >> 1, wx = wid & 1;  // warp tile: 32 rows x 32 cols
    float acc[2][4][4];
#pragma unroll
    for (int mb = 0; mb < 2; mb++)
#pragma unroll
        for (int nb = 0; nb < 4; nb++)
#pragma unroll
            for (int q = 0; q < 4; q++) acc[mb][nb][q] = 0.f;

    int ar0 = t >> 2, ac0 = (t & 3) * 8;   // rows 0..63
    int ar1 = ar0 + 64;                    // rows 64..127
    uint4 vAh0 = *(const uint4*)(g_Lhi + (size_t)(i0 + ar0) * KDIM + ac0);
    uint4 vAh1 = *(const uint4*)(g_Lhi + (size_t)(i0 + ar1) * KDIM + ac0);
    uint4 vAl0 = *(const uint4*)(g_Llo + (size_t)(i0 + ar0) * KDIM + ac0);
    uint4 vAl1 = *(const uint4*)(g_Llo + (size_t)(i0 + ar1) * KDIM + ac0);
    uint4 vBh  = *(const uint4*)(g_Gthi + (size_t)(n0t + ar0) * KDIM + ac0);
    uint4 vBl  = *(const uint4*)(g_Gtlo + (size_t)(n0t + ar0) * KDIM + ac0);

    int gr = lane >> 2, lc2 = (lane & 3) * 2;
    for (int k0 = 0; k0 < KDIM; k0 += 32) {
        *(uint4*)&Ah[ar0][ac0] = vAh0;
        *(uint4*)&Ah[ar1][ac0] = vAh1;
        *(uint4*)&Al[ar0][ac0] = vAl0;
        *(uint4*)&Al[ar1][ac0] = vAl1;
        *(uint4*)&Bh[ar0][ac0] = vBh;
        *(uint4*)&Bl[ar0][ac0] = vBl;
        __syncthreads();
        if (k0 + 32 < KDIM) {
            size_t koff = (size_t)(k0 + 32 + ac0);
            vAh0 = *(const uint4*)(g_Lhi + (size_t)(i0 + ar0) * KDIM + koff);
            vAh1 = *(const uint4*)(g_Lhi + (size_t)(i0 + ar1) * KDIM + koff);
            vAl0 = *(const uint4*)(g_Llo + (size_t)(i0 + ar0) * KDIM + koff);
            vAl1 = *(const uint4*)(g_Llo + (size_t)(i0 + ar1) * KDIM + koff);
            vBh  = *(const uint4*)(g_Gthi + (size_t)(n0t + ar0) * KDIM + koff);
            vBl  = *(const uint4*)(g_Gtlo + (size_t)(n0t + ar0) * KDIM + koff);
        }
#pragma unroll
        for (int kk = 0; kk < 32; kk += 16) {
            uint32_t ah[2][4], al[2][4], bh[4][2], bl[4][2];
#pragma unroll
            for (int mb = 0; mb < 2; mb++) {
                int r = wy * 32 + mb * 16 + gr;
                ah[mb][0] = *(const uint32_t*)&Ah[r][kk + lc2];
                ah[mb][1] = *(const uint32_t*)&Ah[r + 8][kk + lc2];
                ah[mb][2] = *(const uint32_t*)&Ah[r][kk + lc2 + 8];
                ah[mb][3] = *(const uint32_t*)&Ah[r + 8][kk + lc2 + 8];
                al[mb][0] = *(const uint32_t*)&Al[r][kk + lc2];
                al[mb][1] = *(const uint32_t*)&Al[r + 8][kk + lc2];
                al[mb][2] = *(const uint32_t*)&Al[r][kk + lc2 + 8];
                al[mb][3] = *(const uint32_t*)&Al[r + 8][kk + lc2 + 8];
            }
#pragma unroll
            for (int nb = 0; nb < 4; nb++) {
                int bn = wx * 32 + nb * 8 + gr;
                bh[nb][0] = *(const uint32_t*)&Bh[bn][kk + lc2];
                bh[nb][1] = *(const uint32_t*)&Bh[bn][kk + lc2 + 8];
                bl[nb][0] = *(const uint32_t*)&Bl[bn][kk + lc2];
                bl[nb][1] = *(const uint32_t*)&Bl[bn][kk + lc2 + 8];
            }
#define MMA16(ACC, AV, BV)                                                       \
    asm volatile("mma.sync.aligned.m16n8k16.row.col.f32.bf16.bf16.f32 "          \
                 "{%0,%1,%2,%3}, {%4,%5,%6,%7}, {%8,%9}, {%0,%1,%2,%3};"         \
                 : "+f"((ACC)[0]), "+f"((ACC)[1]), "+f"((ACC)[2]), "+f"((ACC)[3])\
                 : "r"((AV)[0]), "r"((AV)[1]), "r"((AV)[2]), "r"((AV)[3]),       \
                   "r"((BV)[0]), "r"((BV)[1]))
#pragma unroll
            for (int mb = 0; mb < 2; mb++)
#pragma unroll
                for (int nb = 0; nb < 4; nb++) {
                    MMA16(acc[mb][nb], ah[mb], bh[nb]);
                    MMA16(acc[mb][nb], ah[mb], bl[nb]);
                    MMA16(acc[mb][nb], al[mb], bh[nb]);
                }
#undef MMA16
        }
        __syncthreads();
    }
#pragma unroll
    for (int mb = 0; mb < 2; mb++)
#pragma unroll
        for (int nb = 0; nb < 4; nb++) {
            int row = i0 + wy * 32 + mb * 16 + gr;
            int col = n0t + wx * 32 + nb * 8 + lc2;
            g_A[(size_t)row * N0 + col]           = acc[mb][nb][0];
            g_A[(size_t)row * N0 + col + 1]       = acc[mb][nb][1];
            g_A[(size_t)(row + 8) * N0 + col]     = acc[mb][nb][2];
            g_A[(size_t)(row + 8) * N0 + col + 1] = acc[mb][nb][3];
        }
}

// ---------------- blocked Cholesky of g_S (512, lower), panel 64 ----------------
__global__ void k_chol_diag(int p) {
    __shared__ float D[64][65];
    int t = threadIdx.x;
    for (int idx = t; idx < 4096; idx += 256) {
        int i = idx >> 6, j = idx & 63;
        D[i][j] = g_S[(p * 64 + i) * N0 + p * 64 + j];
    }
    __syncthreads();
    for (int j = 0; j < 64; j++) {
        if (t == 0) D[j][j] = sqrtf(D[j][j]);
        __syncthreads();
        float dj = D[j][j];
        for (int i = j + 1 + t; i < 64; i += 256) D[i][j] /= dj;
        __syncthreads();
        for (int idx = t; idx < 4096; idx += 256) {
            int i = idx >> 6, kc = idx & 63;
            if (kc > j && i >= kc) D[i][kc] -= D[i][j] * D[kc][j];
        }
        __syncthreads();
    }
    for (int idx = t; idx < 4096; idx += 256) {
        int i = idx >> 6, j = idx & 63;
        g_S[(p * 64 + i) * N0 + p * 64 + j] = D[i][j];
    }
}

__global__ void k_chol_offdiag(int p) {
    __shared__ float C[64][65];
    __shared__ float Dg[64][65];
    int rb = p + 1 + blockIdx.x;
    int t = threadIdx.x;
    for (int idx = t; idx < 4096; idx += 256) {
        int i = idx >> 6, j = idx & 63;
        C[i][j]  = g_S[(rb * 64 + i) * N0 + p * 64 + j];
        Dg[i][j] = g_S[(p * 64 + i) * N0 + p * 64 + j];
    }
    __syncthreads();
    for (int j = 0; j < 64; j++) {
        float inv = 1.0f / Dg[j][j];
        if (t < 64) C[t][j] *= inv;
        __syncthreads();
        for (int idx = t; idx < 4096; idx += 256) {
            int i = idx >> 6, jj = idx & 63;
            if (jj > j) C[i][jj] -= C[i][j] * Dg[jj][j];
        }
        __syncthreads();
    }
    for (int idx = t; idx < 4096; idx += 256) {
        int i = idx >> 6, j = idx & 63;
        g_S[(rb * 64 + i) * N0 + p * 64 + j] = C[i][j];
    }
}

__global__ void k_chol_syrk(int p) {
    __shared__ float Li[64][65];
    __shared__ float Lj[64][65];
    int t7 = 7 - p;
    int q = blockIdx.x, bj = 0;
    while (q >= t7 - bj) { q -= t7 - bj; bj++; }
    int bi = bj + q;
    int gi = p + 1 + bi, gj = p + 1 + bj;
    int t = threadIdx.x;
    for (int idx = t; idx < 4096; idx += 256) {
        int i = idx >> 6, k = idx & 63;
        Li[i][k] = g_S[(gi * 64 + i) * N0 + p * 64 + k];
        Lj[i][k] = g_S[(gj * 64 + i) * N0 + p * 64 + k];
    }
    __syncthreads();
    int ty = t >> 4, tx = t & 15;
#pragma unroll
    for (int u = 0; u < 4; u++)
#pragma unroll
        for (int v = 0; v < 4; v++) {
            float acc = 0.f;
#pragma unroll 8
            for (int k = 0; k < 64; k++) acc += Li[ty * 4 + u][k] * Lj[tx * 4 + v][k];
            g_S[(gi * 64 + ty * 4 + u) * N0 + gj * 64 + tx * 4 + v] -= acc;
        }
}

// ---------------- Q = A R^{-1}, blocked forward TRSM (in place on g_A) ----------------
__global__ void k_qpanel(int p) {
    __shared__ __align__(16) float Qs[16][68];
    __shared__ __align__(16) float Rs[16][68];
    __shared__ float Cs[64][68];
    __shared__ float Ds[64][65];
    int i0 = blockIdx.x * 64;
    int t = threadIdx.x, tx = t & 15, ty = t >> 4;
    int rr = t >> 2, c4 = t & 3;
    float acc[4][4];
#pragma unroll
    for (int u = 0; u < 4; u++)
#pragma unroll
        for (int v = 0; v < 4; v++)
            acc[u][v] = g_A[(i0 + ty * 4 + u) * N0 + p * 64 + tx * 4 + v];
    for (int kb = 0; kb < p * 64; kb += 16) {
        float4 v = *(const float4*)&g_A[(i0 + rr) * N0 + kb + c4 * 4];
        Qs[c4 * 4 + 0][rr] = v.x; Qs[c4 * 4 + 1][rr] = v.y;
        Qs[c4 * 4 + 2][rr] = v.z; Qs[c4 * 4 + 3][rr] = v.w;
        float4 w = *(const float4*)&g_S[(p * 64 + rr) * N0 + kb + c4 * 4];
        Rs[c4 * 4 + 0][rr] = w.x; Rs[c4 * 4 + 1][rr] = w.y;
        Rs[c4 * 4 + 2][rr] = w.z; Rs[c4 * 4 + 3][rr] = w.w;
        __syncthreads();
#pragma unroll
        for (int k = 0; k < 16; k++) {
            float4 av = *(const float4*)&Qs[k][ty * 4];
            float4 bv = *(const float4*)&Rs[k][tx * 4];
            float a_[4] = {av.x, av.y, av.z, av.w};
            float b_[4] = {bv.x, bv.y, bv.z, bv.w};
#pragma unroll
            for (int u = 0; u < 4; u++)
#pragma unroll
                for (int v2 = 0; v2 < 4; v2++) acc[u][v2] -= a_[u] * b_[v2];
        }
        __syncthreads();
    }
#pragma unroll
    for (int u = 0; u < 4; u++)
#pragma unroll
        for (int v = 0; v < 4; v++)
            Cs[ty * 4 + u][tx * 4 + v] = acc[u][v];
    for (int idx = t; idx < 4096; idx += 256) {
        int m = idx >> 6, j = idx & 63;
        Ds[m][j] = g_S[(p * 64 + j) * N0 + p * 64 + m];
    }
    __syncthreads();
    for (int j = 0; j < 64; j++) {
        float inv = 1.0f / Ds[j][j];
        if (t < 64) Cs[t][j] *= inv;
        __syncthreads();
        for (int idx = t; idx < 4096; idx += 256) {
            int i = idx >> 6, jj = idx & 63;
            if (jj > j) Cs[i][jj] -= Cs[i][j] * Ds[j][jj];
        }
        __syncthreads();
    }
    for (int idx = t; idx < 4096; idx += 256) {
        int i = idx >> 6, j = idx & 63;
        g_A[(i0 + i) * N0 + p * 64 + j] = Cs[i][j];
    }
}

// ---------------- new_s = Q2^T (transpose g_G 4608x512 -> 512x4608) ----------------
__global__ void k_write_s(float* __restrict__ outS) {
    __shared__ float tile[32][33];
    int kB = blockIdx.x * 32, nB = blockIdx.y * 32;
    int tx = threadIdx.x, ty = threadIdx.y;
#pragma unroll
    for (int r = 0; r < 32; r += 8)
        tile[ty + r][tx] = g_G[(kB + ty + r) * N0 + nB + tx];
    __syncthreads();
#pragma unroll
    for (int r = 0; r < 32; r += 8)
        outS[(nB + ty + r) * KDIM + kB + tx] = tile[tx][ty + r];
}

extern "C" void kernel_launch(void* const* d_in, const int* in_sizes, int n_in,
                              void* d_out, int out_size) {
    const float* e    = (const float*)d_in[0];
    const float* eg   = (const float*)d_in[1];
    const float* s    = (const float*)d_in[2];
    const float* sg   = (const float*)d_in[3];
    const float* Lh0  = (const float*)d_in[4];
    const float* Lc0  = (const float*)d_in[5];
    const float* Lb   = (const float*)d_in[6];
    const float* Wih0 = (const float*)d_in[7];
    const float* Whh0 = (const float*)d_in[8];
    const float* bih0 = (const float*)d_in[9];
    const float* bhh0 = (const float*)d_in[10];
    const float* Wih1 = (const float*)d_in[11];
    const float* Whh1 = (const float*)d_in[12];
    const float* bih1 = (const float*)d_in[13];
    const float* bhh1 = (const float*)d_in[14];
    const float* Wl   = (const float*)d_in[15];
    const float* bl   = (const float*)d_in[16];
    const float* e_lr = (const float*)d_in[17];
    const float* s_lr = (const float*)d_in[18];
    float* out = (float*)d_out;

    k_update_e<<<16384, 256>>>((const float4*)e, (const float4*)eg, e_lr,
                               (float4*)(out + O_E));
    k_make_MMg<<<dim3(144, 16), dim3(32, 8)>>>(s, sg, s_lr);
    // G = Mg - M @ sym(M^T Mg)
    k_gemm_tn<<<dim3(8, 8, 4), 256>>>(0, 2);
    k_reduce_sym<<<512, 512>>>(0);
    k_proj_nn<<<dim3(72, 8), 256>>>(0, 0);
    // LogAndSign -> LSTM -> L (fp32 + split-bf16)
    k_rowsq<<<576, 256>>>();
    k_lstm<<<18, 256>>>(Lh0, Lc0, Wih0, Whh0, bih0, bhh0,
                        Wih1, Whh1, bih1, bhh1, Wl, bl, out);
    k_mean<<<1, 256>>>();
    k_build_L<<<20736, 256>>>((const float4*)Lb, (float4*)(out + O_L));
    // split-bf16 G^T, then LG on tensor cores (3-term compensated HMMA)
    k_gt<<<dim3(144, 16), dim3(32, 8)>>>();
    k_lg_mma<<<dim3(36, 8), 256>>>();
    // A = M + proj(M, LG)
    k_gemm_tn<<<dim3(8, 8, 4), 256>>>(0, 1);
    k_reduce_sym<<<512, 512>>>(0);
    k_proj_nn<<<dim3(72, 8), 256>>>(1, 1);
    // CholQR pass 1 (exact): Q1 = A R1^{-1}
    k_gemm_tn<<<dim3(8, 8, 4), 256>>>(1, 1);
    k_reduce_sym<<<512, 512>>>(1);
    for (int p = 0; p < 8; p++) {
        k_chol_diag<<<1, 256>>>(p);
        if (p < 7) {
            k_chol_offdiag<<<7 - p, 256>>>(p);
            int t7 = 7 - p;
            k_chol_syrk<<<t7 * (t7 + 1) / 2, 256>>>(p);
        }
    }
    for (int p = 0; p < 8; p++) k_qpanel<<<72, 256>>>(p);
    // Pass 2 via Newton refinement (E = Q1^T Q1 - I is ~1e-5 now): Q2 = Q1 - Q1 U
    k_gemm_tn<<<dim3(8, 8, 4), 256>>>(1, 1);
    k_reduce_sym<<<512, 512>>>(0);
    k_newton<<<dim3(72, 8), 256>>>();
    // new_s
    k_write_s<<<dim3(144, 16), dim3(32, 8)>>>(out + O_S);
}

// round 12
// speedup vs baseline: 1.8285x; 1.1020x over previous
#include <cuda_runtime.h>
#include <cuda_bf16.h>
#include <math.h>
#include <stdint.h>

#define KDIM 4608
#define N0   512
#define WDC  0.0005f

// output layout (floats): new_e, new_s, L, hn, cn
#define O_E 0
#define O_S 16777216
#define O_L 19136512
#define O_H 40370176
#define O_C 40554496

// ---------------- scratch (device globals; no allocation allowed) ----------------
__device__ __align__(256) float g_M[KDIM * N0];      // M (4608x512)
__device__ __align__(256) float g_G[KDIM * N0];      // Mg -> G -> Q2 (final)
__device__ __align__(256) float g_A[KDIM * N0];      // LG -> A = M+P -> Q1 (in place)
__device__ __align__(256) float g_S[N0 * N0];        // Gram -> chol factor (lower)
__device__ __align__(256) float g_Sym[N0 * N0];      // A_sym / E-gram
__device__ __align__(256) float g_part[4 * N0 * N0]; // split-K partials
__device__ __align__(256) float g_x[KDIM];
__device__ __align__(256) float g_lraw[KDIM];
__device__ float g_mean;
__device__ __align__(256) __nv_bfloat16 g_Lhi[(size_t)KDIM * KDIM];
__device__ __align__(256) __nv_bfloat16 g_Llo[(size_t)KDIM * KDIM];
__device__ __align__(256) __nv_bfloat16 g_Gthi[(size_t)N0 * KDIM];  // G^T (for LG)
__device__ __align__(256) __nv_bfloat16 g_Gtlo[(size_t)N0 * KDIM];
__device__ __align__(256) __nv_bfloat16 g_MThi[(size_t)N0 * KDIM];  // M^T
__device__ __align__(256) __nv_bfloat16 g_MTlo[(size_t)N0 * KDIM];
__device__ __align__(256) __nv_bfloat16 g_XThi[(size_t)N0 * KDIM];  // scratch^T
__device__ __align__(256) __nv_bfloat16 g_XTlo[(size_t)N0 * KDIM];
__device__ __align__(256) __nv_bfloat16 g_MRhi[(size_t)KDIM * N0];  // M rows
__device__ __align__(256) __nv_bfloat16 g_MRlo[(size_t)KDIM * N0];
__device__ __align__(256) __nv_bfloat16 g_XRhi[(size_t)KDIM * N0];  // Q1 rows
__device__ __align__(256) __nv_bfloat16 g_XRlo[(size_t)KDIM * N0];
__device__ __align__(256) __nv_bfloat16 g_Bophi[N0 * N0];           // B-operand
__device__ __align__(256) __nv_bfloat16 g_Boplo[N0 * N0];

__device__ __forceinline__ float sigf(float z) { return 1.0f / (1.0f + expf(-z)); }

#define MMA16(ACC, AV, BV)                                                       \
    asm volatile("mma.sync.aligned.m16n8k16.row.col.f32.bf16.bf16.f32 "          \
                 "{%0,%1,%2,%3}, {%4,%5,%6,%7}, {%8,%9}, {%0,%1,%2,%3};"         \
                 : "+f"((ACC)[0]), "+f"((ACC)[1]), "+f"((ACC)[2]), "+f"((ACC)[3])\
                 : "r"((AV)[0]), "r"((AV)[1]), "r"((AV)[2]), "r"((AV)[3]),       \
                   "r"((BV)[0]), "r"((BV)[1]))

// ---------------- new_e ----------------
__global__ void k_update_e(const float4* __restrict__ e, const float4* __restrict__ eg,
                           const float* __restrict__ e_lr, float4* __restrict__ out) {
    int i = blockIdx.x * 256 + threadIdx.x;
    float lr = *e_lr;
    float4 a = e[i], g = eg[i];
    float4 r;
    r.x = a.x - lr * (g.x + WDC * a.x);
    r.y = a.y - lr * (g.y + WDC * a.y);
    r.z = a.z - lr * (g.z + WDC * a.z);
    r.w = a.w - lr * (g.w + WDC * a.w);
    out[i] = r;
}

// ---------------- M, Mg ----------------
__global__ void k_make_MMg(const float* __restrict__ s, const float* __restrict__ sg,
                           const float* __restrict__ s_lr) {
    __shared__ float t0[32][33];
    __shared__ float t1[32][33];
    int iB = blockIdx.x * 32, jB = blockIdx.y * 32;
    int tx = threadIdx.x, ty = threadIdx.y;
#pragma unroll
    for (int r = 0; r < 32; r += 8) {
        t0[ty + r][tx] = s [(jB + ty + r) * KDIM + iB + tx];
        t1[ty + r][tx] = sg[(jB + ty + r) * KDIM + iB + tx];
    }
    __syncthreads();
    float nslr = -(*s_lr);
#pragma unroll
    for (int r = 0; r < 32; r += 8) {
        int i = iB + ty + r;
        g_M[i * N0 + jB + tx] = t0[tx][ty + r];
        g_G[i * N0 + jB + tx] = nslr * t1[tx][ty + r];
    }
}

// ---------------- fp32 Gram (pass-1 only): C = A^T A split-K ----------------
__global__ void k_gemm_tn() {
    const float* A = g_A;
    __shared__ __align__(16) float As[16][68];
    __shared__ __align__(16) float Bs[16][68];
    int a0 = blockIdx.x * 64, b0 = blockIdx.y * 64;
    int k0 = blockIdx.z * (KDIM / 4);
    int t = threadIdx.x, tx = t & 15, ty = t >> 4;
    int lr = t >> 4, lc = t & 15;
    float acc[4][4] = {};
    for (int kk = 0; kk < KDIM / 4; kk += 16) {
        float4 va = *(const float4*)&A[(k0 + kk + lr) * N0 + a0 + lc * 4];
        float4 vb = *(const float4*)&A[(k0 + kk + lr) * N0 + b0 + lc * 4];
        *(float4*)&As[lr][lc * 4] = va;
        *(float4*)&Bs[lr][lc * 4] = vb;
        __syncthreads();
#pragma unroll
        for (int k = 0; k < 16; k++) {
            float4 av = *(const float4*)&As[k][ty * 4];
            float4 bv = *(const float4*)&Bs[k][tx * 4];
            float a_[4] = {av.x, av.y, av.z, av.w};
            float b_[4] = {bv.x, bv.y, bv.z, bv.w};
#pragma unroll
            for (int u = 0; u < 4; u++)
#pragma unroll
                for (int v = 0; v < 4; v++) acc[u][v] += a_[u] * b_[v];
        }
        __syncthreads();
    }
    float* C = g_part + blockIdx.z * (N0 * N0);
#pragma unroll
    for (int u = 0; u < 4; u++)
#pragma unroll
        for (int v = 0; v < 4; v++)
            C[(a0 + ty * 4 + u) * N0 + (b0 + tx * 4 + v)] = acc[u][v];
}

// ---------------- reduce split-K + symmetrize: dst(0=g_Sym,1=g_S) ----------------
__global__ void k_reduce_sym(int dst) {
    int idx = blockIdx.x * 512 + threadIdx.x;
    int a = idx >> 9, b = idx & 511;
    float s1 = 0.f, s2 = 0.f;
#pragma unroll
    for (int z = 0; z < 4; z++) {
        s1 += g_part[z * N0 * N0 + idx];
        s2 += g_part[z * N0 * N0 + b * N0 + a];
    }
    float v = 0.5f * (s1 + s2);
    if (dst == 0) g_Sym[idx] = v; else g_S[idx] = v;
}

// ---------------- transpose + split: sel 0:M->MT 1:A->XT 2:G->XT 3:G->Gt ----------------
__global__ void k_tsplit(int sel) {
    __shared__ float tile[32][33];
    const float* src = (sel == 0) ? g_M : (sel == 1) ? g_A : g_G;
    __nv_bfloat16* dh = (sel == 0) ? g_MThi : (sel == 3) ? g_Gthi : g_XThi;
    __nv_bfloat16* dl = (sel == 0) ? g_MTlo : (sel == 3) ? g_Gtlo : g_XTlo;
    int kB = blockIdx.x * 32, nB = blockIdx.y * 32;
    int tx = threadIdx.x, ty = threadIdx.y;
#pragma unroll
    for (int r = 0; r < 32; r += 8)
        tile[ty + r][tx] = src[(kB + ty + r) * N0 + nB + tx];
    __syncthreads();
#pragma unroll
    for (int r = 0; r < 32; r += 8) {
        float v = tile[tx][ty + r];
        __nv_bfloat16 h = __float2bfloat16(v);
        size_t idx = (size_t)(nB + ty + r) * KDIM + kB + tx;
        dh[idx] = h;
        dl[idx] = __float2bfloat16(v - __bfloat162float(h));
    }
}

// ---------------- row split: sel 0:M->MR 1:A->XR ----------------
__global__ void k_rsplit(int sel) {
    int gid = blockIdx.x * 256 + threadIdx.x;
    const float4* src = (const float4*)(sel ? g_A : g_M);
    __nv_bfloat162* dh = (__nv_bfloat162*)(sel ? g_XRhi : g_MRhi);
    __nv_bfloat162* dl = (__nv_bfloat162*)(sel ? g_XRlo : g_MRlo);
    float4 v = src[gid];
    __nv_bfloat16 hx = __float2bfloat16(v.x), hy = __float2bfloat16(v.y);
    __nv_bfloat16 hz = __float2bfloat16(v.z), hw = __float2bfloat16(v.w);
    dh[2 * gid]     = __nv_bfloat162(hx, hy);
    dh[2 * gid + 1] = __nv_bfloat162(hz, hw);
    dl[2 * gid]     = __nv_bfloat162(__float2bfloat16(v.x - __bfloat162float(hx)),
                                     __float2bfloat16(v.y - __bfloat162float(hy)));
    dl[2 * gid + 1] = __nv_bfloat162(__float2bfloat16(v.z - __bfloat162float(hz)),
                                     __float2bfloat16(v.w - __bfloat162float(hw)));
}

// ---------------- B-operand prep from g_Sym: mode 0 = Sym, 1 = U^T (Newton) ----------------
__global__ void k_bprep(int mode) {
    int j = blockIdx.x, a = threadIdx.x;
    float w = g_Sym[j * N0 + a];
    float v;
    if (mode == 0) v = w;
    else v = (a < j) ? w : ((a == j) ? 0.5f * (w - 1.0f) : 0.0f);
    __nv_bfloat16 h = __float2bfloat16(v);
    g_Bophi[j * N0 + a] = h;
    g_Boplo[j * N0 + a] = __float2bfloat16(v - __bfloat162float(h));
}

// ---------------- shared HMMA core (3-term split-bf16, 128x64 tile) ----------------
struct MmaPtrs {
    const __nv_bfloat16 *Ah, *Al, *Bh, *Bl;
};

template <int STRIDE>
__device__ __forceinline__ void mma_tile_loop(
    const MmaPtrs& P, int i0, int n0t, int kbeg, int kend, float acc[2][4][4],
    __nv_bfloat16 (*sAh)[40], __nv_bfloat16 (*sAl)[40],
    __nv_bfloat16 (*sBh)[40], __nv_bfloat16 (*sBl)[40]) {
    int t = threadIdx.x, lane = t & 31, wid = t >> 5;
    int wy = wid >> 1, wx = wid & 1;
    int ar0 = t >> 2, ac0 = (t & 3) * 8;
    int ar1 = ar0 + 64;
    int gr = lane >> 2, lc2 = (lane & 3) * 2;
    uint4 vAh0 = *(const uint4*)(P.Ah + (size_t)(i0 + ar0) * STRIDE + kbeg + ac0);
    uint4 vAh1 = *(const uint4*)(P.Ah + (size_t)(i0 + ar1) * STRIDE + kbeg + ac0);
    uint4 vAl0 = *(const uint4*)(P.Al + (size_t)(i0 + ar0) * STRIDE + kbeg + ac0);
    uint4 vAl1 = *(const uint4*)(P.Al + (size_t)(i0 + ar1) * STRIDE + kbeg + ac0);
    uint4 vBh  = *(const uint4*)(P.Bh + (size_t)(n0t + ar0) * STRIDE + kbeg + ac0);
    uint4 vBl  = *(const uint4*)(P.Bl + (size_t)(n0t + ar0) * STRIDE + kbeg + ac0);
    for (int k0 = kbeg; k0 < kend; k0 += 32) {
        *(uint4*)&sAh[ar0][ac0] = vAh0;
        *(uint4*)&sAh[ar1][ac0] = vAh1;
        *(uint4*)&sAl[ar0][ac0] = vAl0;
        *(uint4*)&sAl[ar1][ac0] = vAl1;
        *(uint4*)&sBh[ar0][ac0] = vBh;
        *(uint4*)&sBl[ar0][ac0] = vBl;
        __syncthreads();
        if (k0 + 32 < kend) {
            size_t ko = (size_t)(k0 + 32 + ac0);
            vAh0 = *(const uint4*)(P.Ah + (size_t)(i0 + ar0) * STRIDE + ko);
            vAh1 = *(const uint4*)(P.Ah + (size_t)(i0 + ar1) * STRIDE + ko);
            vAl0 = *(const uint4*)(P.Al + (size_t)(i0 + ar0) * STRIDE + ko);
            vAl1 = *(const uint4*)(P.Al + (size_t)(i0 + ar1) * STRIDE + ko);
            vBh  = *(const uint4*)(P.Bh + (size_t)(n0t + ar0) * STRIDE + ko);
            vBl  = *(const uint4*)(P.Bl + (size_t)(n0t + ar0) * STRIDE + ko);
        }
#pragma unroll
        for (int kk = 0; kk < 32; kk += 16) {
            uint32_t ah[2][4], al[2][4], bh[4][2], bl[4][2];
#pragma unroll
            for (int mb = 0; mb < 2; mb++) {
                int r = wy * 32 + mb * 16 + gr;
                ah[mb][0] = *(const uint32_t*)&sAh[r][kk + lc2];
                ah[mb][1] = *(const uint32_t*)&sAh[r + 8][kk + lc2];
                ah[mb][2] = *(const uint32_t*)&sAh[r][kk + lc2 + 8];
                ah[mb][3] = *(const uint32_t*)&sAh[r + 8][kk + lc2 + 8];
                al[mb][0] = *(const uint32_t*)&sAl[r][kk + lc2];
                al[mb][1] = *(const uint32_t*)&sAl[r + 8][kk + lc2];
                al[mb][2] = *(const uint32_t*)&sAl[r][kk + lc2 + 8];
                al[mb][3] = *(const uint32_t*)&sAl[r + 8][kk + lc2 + 8];
            }
#pragma unroll
            for (int nb = 0; nb < 4; nb++) {
                int bn = wx * 32 + nb * 8 + gr;
                bh[nb][0] = *(const uint32_t*)&sBh[bn][kk + lc2];
                bh[nb][1] = *(const uint32_t*)&sBh[bn][kk + lc2 + 8];
                bl[nb][0] = *(const uint32_t*)&sBl[bn][kk + lc2];
                bl[nb][1] = *(const uint32_t*)&sBl[bn][kk + lc2 + 8];
            }
#pragma unroll
            for (int mb = 0; mb < 2; mb++)
#pragma unroll
                for (int nb = 0; nb < 4; nb++) {
                    MMA16(acc[mb][nb], ah[mb], bh[nb]);
                    MMA16(acc[mb][nb], ah[mb], bl[nb]);
                    MMA16(acc[mb][nb], al[mb], bh[nb]);
                }
        }
        __syncthreads();
    }
}

// ---------------- g_A = L @ G (split-bf16 HMMA) ----------------
__global__ void __launch_bounds__(256) k_lg_mma() {
    __shared__ __align__(16) __nv_bfloat16 sAh[128][40];
    __shared__ __align__(16) __nv_bfloat16 sAl[128][40];
    __shared__ __align__(16) __nv_bfloat16 sBh[64][40];
    __shared__ __align__(16) __nv_bfloat16 sBl[64][40];
    int t = threadIdx.x, wid = t >> 5, lane = t & 31;
    int i0 = blockIdx.x * 128, n0t = blockIdx.y * 64;
    int wy = wid >> 1, wx = wid & 1;
    int gr = lane >> 2, lc2 = (lane & 3) * 2;
    float acc[2][4][4] = {};
    MmaPtrs P = {g_Lhi, g_Llo, g_Gthi, g_Gtlo};
    mma_tile_loop<KDIM>(P, i0, n0t, 0, KDIM, acc, sAh, sAl, sBh, sBl);
#pragma unroll
    for (int mb = 0; mb < 2; mb++)
#pragma unroll
        for (int nb = 0; nb < 4; nb++) {
            int row = i0 + wy * 32 + mb * 16 + gr;
            int col = n0t + wx * 32 + nb * 8 + lc2;
            g_A[(size_t)row * N0 + col]           = acc[mb][nb][0];
            g_A[(size_t)row * N0 + col + 1]       = acc[mb][nb][1];
            g_A[(size_t)(row + 8) * N0 + col]     = acc[mb][nb][2];
            g_A[(size_t)(row + 8) * N0 + col + 1] = acc[mb][nb][3];
        }
}

// ---------------- Gram via HMMA: partial C = At·Bt^T over k-chunk ----------------
// selA/selB: 0 = MT, 1 = XT
__global__ void __launch_bounds__(256) k_gram_mma(int selA, int selB) {
    __shared__ __align__(16) __nv_bfloat16 sAh[128][40];
    __shared__ __align__(16) __nv_bfloat16 sAl[128][40];
    __shared__ __align__(16) __nv_bfloat16 sBh[64][40];
    __shared__ __align__(16) __nv_bfloat16 sBl[64][40];
    int t = threadIdx.x, wid = t >> 5, lane = t & 31;
    int i0 = blockIdx.x * 128, n0t = blockIdx.y * 64;
    int kbeg = blockIdx.z * (KDIM / 4);
    int wy = wid >> 1, wx = wid & 1;
    int gr = lane >> 2, lc2 = (lane & 3) * 2;
    float acc[2][4][4] = {};
    MmaPtrs P = {selA ? g_XThi : g_MThi, selA ? g_XTlo : g_MTlo,
                 selB ? g_XThi : g_MThi, selB ? g_XTlo : g_MTlo};
    mma_tile_loop<KDIM>(P, i0, n0t, kbeg, kbeg + KDIM / 4, acc, sAh, sAl, sBh, sBl);
    float* C = g_part + blockIdx.z * (N0 * N0);
#pragma unroll
    for (int mb = 0; mb < 2; mb++)
#pragma unroll
        for (int nb = 0; nb < 4; nb++) {
            int row = i0 + wy * 32 + mb * 16 + gr;
            int col = n0t + wx * 32 + nb * 8 + lc2;
            C[(size_t)row * N0 + col]           = acc[mb][nb][0];
            C[(size_t)row * N0 + col + 1]       = acc[mb][nb][1];
            C[(size_t)(row + 8) * N0 + col]     = acc[mb][nb][2];
            C[(size_t)(row + 8) * N0 + col + 1] = acc[mb][nb][3];
        }
}

// ---------------- proj/newton via HMMA; mode 0: G-=A·Bop  1: A=M+A-M·Bop  2: G=A-A·Bop --
__global__ void __launch_bounds__(256) k_proj_mma(int mode) {
    __shared__ __align__(16) __nv_bfloat16 sAh[128][40];
    __shared__ __align__(16) __nv_bfloat16 sAl[128][40];
    __shared__ __align__(16) __nv_bfloat16 sBh[64][40];
    __shared__ __align__(16) __nv_bfloat16 sBl[64][40];
    int t = threadIdx.x, wid = t >> 5, lane = t & 31;
    int i0 = blockIdx.x * 128, n0t = blockIdx.y * 64;
    int wy = wid >> 1, wx = wid & 1;
    int gr = lane >> 2, lc2 = (lane & 3) * 2;
    float acc[2][4][4] = {};
    MmaPtrs P = {(mode == 2) ? g_XRhi : g_MRhi, (mode == 2) ? g_XRlo : g_MRlo,
                 g_Bophi, g_Boplo};
    mma_tile_loop<N0>(P, i0, n0t, 0, N0, acc, sAh, sAl, sBh, sBl);
#pragma unroll
    for (int mb = 0; mb < 2; mb++)
#pragma unroll
        for (int nb = 0; nb < 4; nb++) {
            int row = i0 + wy * 32 + mb * 16 + gr;
            int col = n0t + wx * 32 + nb * 8 + lc2;
#pragma unroll
            for (int q = 0; q < 4; q++) {
                int rr = row + (q >> 1) * 8;
                int cc = col + (q & 1);
                size_t idx = (size_t)rr * N0 + cc;
                float a = acc[mb][nb][q];
                if (mode == 0)      g_G[idx] = g_G[idx] - a;
                else if (mode == 1) g_A[idx] = g_M[idx] + g_A[idx] - a;
                else                g_G[idx] = g_A[idx] - a;
            }
        }
}

// ---------------- x[i] = clip(log(|rowsumsq(G)|)/10, -1, 1) ----------------
__global__ void k_rowsq() {
    int gt = blockIdx.x * 256 + threadIdx.x;
    int row = gt >> 5, lane = gt & 31;
    const float4* rp = (const float4*)&g_G[row * N0];
    float s = 0.f;
#pragma unroll 4
    for (int c = lane; c < 128; c += 32) {
        float4 v = rp[c];
        s += v.x * v.x + v.y * v.y + v.z * v.z + v.w * v.w;
    }
#pragma unroll
    for (int o = 16; o; o >>= 1) s += __shfl_xor_sync(0xffffffffu, s, o);
    if (lane == 0) {
        float x = logf(fabsf(s)) * 0.1f;
        g_x[row] = fminf(1.0f, fmaxf(-1.0f, x));
    }
}

// ---------------- 2-layer LSTM ----------------
__global__ void k_lstm(const float* __restrict__ Lh0, const float* __restrict__ Lc0,
                       const float* __restrict__ Wih0, const float* __restrict__ Whh0,
                       const float* __restrict__ bih0, const float* __restrict__ bhh0,
                       const float* __restrict__ Wih1, const float* __restrict__ Whh1,
                       const float* __restrict__ bih1, const float* __restrict__ bhh1,
                       const float* __restrict__ Wl, const float* __restrict__ bl,
                       float* __restrict__ out) {
    __shared__ float sWih0[80], sWhh0[1600], sb0[80];
    __shared__ float sWih1[1600], sWhh1[1600], sb1[80];
    __shared__ float sWl[20], sbl[1];
    int t = threadIdx.x;
    for (int i = t; i < 80; i += 256) {
        sWih0[i] = Wih0[i];
        sb0[i] = bih0[i] + bhh0[i];
        sb1[i] = bih1[i] + bhh1[i];
    }
    for (int i = t; i < 1600; i += 256) {
        sWhh0[i] = Whh0[i];
        sWih1[i] = Wih1[i];
        sWhh1[i] = Whh1[i];
    }
    if (t < 20) sWl[t] = Wl[t];
    if (t == 0) sbl[0] = bl[0];
    __syncthreads();

    int i = blockIdx.x * 256 + t;
    float x = g_x[i];
    float h0p[20], h1p[20], h0n[20];
#pragma unroll
    for (int h = 0; h < 20; h++) {
        h0p[h] = Lh0[i * 20 + h];
        h1p[h] = Lh0[92160 + i * 20 + h];
    }
#pragma unroll
    for (int h = 0; h < 20; h++) {
        float pi = sb0[h]      + x * sWih0[h];
        float pf = sb0[20 + h] + x * sWih0[20 + h];
        float pg = sb0[40 + h] + x * sWih0[40 + h];
        float po = sb0[60 + h] + x * sWih0[60 + h];
#pragma unroll
        for (int m = 0; m < 20; m++) {
            float hm = h0p[m];
            pi += hm * sWhh0[h * 20 + m];
            pf += hm * sWhh0[(20 + h) * 20 + m];
            pg += hm * sWhh0[(40 + h) * 20 + m];
            po += hm * sWhh0[(60 + h) * 20 + m];
        }
        float c0 = Lc0[i * 20 + h];
        float c = sigf(pf) * c0 + sigf(pi) * tanhf(pg);
        float hh = sigf(po) * tanhf(c);
        h0n[h] = hh;
        out[O_H + i * 20 + h] = hh;
        out[O_C + i * 20 + h] = c;
    }
    float lacc = sbl[0];
#pragma unroll
    for (int h = 0; h < 20; h++) {
        float pi = sb1[h], pf = sb1[20 + h], pg = sb1[40 + h], po = sb1[60 + h];
#pragma unroll
        for (int m = 0; m < 20; m++) {
            float a = h0n[m], b = h1p[m];
            pi += a * sWih1[h * 20 + m]        + b * sWhh1[h * 20 + m];
            pf += a * sWih1[(20 + h) * 20 + m] + b * sWhh1[(20 + h) * 20 + m];
            pg += a * sWih1[(40 + h) * 20 + m] + b * sWhh1[(40 + h) * 20 + m];
            po += a * sWih1[(60 + h) * 20 + m] + b * sWhh1[(60 + h) * 20 + m];
        }
        float c1 = Lc0[92160 + i * 20 + h];
        float c = sigf(pf) * c1 + sigf(pi) * tanhf(pg);
        float hh = sigf(po) * tanhf(c);
        out[O_H + 92160 + i * 20 + h] = hh;
        out[O_C + 92160 + i * 20 + h] = c;
        lacc += hh * sWl[h];
    }
    g_lraw[i] = lacc * 0.1f;
}

__global__ void k_mean() {
    __shared__ float sm[256];
    int t = threadIdx.x;
    float s = 0.f;
    for (int i = t; i < KDIM; i += 256) s += g_lraw[i];
    sm[t] = s;
    __syncthreads();
    for (int o = 128; o; o >>= 1) {
        if (t < o) sm[t] += sm[t + o];
        __syncthreads();
    }
    if (t == 0) g_mean = sm[0] * (1.0f / KDIM);
}

// ---------------- L (fp32 out + split-bf16) ----------------
__global__ void k_build_L(const float4* __restrict__ Lb, float4* __restrict__ outL) {
    int gid = blockIdx.x * 256 + threadIdx.x;
    int base = gid * 4;
    int i = base / KDIM;
    int j0 = base - i * KDIM;
    float dv = g_lraw[i] - g_mean + 1.0f;
    float4 lb = Lb[gid];
    float4 r;
    r.x = fmaxf((j0 + 0 == i) ? dv : 0.0f, lb.x);
    r.y = fmaxf((j0 + 1 == i) ? dv : 0.0f, lb.y);
    r.z = fmaxf((j0 + 2 == i) ? dv : 0.0f, lb.z);
    r.w = fmaxf((j0 + 3 == i) ? dv : 0.0f, lb.w);
    outL[gid] = r;
    __nv_bfloat16 hx = __float2bfloat16(r.x), hy = __float2bfloat16(r.y);
    __nv_bfloat16 hz = __float2bfloat16(r.z), hw = __float2bfloat16(r.w);
    __nv_bfloat162* ph = (__nv_bfloat162*)g_Lhi;
    __nv_bfloat162* pl = (__nv_bfloat162*)g_Llo;
    ph[2 * gid]     = __nv_bfloat162(hx, hy);
    ph[2 * gid + 1] = __nv_bfloat162(hz, hw);
    pl[2 * gid]     = __nv_bfloat162(__float2bfloat16(r.x - __bfloat162float(hx)),
                                     __float2bfloat16(r.y - __bfloat162float(hy)));
    pl[2 * gid + 1] = __nv_bfloat162(__float2bfloat16(r.z - __bfloat162float(hz)),
                                     __float2bfloat16(r.w - __bfloat162float(hw)));
}

// ---------------- blocked Cholesky of g_S (512, lower), panel 64 ----------------
__global__ void k_chol_diag(int p) {
    __shared__ float D[64][65];
    int t = threadIdx.x;
    for (int idx = t; idx < 4096; idx += 256) {
        int i = idx >> 6, j = idx & 63;
        D[i][j] = g_S[(p * 64 + i) * N0 + p * 64 + j];
    }
    __syncthreads();
    for (int j = 0; j < 64; j++) {
        if (t == 0) D[j][j] = sqrtf(D[j][j]);
        __syncthreads();
        float dj = D[j][j];
        for (int i = j + 1 + t; i < 64; i += 256) D[i][j] /= dj;
        __syncthreads();
        for (int idx = t; idx < 4096; idx += 256) {
            int i = idx >> 6, kc = idx & 63;
            if (kc > j && i >= kc) D[i][kc] -= D[i][j] * D[kc][j];
        }
        __syncthreads();
    }
    for (int idx = t; idx < 4096; idx += 256) {
        int i = idx >> 6, j = idx & 63;
        g_S[(p * 64 + i) * N0 + p * 64 + j] = D[i][j];
    }
}

__global__ void k_chol_offdiag(int p) {
    __shared__ float C[64][65];
    __shared__ float Dg[64][65];
    int rb = p + 1 + blockIdx.x;
    int t = threadIdx.x;
    for (int idx = t; idx < 4096; idx += 256) {
        int i = idx >> 6, j = idx & 63;
        C[i][j]  = g_S[(rb * 64 + i) * N0 + p * 64 + j];
        Dg[i][j] = g_S[(p * 64 + i) * N0 + p * 64 + j];
    }
    __syncthreads();
    for (int j = 0; j < 64; j++) {
        float inv = 1.0f / Dg[j][j];
        if (t < 64) C[t][j] *= inv;
        __syncthreads();
        for (int idx = t; idx < 4096; idx += 256) {
            int i = idx >> 6, jj = idx & 63;
            if (jj > j) C[i][jj] -= C[i][j] * Dg[jj][j];
        }
        __syncthreads();
    }
    for (int idx = t; idx < 4096; idx += 256) {
        int i = idx >> 6, j = idx & 63;
        g_S[(rb * 64 + i) * N0 + p * 64 + j] = C[i][j];
    }
}

__global__ void k_chol_syrk(int p) {
    __shared__ float Li[64][65];
    __shared__ float Lj[64][65];
    int t7 = 7 - p;
    int q = blockIdx.x, bj = 0;
    while (q >= t7 - bj) { q -= t7 - bj; bj++; }
    int bi = bj + q;
    int gi = p + 1 + bi, gj = p + 1 + bj;
    int t = threadIdx.x;
    for (int idx = t; idx < 4096; idx += 256) {
        int i = idx >> 6, k = idx & 63;
        Li[i][k] = g_S[(gi * 64 + i) * N0 + p * 64 + k];
        Lj[i][k] = g_S[(gj * 64 + i) * N0 + p * 64 + k];
    }
    __syncthreads();
    int ty = t >> 4, tx = t & 15;
#pragma unroll
    for (int u = 0; u < 4; u++)
#pragma unroll
        for (int v = 0; v < 4; v++) {
            float acc = 0.f;
#pragma unroll 8
            for (int k = 0; k < 64; k++) acc += Li[ty * 4 + u][k] * Lj[tx * 4 + v][k];
            g_S[(gi * 64 + ty * 4 + u) * N0 + gj * 64 + tx * 4 + v] -= acc;
        }
}

// ---------------- Q = A R^{-1}, blocked forward TRSM (in place on g_A) ----------------
__global__ void k_qpanel(int p) {
    __shared__ __align__(16) float Qs[16][68];
    __shared__ __align__(16) float Rs[16][68];
    __shared__ float Cs[64][68];
    __shared__ float Ds[64][65];
    int i0 = blockIdx.x * 64;
    int t = threadIdx.x, tx = t & 15, ty = t >> 4;
    int rr = t >> 2, c4 = t & 3;
    float acc[4][4];
#pragma unroll
    for (int u = 0; u < 4; u++)
#pragma unroll
        for (int v = 0; v < 4; v++)
            acc[u][v] = g_A[(i0 + ty * 4 + u) * N0 + p * 64 + tx * 4 + v];
    for (int kb = 0; kb < p * 64; kb += 16) {
        float4 v = *(const float4*)&g_A[(i0 + rr) * N0 + kb + c4 * 4];
        Qs[c4 * 4 + 0][rr] = v.x; Qs[c4 * 4 + 1][rr] = v.y;
        Qs[c4 * 4 + 2][rr] = v.z; Qs[c4 * 4 + 3][rr] = v.w;
        float4 w = *(const float4*)&g_S[(p * 64 + rr) * N0 + kb + c4 * 4];
        Rs[c4 * 4 + 0][rr] = w.x; Rs[c4 * 4 + 1][rr] = w.y;
        Rs[c4 * 4 + 2][rr] = w.z; Rs[c4 * 4 + 3][rr] = w.w;
        __syncthreads();
#pragma unroll
        for (int k = 0; k < 16; k++) {
            float4 av = *(const float4*)&Qs[k][ty * 4];
            float4 bv = *(const float4*)&Rs[k][tx * 4];
            float a_[4] = {av.x, av.y, av.z, av.w};
            float b_[4] = {bv.x, bv.y, bv.z, bv.w};
#pragma unroll
            for (int u = 0; u < 4; u++)
#pragma unroll
                for (int v2 = 0; v2 < 4; v2++) acc[u][v2] -= a_[u] * b_[v2];
        }
        __syncthreads();
    }
#pragma unroll
    for (int u = 0; u < 4; u++)
#pragma unroll
        for (int v = 0; v < 4; v++)
            Cs[ty * 4 + u][tx * 4 + v] = acc[u][v];
    for (int idx = t; idx < 4096; idx += 256) {
        int m = idx >> 6, j = idx & 63;
        Ds[m][j] = g_S[(p * 64 + j) * N0 + p * 64 + m];
    }
    __syncthreads();
    for (int j = 0; j < 64; j++) {
        float inv = 1.0f / Ds[j][j];
        if (t < 64) Cs[t][j] *= inv;
        __syncthreads();
        for (int idx = t; idx < 4096; idx += 256) {
            int i = idx >> 6, jj = idx & 63;
            if (jj > j) Cs[i][jj] -= Cs[i][j] * Ds[j][jj];
        }
        __syncthreads();
    }
    for (int idx = t; idx < 4096; idx += 256) {
        int i = idx >> 6, j = idx & 63;
        g_A[(i0 + i) * N0 + p * 64 + j] = Cs[i][j];
    }
}

// ---------------- new_s = Q2^T ----------------
__global__ void k_write_s(float* __restrict__ outS) {
    __shared__ float tile[32][33];
    int kB = blockIdx.x * 32, nB = blockIdx.y * 32;
    int tx = threadIdx.x, ty = threadIdx.y;
#pragma unroll
    for (int r = 0; r < 32; r += 8)
        tile[ty + r][tx] = g_G[(kB + ty + r) * N0 + nB + tx];
    __syncthreads();
#pragma unroll
    for (int r = 0; r < 32; r += 8)
        outS[(nB + ty + r) * KDIM + kB + tx] = tile[tx][ty + r];
}

extern "C" void kernel_launch(void* const* d_in, const int* in_sizes, int n_in,
                              void* d_out, int out_size) {
    const float* e    = (const float*)d_in[0];
    const float* eg   = (const float*)d_in[1];
    const float* s    = (const float*)d_in[2];
    const float* sg   = (const float*)d_in[3];
    const float* Lh0  = (const float*)d_in[4];
    const float* Lc0  = (const float*)d_in[5];
    const float* Lb   = (const float*)d_in[6];
    const float* Wih0 = (const float*)d_in[7];
    const float* Whh0 = (const float*)d_in[8];
    const float* bih0 = (const float*)d_in[9];
    const float* bhh0 = (const float*)d_in[10];
    const float* Wih1 = (const float*)d_in[11];
    const float* Whh1 = (const float*)d_in[12];
    const float* bih1 = (const float*)d_in[13];
    const float* bhh1 = (const float*)d_in[14];
    const float* Wl   = (const float*)d_in[15];
    const float* bl   = (const float*)d_in[16];
    const float* e_lr = (const float*)d_in[17];
    const float* s_lr = (const float*)d_in[18];
    float* out = (float*)d_out;

    k_update_e<<<16384, 256>>>((const float4*)e, (const float4*)eg, e_lr,
                               (float4*)(out + O_E));
    k_make_MMg<<<dim3(144, 16), dim3(32, 8)>>>(s, sg, s_lr);
    // splits for Gram(M^T Mg) and proj
    k_tsplit<<<dim3(144, 16), dim3(32, 8)>>>(0);   // M^T  -> MT
    k_tsplit<<<dim3(144, 16), dim3(32, 8)>>>(2);   // Mg^T -> XT
    k_rsplit<<<2304, 256>>>(0);                    // M rows -> MR
    // Sym = sym(M^T Mg); G = Mg - M @ Sym
    k_gram_mma<<<dim3(4, 8, 4), 256>>>(0, 1);
    k_reduce_sym<<<512, 512>>>(0);
    k_bprep<<<512, 512>>>(0);
    k_proj_mma<<<dim3(36, 8), 256>>>(0);
    // LogAndSign -> LSTM -> L
    k_rowsq<<<576, 256>>>();
    k_lstm<<<18, 256>>>(Lh0, Lc0, Wih0, Whh0, bih0, bhh0,
                        Wih1, Whh1, bih1, bhh1, Wl, bl, out);
    k_mean<<<1, 256>>>();
    k_build_L<<<20736, 256>>>((const float4*)Lb, (float4*)(out + O_L));
    // LG on tensor cores
    k_tsplit<<<dim3(144, 16), dim3(32, 8)>>>(3);   // G^T -> Gt
    k_lg_mma<<<dim3(36, 8), 256>>>();
    // A = M + LG - M @ sym(M^T LG)
    k_tsplit<<<dim3(144, 16), dim3(32, 8)>>>(1);   // LG^T -> XT
    k_gram_mma<<<dim3(4, 8, 4), 256>>>(0, 1);
    k_reduce_sym<<<512, 512>>>(0);
    k_bprep<<<512, 512>>>(0);
    k_proj_mma<<<dim3(36, 8), 256>>>(1);
    // CholQR pass 1 (fp32 Gram + chol + TRSM): Q1 = A R1^{-1}
    k_gemm_tn<<<dim3(8, 8, 4), 256>>>();
    k_reduce_sym<<<512, 512>>>(1);
    for (int p = 0; p < 8; p++) {
        k_chol_diag<<<1, 256>>>(p);
        if (p < 7) {
            k_chol_offdiag<<<7 - p, 256>>>(p);
            int t7 = 7 - p;
            k_chol_syrk<<<t7 * (t7 + 1) / 2, 256>>>(p);
        }
    }
    for (int p = 0; p < 8; p++) k_qpanel<<<72, 256>>>(p);
    // Newton pass 2 (HMMA): E-gram, U, Q2 = Q1 - Q1 U
    k_tsplit<<<dim3(144, 16), dim3(32, 8)>>>(1);   // Q1^T -> XT
    k_rsplit<<<2304, 256>>>(1);                    // Q1 rows -> XR
    k_gram_mma<<<dim3(4, 8, 4), 256>>>(1, 1);
    k_reduce_sym<<<512, 512>>>(0);
    k_bprep<<<512, 512>>>(1);
    k_proj_mma<<<dim3(36, 8), 256>>>(2);
    // new_s
    k_write_s<<<dim3(144, 16), dim3(32, 8)>>>(out + O_S);
}

// round 13
// speedup vs baseline: 2.1257x; 1.1626x over previous
#include <cuda_runtime.h>
#include <cuda_bf16.h>
#include <math.h>
#include <stdint.h>

#define KDIM 4608
#define N0   512
#define WDC  0.0005f

// output layout (floats): new_e, new_s, L, hn, cn
#define O_E 0
#define O_S 16777216
#define O_L 19136512
#define O_H 40370176
#define O_C 40554496

// ---------------- scratch (device globals; no allocation allowed) ----------------
__device__ __align__(256) float g_M[KDIM * N0];
__device__ __align__(256) float g_G[KDIM * N0];      // Mg -> G -> Q2
__device__ __align__(256) float g_A[KDIM * N0];      // LG -> A -> Q1
__device__ __align__(256) float g_S[N0 * N0];        // Gram -> chol L (lower)
__device__ __align__(256) float g_Sym[N0 * N0];
__device__ __align__(256) float g_part[4 * N0 * N0]; // split-K partials / Linv
__device__ __align__(256) float g_x[KDIM];
__device__ __align__(256) float g_lraw[KDIM];
__device__ float g_mean;
__device__ __align__(256) __nv_bfloat16 g_Lhi[(size_t)KDIM * KDIM];
__device__ __align__(256) __nv_bfloat16 g_Llo[(size_t)KDIM * KDIM];
__device__ __align__(256) __nv_bfloat16 g_Gthi[(size_t)N0 * KDIM];
__device__ __align__(256) __nv_bfloat16 g_Gtlo[(size_t)N0 * KDIM];
__device__ __align__(256) __nv_bfloat16 g_MThi[(size_t)N0 * KDIM];
__device__ __align__(256) __nv_bfloat16 g_MTlo[(size_t)N0 * KDIM];
__device__ __align__(256) __nv_bfloat16 g_XThi[(size_t)N0 * KDIM];
__device__ __align__(256) __nv_bfloat16 g_XTlo[(size_t)N0 * KDIM];
__device__ __align__(256) __nv_bfloat16 g_MRhi[(size_t)KDIM * N0];
__device__ __align__(256) __nv_bfloat16 g_MRlo[(size_t)KDIM * N0];
__device__ __align__(256) __nv_bfloat16 g_XRhi[(size_t)KDIM * N0];
__device__ __align__(256) __nv_bfloat16 g_XRlo[(size_t)KDIM * N0];
__device__ __align__(256) __nv_bfloat16 g_Bophi[N0 * N0];
__device__ __align__(256) __nv_bfloat16 g_Boplo[N0 * N0];

__device__ __forceinline__ float sigf(float z) { return 1.0f / (1.0f + expf(-z)); }

#define MMA16(ACC, AV, BV)                                                       \
    asm volatile("mma.sync.aligned.m16n8k16.row.col.f32.bf16.bf16.f32 "          \
                 "{%0,%1,%2,%3}, {%4,%5,%6,%7}, {%8,%9}, {%0,%1,%2,%3};"         \
                 : "+f"((ACC)[0]), "+f"((ACC)[1]), "+f"((ACC)[2]), "+f"((ACC)[3])\
                 : "r"((AV)[0]), "r"((AV)[1]), "r"((AV)[2]), "r"((AV)[3]),       \
                   "r"((BV)[0]), "r"((BV)[1]))

// ---------------- new_e ----------------
__global__ void k_update_e(const float4* __restrict__ e, const float4* __restrict__ eg,
                           const float* __restrict__ e_lr, float4* __restrict__ out) {
    int i = blockIdx.x * 256 + threadIdx.x;
    float lr = *e_lr;
    float4 a = e[i], g = eg[i];
    float4 r;
    r.x = a.x - lr * (g.x + WDC * a.x);
    r.y = a.y - lr * (g.y + WDC * a.y);
    r.z = a.z - lr * (g.z + WDC * a.z);
    r.w = a.w - lr * (g.w + WDC * a.w);
    out[i] = r;
}

// ---------------- M, Mg ----------------
__global__ void k_make_MMg(const float* __restrict__ s, const float* __restrict__ sg,
                           const float* __restrict__ s_lr) {
    __shared__ float t0[32][33];
    __shared__ float t1[32][33];
    int iB = blockIdx.x * 32, jB = blockIdx.y * 32;
    int tx = threadIdx.x, ty = threadIdx.y;
#pragma unroll
    for (int r = 0; r < 32; r += 8) {
        t0[ty + r][tx] = s [(jB + ty + r) * KDIM + iB + tx];
        t1[ty + r][tx] = sg[(jB + ty + r) * KDIM + iB + tx];
    }
    __syncthreads();
    float nslr = -(*s_lr);
#pragma unroll
    for (int r = 0; r < 32; r += 8) {
        int i = iB + ty + r;
        g_M[i * N0 + jB + tx] = t0[tx][ty + r];
        g_G[i * N0 + jB + tx] = nslr * t1[tx][ty + r];
    }
}

// ---------------- fp32 Gram (pass-1 only): C = A^T A split-K ----------------
__global__ void k_gemm_tn() {
    const float* A = g_A;
    __shared__ __align__(16) float As[16][68];
    __shared__ __align__(16) float Bs[16][68];
    int a0 = blockIdx.x * 64, b0 = blockIdx.y * 64;
    int k0 = blockIdx.z * (KDIM / 4);
    int t = threadIdx.x, tx = t & 15, ty = t >> 4;
    int lr = t >> 4, lc = t & 15;
    float acc[4][4] = {};
    for (int kk = 0; kk < KDIM / 4; kk += 16) {
        float4 va = *(const float4*)&A[(k0 + kk + lr) * N0 + a0 + lc * 4];
        float4 vb = *(const float4*)&A[(k0 + kk + lr) * N0 + b0 + lc * 4];
        *(float4*)&As[lr][lc * 4] = va;
        *(float4*)&Bs[lr][lc * 4] = vb;
        __syncthreads();
#pragma unroll
        for (int k = 0; k < 16; k++) {
            float4 av = *(const float4*)&As[k][ty * 4];
            float4 bv = *(const float4*)&Bs[k][tx * 4];
            float a_[4] = {av.x, av.y, av.z, av.w};
            float b_[4] = {bv.x, bv.y, bv.z, bv.w};
#pragma unroll
            for (int u = 0; u < 4; u++)
#pragma unroll
                for (int v = 0; v < 4; v++) acc[u][v] += a_[u] * b_[v];
        }
        __syncthreads();
    }
    float* C = g_part + blockIdx.z * (N0 * N0);
#pragma unroll
    for (int u = 0; u < 4; u++)
#pragma unroll
        for (int v = 0; v < 4; v++)
            C[(a0 + ty * 4 + u) * N0 + (b0 + tx * 4 + v)] = acc[u][v];
}

// ------- reduce split-K + symmetrize; optionally emit Bop split (bmode -1/0/1) -------
__global__ void k_reduce_sym(int dst, int bmode) {
    int idx = blockIdx.x * 512 + threadIdx.x;
    int a = idx >> 9, b = idx & 511;
    float s1 = 0.f, s2 = 0.f;
#pragma unroll
    for (int z = 0; z < 4; z++) {
        s1 += g_part[z * N0 * N0 + idx];
        s2 += g_part[z * N0 * N0 + b * N0 + a];
    }
    float v = 0.5f * (s1 + s2);
    if (dst == 0) g_Sym[idx] = v; else g_S[idx] = v;
    if (bmode >= 0) {
        float bv = v;
        if (bmode == 1)
            bv = (b < a) ? v : ((b == a) ? 0.5f * (v - 1.0f) : 0.0f);
        __nv_bfloat16 h = __float2bfloat16(bv);
        g_Bophi[idx] = h;
        g_Boplo[idx] = __float2bfloat16(bv - __bfloat162float(h));
    }
}

// ---------------- transpose + split: sel 0:M->MT 1:A->XT 2:G->XT 3:G->Gt ----------------
__global__ void k_tsplit(int sel) {
    __shared__ float tile[32][33];
    const float* src = (sel == 0) ? g_M : (sel == 1) ? g_A : g_G;
    __nv_bfloat16* dh = (sel == 0) ? g_MThi : (sel == 3) ? g_Gthi : g_XThi;
    __nv_bfloat16* dl = (sel == 0) ? g_MTlo : (sel == 3) ? g_Gtlo : g_XTlo;
    int kB = blockIdx.x * 32, nB = blockIdx.y * 32;
    int tx = threadIdx.x, ty = threadIdx.y;
#pragma unroll
    for (int r = 0; r < 32; r += 8)
        tile[ty + r][tx] = src[(kB + ty + r) * N0 + nB + tx];
    __syncthreads();
#pragma unroll
    for (int r = 0; r < 32; r += 8) {
        float v = tile[tx][ty + r];
        __nv_bfloat16 h = __float2bfloat16(v);
        size_t idx = (size_t)(nB + ty + r) * KDIM + kB + tx;
        dh[idx] = h;
        dl[idx] = __float2bfloat16(v - __bfloat162float(h));
    }
}

// ---------------- row split: sel 0:M->MR 1:A->XR ----------------
__global__ void k_rsplit(int sel) {
    int gid = blockIdx.x * 256 + threadIdx.x;
    const float4* src = (const float4*)(sel ? g_A : g_M);
    __nv_bfloat162* dh = (__nv_bfloat162*)(sel ? g_XRhi : g_MRhi);
    __nv_bfloat162* dl = (__nv_bfloat162*)(sel ? g_XRlo : g_MRlo);
    float4 v = src[gid];
    __nv_bfloat16 hx = __float2bfloat16(v.x), hy = __float2bfloat16(v.y);
    __nv_bfloat16 hz = __float2bfloat16(v.z), hw = __float2bfloat16(v.w);
    dh[2 * gid]     = __nv_bfloat162(hx, hy);
    dh[2 * gid + 1] = __nv_bfloat162(hz, hw);
    dl[2 * gid]     = __nv_bfloat162(__float2bfloat16(v.x - __bfloat162float(hx)),
                                     __float2bfloat16(v.y - __bfloat162float(hy)));
    dl[2 * gid + 1] = __nv_bfloat162(__float2bfloat16(v.z - __bfloat162float(hz)),
                                     __float2bfloat16(v.w - __bfloat162float(hw)));
}

// ---------------- Bop from Linv (g_part, lower-masked) ----------------
__global__ void k_bsplit_linv() {
    int j = blockIdx.x, a = threadIdx.x;
    float v = (a <= j) ? g_part[j * N0 + a] : 0.0f;
    __nv_bfloat16 h = __float2bfloat16(v);
    g_Bophi[j * N0 + a] = h;
    g_Boplo[j * N0 + a] = __float2bfloat16(v - __bfloat162float(h));
}

// ---------------- shared HMMA core (3-term split-bf16, 128x64 tile) ----------------
struct MmaPtrs {
    const __nv_bfloat16 *Ah, *Al, *Bh, *Bl;
};

template <int STRIDE>
__device__ __forceinline__ void mma_tile_loop(
    const MmaPtrs& P, int i0, int n0t, int kbeg, int kend, float acc[2][4][4],
    __nv_bfloat16 (*sAh)[40], __nv_bfloat16 (*sAl)[40],
    __nv_bfloat16 (*sBh)[40], __nv_bfloat16 (*sBl)[40]) {
    int t = threadIdx.x, lane = t & 31, wid = t >> 5;
    int wy = wid >> 1, wx = wid & 1;
    int ar0 = t >> 2, ac0 = (t & 3) * 8;
    int ar1 = ar0 + 64;
    int gr = lane >> 2, lc2 = (lane & 3) * 2;
    uint4 vAh0 = *(const uint4*)(P.Ah + (size_t)(i0 + ar0) * STRIDE + kbeg + ac0);
    uint4 vAh1 = *(const uint4*)(P.Ah + (size_t)(i0 + ar1) * STRIDE + kbeg + ac0);
    uint4 vAl0 = *(const uint4*)(P.Al + (size_t)(i0 + ar0) * STRIDE + kbeg + ac0);
    uint4 vAl1 = *(const uint4*)(P.Al + (size_t)(i0 + ar1) * STRIDE + kbeg + ac0);
    uint4 vBh  = *(const uint4*)(P.Bh + (size_t)(n0t + ar0) * STRIDE + kbeg + ac0);
    uint4 vBl  = *(const uint4*)(P.Bl + (size_t)(n0t + ar0) * STRIDE + kbeg + ac0);
    for (int k0 = kbeg; k0 < kend; k0 += 32) {
        *(uint4*)&sAh[ar0][ac0] = vAh0;
        *(uint4*)&sAh[ar1][ac0] = vAh1;
        *(uint4*)&sAl[ar0][ac0] = vAl0;
        *(uint4*)&sAl[ar1][ac0] = vAl1;
        *(uint4*)&sBh[ar0][ac0] = vBh;
        *(uint4*)&sBl[ar0][ac0] = vBl;
        __syncthreads();
        if (k0 + 32 < kend) {
            size_t ko = (size_t)(k0 + 32 + ac0);
            vAh0 = *(const uint4*)(P.Ah + (size_t)(i0 + ar0) * STRIDE + ko);
            vAh1 = *(const uint4*)(P.Ah + (size_t)(i0 + ar1) * STRIDE + ko);
            vAl0 = *(const uint4*)(P.Al + (size_t)(i0 + ar0) * STRIDE + ko);
            vAl1 = *(const uint4*)(P.Al + (size_t)(i0 + ar1) * STRIDE + ko);
            vBh  = *(const uint4*)(P.Bh + (size_t)(n0t + ar0) * STRIDE + ko);
            vBl  = *(const uint4*)(P.Bl + (size_t)(n0t + ar0) * STRIDE + ko);
        }
#pragma unroll
        for (int kk = 0; kk < 32; kk += 16) {
            uint32_t ah[2][4], al[2][4], bh[4][2], bl[4][2];
#pragma unroll
            for (int mb = 0; mb < 2; mb++) {
                int r = wy * 32 + mb * 16 + gr;
                ah[mb][0] = *(const uint32_t*)&sAh[r][kk + lc2];
                ah[mb][1] = *(const uint32_t*)&sAh[r + 8][kk + lc2];
                ah[mb][2] = *(const uint32_t*)&sAh[r][kk + lc2 + 8];
                ah[mb][3] = *(const uint32_t*)&sAh[r + 8][kk + lc2 + 8];
                al[mb][0] = *(const uint32_t*)&sAl[r][kk + lc2];
                al[mb][1] = *(const uint32_t*)&sAl[r + 8][kk + lc2];
                al[mb][2] = *(const uint32_t*)&sAl[r][kk + lc2 + 8];
                al[mb][3] = *(const uint32_t*)&sAl[r + 8][kk + lc2 + 8];
            }
#pragma unroll
            for (int nb = 0; nb < 4; nb++) {
                int bn = wx * 32 + nb * 8 + gr;
                bh[nb][0] = *(const uint32_t*)&sBh[bn][kk + lc2];
                bh[nb][1] = *(const uint32_t*)&sBh[bn][kk + lc2 + 8];
                bl[nb][0] = *(const uint32_t*)&sBl[bn][kk + lc2];
                bl[nb][1] = *(const uint32_t*)&sBl[bn][kk + lc2 + 8];
            }
#pragma unroll
            for (int mb = 0; mb < 2; mb++)
#pragma unroll
                for (int nb = 0; nb < 4; nb++) {
                    MMA16(acc[mb][nb], ah[mb], bh[nb]);
                    MMA16(acc[mb][nb], ah[mb], bl[nb]);
                    MMA16(acc[mb][nb], al[mb], bh[nb]);
                }
        }
        __syncthreads();
    }
}

// ---------------- g_A = L @ G (split-bf16 HMMA) ----------------
__global__ void __launch_bounds__(256) k_lg_mma() {
    __shared__ __align__(16) __nv_bfloat16 sAh[128][40];
    __shared__ __align__(16) __nv_bfloat16 sAl[128][40];
    __shared__ __align__(16) __nv_bfloat16 sBh[64][40];
    __shared__ __align__(16) __nv_bfloat16 sBl[64][40];
    int t = threadIdx.x, wid = t >> 5, lane = t & 31;
    int i0 = blockIdx.x * 128, n0t = blockIdx.y * 64;
    int wy = wid >> 1, wx = wid & 1;
    int gr = lane >> 2, lc2 = (lane & 3) * 2;
    float acc[2][4][4] = {};
    MmaPtrs P = {g_Lhi, g_Llo, g_Gthi, g_Gtlo};
    mma_tile_loop<KDIM>(P, i0, n0t, 0, KDIM, acc, sAh, sAl, sBh, sBl);
#pragma unroll
    for (int mb = 0; mb < 2; mb++)
#pragma unroll
        for (int nb = 0; nb < 4; nb++) {
            int row = i0 + wy * 32 + mb * 16 + gr;
            int col = n0t + wx * 32 + nb * 8 + lc2;
            g_A[(size_t)row * N0 + col]           = acc[mb][nb][0];
            g_A[(size_t)row * N0 + col + 1]       = acc[mb][nb][1];
            g_A[(size_t)(row + 8) * N0 + col]     = acc[mb][nb][2];
            g_A[(size_t)(row + 8) * N0 + col + 1] = acc[mb][nb][3];
        }
}

// ---------------- Gram via HMMA: partial C = At·Bt^T over k-chunk ----------------
__global__ void __launch_bounds__(256) k_gram_mma(int selA, int selB) {
    __shared__ __align__(16) __nv_bfloat16 sAh[128][40];
    __shared__ __align__(16) __nv_bfloat16 sAl[128][40];
    __shared__ __align__(16) __nv_bfloat16 sBh[64][40];
    __shared__ __align__(16) __nv_bfloat16 sBl[64][40];
    int t = threadIdx.x, wid = t >> 5, lane = t & 31;
    int i0 = blockIdx.x * 128, n0t = blockIdx.y * 64;
    int kbeg = blockIdx.z * (KDIM / 4);
    int wy = wid >> 1, wx = wid & 1;
    int gr = lane >> 2, lc2 = (lane & 3) * 2;
    float acc[2][4][4] = {};
    MmaPtrs P = {selA ? g_XThi : g_MThi, selA ? g_XTlo : g_MTlo,
                 selB ? g_XThi : g_MThi, selB ? g_XTlo : g_MTlo};
    mma_tile_loop<KDIM>(P, i0, n0t, kbeg, kbeg + KDIM / 4, acc, sAh, sAl, sBh, sBl);
    float* C = g_part + blockIdx.z * (N0 * N0);
#pragma unroll
    for (int mb = 0; mb < 2; mb++)
#pragma unroll
        for (int nb = 0; nb < 4; nb++) {
            int row = i0 + wy * 32 + mb * 16 + gr;
            int col = n0t + wx * 32 + nb * 8 + lc2;
            C[(size_t)row * N0 + col]           = acc[mb][nb][0];
            C[(size_t)row * N0 + col + 1]       = acc[mb][nb][1];
            C[(size_t)(row + 8) * N0 + col]     = acc[mb][nb][2];
            C[(size_t)(row + 8) * N0 + col + 1] = acc[mb][nb][3];
        }
}

// -- proj via HMMA; mode 0: G-=M·Bop  1: A=M+A-M·Bop  2: G=A-A·Bop  3: A=A·Bop --
__global__ void __launch_bounds__(256) k_proj_mma(int mode) {
    __shared__ __align__(16) __nv_bfloat16 sAh[128][40];
    __shared__ __align__(16) __nv_bfloat16 sAl[128][40];
    __shared__ __align__(16) __nv_bfloat16 sBh[64][40];
    __shared__ __align__(16) __nv_bfloat16 sBl[64][40];
    int t = threadIdx.x, wid = t >> 5, lane = t & 31;
    int i0 = blockIdx.x * 128, n0t = blockIdx.y * 64;
    int wy = wid >> 1, wx = wid & 1;
    int gr = lane >> 2, lc2 = (lane & 3) * 2;
    float acc[2][4][4] = {};
    MmaPtrs P = {(mode >= 2) ? g_XRhi : g_MRhi, (mode >= 2) ? g_XRlo : g_MRlo,
                 g_Bophi, g_Boplo};
    mma_tile_loop<N0>(P, i0, n0t, 0, N0, acc, sAh, sAl, sBh, sBl);
#pragma unroll
    for (int mb = 0; mb < 2; mb++)
#pragma unroll
        for (int nb = 0; nb < 4; nb++) {
            int row = i0 + wy * 32 + mb * 16 + gr;
            int col = n0t + wx * 32 + nb * 8 + lc2;
#pragma unroll
            for (int q = 0; q < 4; q++) {
                int rr = row + (q >> 1) * 8;
                int cc = col + (q & 1);
                size_t idx = (size_t)rr * N0 + cc;
                float a = acc[mb][nb][q];
                if (mode == 0)      g_G[idx] = g_G[idx] - a;
                else if (mode == 1) g_A[idx] = g_M[idx] + g_A[idx] - a;
                else if (mode == 2) g_G[idx] = g_A[idx] - a;
                else                g_A[idx] = a;
            }
        }
}

// ---------------- x[i] = clip(log(|rowsumsq(G)|)/10, -1, 1) ----------------
__global__ void k_rowsq() {
    int gt = blockIdx.x * 256 + threadIdx.x;
    int row = gt >> 5, lane = gt & 31;
    const float4* rp = (const float4*)&g_G[row * N0];
    float s = 0.f;
#pragma unroll 4
    for (int c = lane; c < 128; c += 32) {
        float4 v = rp[c];
        s += v.x * v.x + v.y * v.y + v.z * v.z + v.w * v.w;
    }
#pragma unroll
    for (int o = 16; o; o >>= 1) s += __shfl_xor_sync(0xffffffffu, s, o);
    if (lane == 0) {
        float x = logf(fabsf(s)) * 0.1f;
        g_x[row] = fminf(1.0f, fmaxf(-1.0f, x));
    }
}

// ---------------- 2-layer LSTM ----------------
__global__ void k_lstm(const float* __restrict__ Lh0, const float* __restrict__ Lc0,
                       const float* __restrict__ Wih0, const float* __restrict__ Whh0,
                       const float* __restrict__ bih0, const float* __restrict__ bhh0,
                       const float* __restrict__ Wih1, const float* __restrict__ Whh1,
                       const float* __restrict__ bih1, const float* __restrict__ bhh1,
                       const float* __restrict__ Wl, const float* __restrict__ bl,
                       float* __restrict__ out) {
    __shared__ float sWih0[80], sWhh0[1600], sb0[80];
    __shared__ float sWih1[1600], sWhh1[1600], sb1[80];
    __shared__ float sWl[20], sbl[1];
    int t = threadIdx.x;
    for (int i = t; i < 80; i += 256) {
        sWih0[i] = Wih0[i];
        sb0[i] = bih0[i] + bhh0[i];
        sb1[i] = bih1[i] + bhh1[i];
    }
    for (int i = t; i < 1600; i += 256) {
        sWhh0[i] = Whh0[i];
        sWih1[i] = Wih1[i];
        sWhh1[i] = Whh1[i];
    }
    if (t < 20) sWl[t] = Wl[t];
    if (t == 0) sbl[0] = bl[0];
    __syncthreads();

    int i = blockIdx.x * 256 + t;
    float x = g_x[i];
    float h0p[20], h1p[20], h0n[20];
#pragma unroll
    for (int h = 0; h < 20; h++) {
        h0p[h] = Lh0[i * 20 + h];
        h1p[h] = Lh0[92160 + i * 20 + h];
    }
#pragma unroll
    for (int h = 0; h < 20; h++) {
        float pi = sb0[h]      + x * sWih0[h];
        float pf = sb0[20 + h] + x * sWih0[20 + h];
        float pg = sb0[40 + h] + x * sWih0[40 + h];
        float po = sb0[60 + h] + x * sWih0[60 + h];
#pragma unroll
        for (int m = 0; m < 20; m++) {
            float hm = h0p[m];
            pi += hm * sWhh0[h * 20 + m];
            pf += hm * sWhh0[(20 + h) * 20 + m];
            pg += hm * sWhh0[(40 + h) * 20 + m];
            po += hm * sWhh0[(60 + h) * 20 + m];
        }
        float c0 = Lc0[i * 20 + h];
        float c = sigf(pf) * c0 + sigf(pi) * tanhf(pg);
        float hh = sigf(po) * tanhf(c);
        h0n[h] = hh;
        out[O_H + i * 20 + h] = hh;
        out[O_C + i * 20 + h] = c;
    }
    float lacc = sbl[0];
#pragma unroll
    for (int h = 0; h < 20; h++) {
        float pi = sb1[h], pf = sb1[20 + h], pg = sb1[40 + h], po = sb1[60 + h];
#pragma unroll
        for (int m = 0; m < 20; m++) {
            float a = h0n[m], b = h1p[m];
            pi += a * sWih1[h * 20 + m]        + b * sWhh1[h * 20 + m];
            pf += a * sWih1[(20 + h) * 20 + m] + b * sWhh1[(20 + h) * 20 + m];
            pg += a * sWih1[(40 + h) * 20 + m] + b * sWhh1[(40 + h) * 20 + m];
            po += a * sWih1[(60 + h) * 20 + m] + b * sWhh1[(60 + h) * 20 + m];
        }
        float c1 = Lc0[92160 + i * 20 + h];
        float c = sigf(pf) * c1 + sigf(pi) * tanhf(pg);
        float hh = sigf(po) * tanhf(c);
        out[O_H + 92160 + i * 20 + h] = hh;
        out[O_C + 92160 + i * 20 + h] = c;
        lacc += hh * sWl[h];
    }
    g_lraw[i] = lacc * 0.1f;
}

__global__ void k_mean() {
    __shared__ float sm[256];
    int t = threadIdx.x;
    float s = 0.f;
    for (int i = t; i < KDIM; i += 256) s += g_lraw[i];
    sm[t] = s;
    __syncthreads();
    for (int o = 128; o; o >>= 1) {
        if (t < o) sm[t] += sm[t + o];
        __syncthreads();
    }
    if (t == 0) g_mean = sm[0] * (1.0f / KDIM);
}

// ---------------- L (fp32 out + split-bf16) ----------------
__global__ void k_build_L(const float4* __restrict__ Lb, float4* __restrict__ outL) {
    int gid = blockIdx.x * 256 + threadIdx.x;
    int base = gid * 4;
    int i = base / KDIM;
    int j0 = base - i * KDIM;
    float dv = g_lraw[i] - g_mean + 1.0f;
    float4 lb = Lb[gid];
    float4 r;
    r.x = fmaxf((j0 + 0 == i) ? dv : 0.0f, lb.x);
    r.y = fmaxf((j0 + 1 == i) ? dv : 0.0f, lb.y);
    r.z = fmaxf((j0 + 2 == i) ? dv : 0.0f, lb.z);
    r.w = fmaxf((j0 + 3 == i) ? dv : 0.0f, lb.w);
    outL[gid] = r;
    __nv_bfloat16 hx = __float2bfloat16(r.x), hy = __float2bfloat16(r.y);
    __nv_bfloat16 hz = __float2bfloat16(r.z), hw = __float2bfloat16(r.w);
    __nv_bfloat162* ph = (__nv_bfloat162*)g_Lhi;
    __nv_bfloat162* pl = (__nv_bfloat162*)g_Llo;
    ph[2 * gid]     = __nv_bfloat162(hx, hy);
    ph[2 * gid + 1] = __nv_bfloat162(hz, hw);
    pl[2 * gid]     = __nv_bfloat162(__float2bfloat16(r.x - __bfloat162float(hx)),
                                     __float2bfloat16(r.y - __bfloat162float(hy)));
    pl[2 * gid + 1] = __nv_bfloat162(__float2bfloat16(r.z - __bfloat162float(hz)),
                                     __float2bfloat16(r.w - __bfloat162float(hw)));
}

// ---------------- left-looking blocked Cholesky: one launch per panel ----------------
__global__ void k_chol_left(int p) {
    __shared__ float S1[64][65];   // Lb tiles, then D
    __shared__ float S2[64][65];   // Lp tiles, then C
    int bi = p + blockIdx.x;
    int t = threadIdx.x, ty = t >> 4, tx = t & 15;
    float accC[4][4], accD[4][4];
#pragma unroll
    for (int u = 0; u < 4; u++)
#pragma unroll
        for (int v = 0; v < 4; v++) {
            accC[u][v] = g_S[(bi * 64 + ty * 4 + u) * N0 + p * 64 + tx * 4 + v];
            accD[u][v] = g_S[(p * 64 + ty * 4 + u) * N0 + p * 64 + tx * 4 + v];
        }
    for (int kb = 0; kb < p; kb++) {
        for (int idx = t; idx < 4096; idx += 256) {
            int r = idx >> 6, c = idx & 63;
            S1[r][c] = g_S[(bi * 64 + r) * N0 + kb * 64 + c];
            S2[r][c] = g_S[(p * 64 + r) * N0 + kb * 64 + c];
        }
        __syncthreads();
#pragma unroll 8
        for (int k = 0; k < 64; k++) {
            float lb_[4], lp_[4];
#pragma unroll
            for (int u = 0; u < 4; u++) { lb_[u] = S1[ty * 4 + u][k]; lp_[u] = S2[tx * 4 + u][k]; }
            float lpr[4];
#pragma unroll
            for (int u = 0; u < 4; u++) lpr[u] = S2[ty * 4 + u][k];
#pragma unroll
            for (int u = 0; u < 4; u++)
#pragma unroll
                for (int v = 0; v < 4; v++) {
                    accC[u][v] -= lb_[u] * lp_[v];
                    accD[u][v] -= lpr[u] * lp_[v];
                }
        }
        __syncthreads();
    }
    // store accD -> S1 (D), accC -> S2 (C)
#pragma unroll
    for (int u = 0; u < 4; u++)
#pragma unroll
        for (int v = 0; v < 4; v++) {
            S1[ty * 4 + u][tx * 4 + v] = accD[u][v];
            S2[ty * 4 + u][tx * 4 + v] = accC[u][v];
        }
    __syncthreads();
    // factor D (lower) in smem
    for (int j = 0; j < 64; j++) {
        if (t == 0) S1[j][j] = sqrtf(S1[j][j]);
        __syncthreads();
        float dj = S1[j][j];
        for (int r = j + 1 + t; r < 64; r += 256) S1[r][j] /= dj;
        __syncthreads();
        for (int idx = t; idx < 4096; idx += 256) {
            int r = idx >> 6, c = idx & 63;
            if (c > j && r >= c) S1[r][c] -= S1[r][j] * S1[c][j];
        }
        __syncthreads();
    }
    if (bi == p) {
        for (int idx = t; idx < 4096; idx += 256) {
            int r = idx >> 6, c = idx & 63;
            g_S[(p * 64 + r) * N0 + p * 64 + c] = S1[r][c];
        }
        return;
    }
    // TRSM: C = C * D^{-T}
    for (int j = 0; j < 64; j++) {
        float inv = 1.0f / S1[j][j];
        if (t < 64) S2[t][j] *= inv;
        __syncthreads();
        for (int idx = t; idx < 4096; idx += 256) {
            int r = idx >> 6, c = idx & 63;
            if (c > j) S2[r][c] -= S2[r][j] * S1[c][j];
        }
        __syncthreads();
    }
    for (int idx = t; idx < 4096; idx += 256) {
        int r = idx >> 6, c = idx & 63;
        g_S[(bi * 64 + r) * N0 + p * 64 + c] = S2[r][c];
    }
}

// ---------------- triangular inverse of L by diagonal sweep; Linv -> g_part --------
__global__ void k_trinv(int d) {
    __shared__ float S1[64][65];
    __shared__ float S2[64][65];
    int j = blockIdx.x, i = j + d;
    int t = threadIdx.x;
    if (d == 0) {
        for (int idx = t; idx < 4096; idx += 256) {
            int r = idx >> 6, c = idx & 63;
            S1[r][c] = g_S[(i * 64 + r) * N0 + i * 64 + c];
        }
        __syncthreads();
        if (t < 64) {
            int c = t;
            for (int r = 0; r < 64; r++) {
                if (r < c) { S2[r][c] = 0.0f; continue; }
                float s = (r == c) ? 1.0f : 0.0f;
                for (int k = c; k < r; k++) s -= S1[r][k] * S2[k][c];
                S2[r][c] = s / S1[r][r];
            }
        }
        __syncthreads();
        for (int idx = t; idx < 4096; idx += 256) {
            int r = idx >> 6, c = idx & 63;
            g_part[(i * 64 + r) * N0 + i * 64 + c] = S2[r][c];
        }
    } else {
        int ty = t >> 4, tx = t & 15;
        float acc[4][4] = {};
        for (int kb = j; kb < i; kb++) {
            for (int idx = t; idx < 4096; idx += 256) {
                int r = idx >> 6, c = idx & 63;
                S1[r][c] = g_S[(i * 64 + r) * N0 + kb * 64 + c];
                S2[r][c] = g_part[(kb * 64 + r) * N0 + j * 64 + c];
            }
            __syncthreads();
#pragma unroll 8
            for (int k = 0; k < 64; k++)
#pragma unroll
                for (int u = 0; u < 4; u++)
#pragma unroll
                    for (int v = 0; v < 4; v++)
                        acc[u][v] += S1[ty * 4 + u][k] * S2[k][tx * 4 + v];
            __syncthreads();
        }
        // Ts = acc -> S2; Dinv -> S1; out = -Dinv * Ts
#pragma unroll
        for (int u = 0; u < 4; u++)
#pragma unroll
            for (int v = 0; v < 4; v++)
                S2[ty * 4 + u][tx * 4 + v] = acc[u][v];
        for (int idx = t; idx < 4096; idx += 256) {
            int r = idx >> 6, c = idx & 63;
            S1[r][c] = g_part[(i * 64 + r) * N0 + i * 64 + c];
        }
        __syncthreads();
        float outv[4][4] = {};
#pragma unroll 8
        for (int m = 0; m < 64; m++)
#pragma unroll
            for (int u = 0; u < 4; u++)
#pragma unroll
                for (int v = 0; v < 4; v++)
                    outv[u][v] -= S1[ty * 4 + u][m] * S2[m][tx * 4 + v];
#pragma unroll
        for (int u = 0; u < 4; u++)
#pragma unroll
            for (int v = 0; v < 4; v++)
                g_part[(i * 64 + ty * 4 + u) * N0 + j * 64 + tx * 4 + v] = outv[u][v];
    }
}

// ---------------- new_s = Q2^T ----------------
__global__ void k_write_s(float* __restrict__ outS) {
    __shared__ float tile[32][33];
    int kB = blockIdx.x * 32, nB = blockIdx.y * 32;
    int tx = threadIdx.x, ty = threadIdx.y;
#pragma unroll
    for (int r = 0; r < 32; r += 8)
        tile[ty + r][tx] = g_G[(kB + ty + r) * N0 + nB + tx];
    __syncthreads();
#pragma unroll
    for (int r = 0; r < 32; r += 8)
        outS[(nB + ty + r) * KDIM + kB + tx] = tile[tx][ty + r];
}

extern "C" void kernel_launch(void* const* d_in, const int* in_sizes, int n_in,
                              void* d_out, int out_size) {
    const float* e    = (const float*)d_in[0];
    const float* eg   = (const float*)d_in[1];
    const float* s    = (const float*)d_in[2];
    const float* sg   = (const float*)d_in[3];
    const float* Lh0  = (const float*)d_in[4];
    const float* Lc0  = (const float*)d_in[5];
    const float* Lb   = (const float*)d_in[6];
    const float* Wih0 = (const float*)d_in[7];
    const float* Whh0 = (const float*)d_in[8];
    const float* bih0 = (const float*)d_in[9];
    const float* bhh0 = (const float*)d_in[10];
    const float* Wih1 = (const float*)d_in[11];
    const float* Whh1 = (const float*)d_in[12];
    const float* bih1 = (const float*)d_in[13];
    const float* bhh1 = (const float*)d_in[14];
    const float* Wl   = (const float*)d_in[15];
    const float* bl   = (const float*)d_in[16];
    const float* e_lr = (const float*)d_in[17];
    const float* s_lr = (const float*)d_in[18];
    float* out = (float*)d_out;

    k_update_e<<<16384, 256>>>((const float4*)e, (const float4*)eg, e_lr,
                               (float4*)(out + O_E));
    k_make_MMg<<<dim3(144, 16), dim3(32, 8)>>>(s, sg, s_lr);
    k_tsplit<<<dim3(144, 16), dim3(32, 8)>>>(0);   // M^T  -> MT
    k_tsplit<<<dim3(144, 16), dim3(32, 8)>>>(2);   // Mg^T -> XT
    k_rsplit<<<2304, 256>>>(0);                    // M rows -> MR
    // Sym = sym(M^T Mg) (+Bop); G = Mg - M @ Sym
    k_gram_mma<<<dim3(4, 8, 4), 256>>>(0, 1);
    k_reduce_sym<<<512, 512>>>(0, 0);
    k_proj_mma<<<dim3(36, 8), 256>>>(0);
    // LogAndSign -> LSTM -> L
    k_rowsq<<<576, 256>>>();
    k_lstm<<<18, 256>>>(Lh0, Lc0, Wih0, Whh0, bih0, bhh0,
                        Wih1, Whh1, bih1, bhh1, Wl, bl, out);
    k_mean<<<1, 256>>>();
    k_build_L<<<20736, 256>>>((const float4*)Lb, (float4*)(out + O_L));
    // LG on tensor cores
    k_tsplit<<<dim3(144, 16), dim3(32, 8)>>>(3);   // G^T -> Gt
    k_lg_mma<<<dim3(36, 8), 256>>>();
    // A = M + LG - M @ sym(M^T LG)
    k_tsplit<<<dim3(144, 16), dim3(32, 8)>>>(1);   // LG^T -> XT
    k_gram_mma<<<dim3(4, 8, 4), 256>>>(0, 1);
    k_reduce_sym<<<512, 512>>>(0, 0);
    k_proj_mma<<<dim3(36, 8), 256>>>(1);
    // CholQR pass 1: fp32 Gram -> left-looking chol (8 launches) -> L^{-1} -> Q1 = A·Linv^T
    k_gemm_tn<<<dim3(8, 8, 4), 256>>>();
    k_reduce_sym<<<512, 512>>>(1, -1);
    for (int p = 0; p < 8; p++) k_chol_left<<<8 - p, 256>>>(p);
    for (int d = 0; d < 8; d++) k_trinv<<<8 - d, 256>>>(d);
    k_bsplit_linv<<<512, 512>>>();
    k_rsplit<<<2304, 256>>>(1);                    // A rows -> XR
    k_proj_mma<<<dim3(36, 8), 256>>>(3);           // g_A = Q1
    // Newton pass 2: E-gram (+Bop U), Q2 = Q1 - Q1 U
    k_tsplit<<<dim3(144, 16), dim3(32, 8)>>>(1);   // Q1^T -> XT
    k_rsplit<<<2304, 256>>>(1);                    // Q1 rows -> XR
    k_gram_mma<<<dim3(4, 8, 4), 256>>>(1, 1);
    k_reduce_sym<<<512, 512>>>(0, 1);
    k_proj_mma<<<dim3(36, 8), 256>>>(2);
    // new_s
    k_write_s<<<dim3(144, 16), dim3(32, 8)>>>(out + O_S);
}

// round 14
// speedup vs baseline: 2.1277x; 1.0009x over previous
#include <cuda_runtime.h>
#include <cuda_bf16.h>
#include <math.h>
#include <stdint.h>

#define KDIM 4608
#define N0   512
#define WDC  0.0005f

// output layout (floats): new_e, new_s, L, hn, cn
#define O_E 0
#define O_S 16777216
#define O_L 19136512
#define O_H 40370176
#define O_C 40554496

// ---------------- scratch ----------------
__device__ __align__(256) float g_M[KDIM * N0];
__device__ __align__(256) float g_G[KDIM * N0];      // Mg -> G -> Q2
__device__ __align__(256) float g_A[KDIM * N0];      // LG -> A -> Q1
__device__ __align__(256) float g_S[N0 * N0];        // Gram -> chol L (lower)
__device__ __align__(256) float g_Sym[N0 * N0];
__device__ __align__(256) float g_part[4 * N0 * N0]; // split-K partials / Linv
__device__ __align__(256) float g_x[KDIM];
__device__ __align__(256) float g_lraw[KDIM];
__device__ float g_mean;
__device__ __align__(256) __nv_bfloat16 g_Lhi[(size_t)KDIM * KDIM];
__device__ __align__(256) __nv_bfloat16 g_Llo[(size_t)KDIM * KDIM];
__device__ __align__(256) __nv_bfloat16 g_Gthi[(size_t)N0 * KDIM];  // G^T; later Q1 rows
__device__ __align__(256) __nv_bfloat16 g_Gtlo[(size_t)N0 * KDIM];
__device__ __align__(256) __nv_bfloat16 g_MThi[(size_t)N0 * KDIM];
__device__ __align__(256) __nv_bfloat16 g_MTlo[(size_t)N0 * KDIM];
__device__ __align__(256) __nv_bfloat16 g_XThi[(size_t)N0 * KDIM];
__device__ __align__(256) __nv_bfloat16 g_XTlo[(size_t)N0 * KDIM];
__device__ __align__(256) __nv_bfloat16 g_MRhi[(size_t)KDIM * N0];
__device__ __align__(256) __nv_bfloat16 g_MRlo[(size_t)KDIM * N0];
__device__ __align__(256) __nv_bfloat16 g_XRhi[(size_t)KDIM * N0];
__device__ __align__(256) __nv_bfloat16 g_XRlo[(size_t)KDIM * N0];
__device__ __align__(256) __nv_bfloat16 g_Bophi[N0 * N0];
__device__ __align__(256) __nv_bfloat16 g_Boplo[N0 * N0];

__device__ __forceinline__ float sigf(float z) { return 1.0f / (1.0f + expf(-z)); }

#define MMA16(ACC, AV, BV)                                                       \
    asm volatile("mma.sync.aligned.m16n8k16.row.col.f32.bf16.bf16.f32 "          \
                 "{%0,%1,%2,%3}, {%4,%5,%6,%7}, {%8,%9}, {%0,%1,%2,%3};"         \
                 : "+f"((ACC)[0]), "+f"((ACC)[1]), "+f"((ACC)[2]), "+f"((ACC)[3])\
                 : "r"((AV)[0]), "r"((AV)[1]), "r"((AV)[2]), "r"((AV)[3]),       \
                   "r"((BV)[0]), "r"((BV)[1]))

// ---------------- new_e ----------------
__global__ void k_update_e(const float4* __restrict__ e, const float4* __restrict__ eg,
                           const float* __restrict__ e_lr, float4* __restrict__ out) {
    int i = blockIdx.x * 256 + threadIdx.x;
    float lr = *e_lr;
    float4 a = e[i], g = eg[i];
    float4 r;
    r.x = a.x - lr * (g.x + WDC * a.x);
    r.y = a.y - lr * (g.y + WDC * a.y);
    r.z = a.z - lr * (g.z + WDC * a.z);
    r.w = a.w - lr * (g.w + WDC * a.w);
    out[i] = r;
}

// ---------------- M, Mg (row-major 4608x512) ----------------
__global__ void k_make_MMg(const float* __restrict__ s, const float* __restrict__ sg,
                           const float* __restrict__ s_lr) {
    __shared__ float t0[32][33];
    __shared__ float t1[32][33];
    int iB = blockIdx.x * 32, jB = blockIdx.y * 32;
    int tx = threadIdx.x, ty = threadIdx.y;
#pragma unroll
    for (int r = 0; r < 32; r += 8) {
        t0[ty + r][tx] = s [(jB + ty + r) * KDIM + iB + tx];
        t1[ty + r][tx] = sg[(jB + ty + r) * KDIM + iB + tx];
    }
    __syncthreads();
    float nslr = -(*s_lr);
#pragma unroll
    for (int r = 0; r < 32; r += 8) {
        int i = iB + ty + r;
        g_M[i * N0 + jB + tx] = t0[tx][ty + r];
        g_G[i * N0 + jB + tx] = nslr * t1[tx][ty + r];
    }
}

// ---------------- split directly from s/sg (already M^T layout) ----------------
__global__ void k_stsplit(const float4* __restrict__ src, const float* __restrict__ lr,
                          int sel) {
    int gid = blockIdx.x * 256 + threadIdx.x;
    float sc = sel ? -(*lr) : 1.0f;
    float4 v = src[gid];
    v.x *= sc; v.y *= sc; v.z *= sc; v.w *= sc;
    __nv_bfloat162* dh = (__nv_bfloat162*)(sel ? g_XThi : g_MThi);
    __nv_bfloat162* dl = (__nv_bfloat162*)(sel ? g_XTlo : g_MTlo);
    __nv_bfloat16 hx = __float2bfloat16(v.x), hy = __float2bfloat16(v.y);
    __nv_bfloat16 hz = __float2bfloat16(v.z), hw = __float2bfloat16(v.w);
    dh[2 * gid]     = __nv_bfloat162(hx, hy);
    dh[2 * gid + 1] = __nv_bfloat162(hz, hw);
    dl[2 * gid]     = __nv_bfloat162(__float2bfloat16(v.x - __bfloat162float(hx)),
                                     __float2bfloat16(v.y - __bfloat162float(hy)));
    dl[2 * gid + 1] = __nv_bfloat162(__float2bfloat16(v.z - __bfloat162float(hz)),
                                     __float2bfloat16(v.w - __bfloat162float(hw)));
}

// ---------------- fp32 Gram (pass-1 only): C = A^T A split-K ----------------
__global__ void k_gemm_tn() {
    const float* A = g_A;
    __shared__ __align__(16) float As[16][68];
    __shared__ __align__(16) float Bs[16][68];
    int a0 = blockIdx.x * 64, b0 = blockIdx.y * 64;
    int k0 = blockIdx.z * (KDIM / 4);
    int t = threadIdx.x, tx = t & 15, ty = t >> 4;
    int lr = t >> 4, lc = t & 15;
    float acc[4][4] = {};
    for (int kk = 0; kk < KDIM / 4; kk += 16) {
        float4 va = *(const float4*)&A[(k0 + kk + lr) * N0 + a0 + lc * 4];
        float4 vb = *(const float4*)&A[(k0 + kk + lr) * N0 + b0 + lc * 4];
        *(float4*)&As[lr][lc * 4] = va;
        *(float4*)&Bs[lr][lc * 4] = vb;
        __syncthreads();
#pragma unroll
        for (int k = 0; k < 16; k++) {
            float4 av = *(const float4*)&As[k][ty * 4];
            float4 bv = *(const float4*)&Bs[k][tx * 4];
            float a_[4] = {av.x, av.y, av.z, av.w};
            float b_[4] = {bv.x, bv.y, bv.z, bv.w};
#pragma unroll
            for (int u = 0; u < 4; u++)
#pragma unroll
                for (int v = 0; v < 4; v++) acc[u][v] += a_[u] * b_[v];
        }
        __syncthreads();
    }
    float* C = g_part + blockIdx.z * (N0 * N0);
#pragma unroll
    for (int u = 0; u < 4; u++)
#pragma unroll
        for (int v = 0; v < 4; v++)
            C[(a0 + ty * 4 + u) * N0 + (b0 + tx * 4 + v)] = acc[u][v];
}

// ------- reduce split-K + symmetrize; optionally emit Bop split (bmode -1/0/1) -------
__global__ void k_reduce_sym(int dst, int bmode) {
    int idx = blockIdx.x * 512 + threadIdx.x;
    int a = idx >> 9, b = idx & 511;
    float s1 = 0.f, s2 = 0.f;
#pragma unroll
    for (int z = 0; z < 4; z++) {
        s1 += g_part[z * N0 * N0 + idx];
        s2 += g_part[z * N0 * N0 + b * N0 + a];
    }
    float v = 0.5f * (s1 + s2);
    if (dst == 0) g_Sym[idx] = v; else g_S[idx] = v;
    if (bmode >= 0) {
        float bv = v;
        if (bmode == 1)
            bv = (b < a) ? v : ((b == a) ? 0.5f * (v - 1.0f) : 0.0f);
        __nv_bfloat16 h = __float2bfloat16(bv);
        g_Bophi[idx] = h;
        g_Boplo[idx] = __float2bfloat16(bv - __bfloat162float(h));
    }
}

// ---------------- transpose + split: sel 1:A->XT 3:G->Gt ----------------
__global__ void k_tsplit(int sel) {
    __shared__ float tile[32][33];
    const float* src = (sel == 1) ? g_A : g_G;
    __nv_bfloat16* dh = (sel == 3) ? g_Gthi : g_XThi;
    __nv_bfloat16* dl = (sel == 3) ? g_Gtlo : g_XTlo;
    int kB = blockIdx.x * 32, nB = blockIdx.y * 32;
    int tx = threadIdx.x, ty = threadIdx.y;
#pragma unroll
    for (int r = 0; r < 32; r += 8)
        tile[ty + r][tx] = src[(kB + ty + r) * N0 + nB + tx];
    __syncthreads();
#pragma unroll
    for (int r = 0; r < 32; r += 8) {
        float v = tile[tx][ty + r];
        __nv_bfloat16 h = __float2bfloat16(v);
        size_t idx = (size_t)(nB + ty + r) * KDIM + kB + tx;
        dh[idx] = h;
        dl[idx] = __float2bfloat16(v - __bfloat162float(h));
    }
}

// ---------------- row split: sel 0:M->MR 1:A->XR ----------------
__global__ void k_rsplit(int sel) {
    int gid = blockIdx.x * 256 + threadIdx.x;
    const float4* src = (const float4*)(sel ? g_A : g_M);
    __nv_bfloat162* dh = (__nv_bfloat162*)(sel ? g_XRhi : g_MRhi);
    __nv_bfloat162* dl = (__nv_bfloat162*)(sel ? g_XRlo : g_MRlo);
    float4 v = src[gid];
    __nv_bfloat16 hx = __float2bfloat16(v.x), hy = __float2bfloat16(v.y);
    __nv_bfloat16 hz = __float2bfloat16(v.z), hw = __float2bfloat16(v.w);
    dh[2 * gid]     = __nv_bfloat162(hx, hy);
    dh[2 * gid + 1] = __nv_bfloat162(hz, hw);
    dl[2 * gid]     = __nv_bfloat162(__float2bfloat16(v.x - __bfloat162float(hx)),
                                     __float2bfloat16(v.y - __bfloat162float(hy)));
    dl[2 * gid + 1] = __nv_bfloat162(__float2bfloat16(v.z - __bfloat162float(hz)),
                                     __float2bfloat16(v.w - __bfloat162float(hw)));
}

// ---------------- Bop from Linv (g_part, lower-masked) ----------------
__global__ void k_bsplit_linv() {
    int j = blockIdx.x, a = threadIdx.x;
    float v = (a <= j) ? g_part[j * N0 + a] : 0.0f;
    __nv_bfloat16 h = __float2bfloat16(v);
    g_Bophi[j * N0 + a] = h;
    g_Boplo[j * N0 + a] = __float2bfloat16(v - __bfloat162float(h));
}

// ======== 128x128-tile split-bf16 HMMA core (3-term), warp tile 32x64 ========
template <int STRIDE>
__device__ __forceinline__ void mma128(
    const __nv_bfloat16* __restrict__ Ah, const __nv_bfloat16* __restrict__ Al,
    const __nv_bfloat16* __restrict__ Bh, const __nv_bfloat16* __restrict__ Bl,
    int i0, int n0t, int kbeg, int kend, float acc[2][8][4],
    __nv_bfloat16 (*sAh)[40], __nv_bfloat16 (*sAl)[40],
    __nv_bfloat16 (*sBh)[40], __nv_bfloat16 (*sBl)[40]) {
    int t = threadIdx.x, lane = t & 31, wid = t >> 5;
    int wy = wid >> 1, wx = wid & 1;
    int r0 = t >> 2, c0 = (t & 3) * 8;      // loader: rows 0..63
    int r1 = r0 + 64;                       // rows 64..127
    int gr = lane >> 2, lc2 = (lane & 3) * 2;
    uint4 pAh0 = *(const uint4*)(Ah + (size_t)(i0 + r0) * STRIDE + kbeg + c0);
    uint4 pAh1 = *(const uint4*)(Ah + (size_t)(i0 + r1) * STRIDE + kbeg + c0);
    uint4 pAl0 = *(const uint4*)(Al + (size_t)(i0 + r0) * STRIDE + kbeg + c0);
    uint4 pAl1 = *(const uint4*)(Al + (size_t)(i0 + r1) * STRIDE + kbeg + c0);
    uint4 pBh0 = *(const uint4*)(Bh + (size_t)(n0t + r0) * STRIDE + kbeg + c0);
    uint4 pBh1 = *(const uint4*)(Bh + (size_t)(n0t + r1) * STRIDE + kbeg + c0);
    uint4 pBl0 = *(const uint4*)(Bl + (size_t)(n0t + r0) * STRIDE + kbeg + c0);
    uint4 pBl1 = *(const uint4*)(Bl + (size_t)(n0t + r1) * STRIDE + kbeg + c0);
    for (int k0 = kbeg; k0 < kend; k0 += 32) {
        *(uint4*)&sAh[r0][c0] = pAh0;
        *(uint4*)&sAh[r1][c0] = pAh1;
        *(uint4*)&sAl[r0][c0] = pAl0;
        *(uint4*)&sAl[r1][c0] = pAl1;
        *(uint4*)&sBh[r0][c0] = pBh0;
        *(uint4*)&sBh[r1][c0] = pBh1;
        *(uint4*)&sBl[r0][c0] = pBl0;
        *(uint4*)&sBl[r1][c0] = pBl1;
        __syncthreads();
        if (k0 + 32 < kend) {
            size_t ko = (size_t)(k0 + 32 + c0);
            pAh0 = *(const uint4*)(Ah + (size_t)(i0 + r0) * STRIDE + ko);
            pAh1 = *(const uint4*)(Ah + (size_t)(i0 + r1) * STRIDE + ko);
            pAl0 = *(const uint4*)(Al + (size_t)(i0 + r0) * STRIDE + ko);
            pAl1 = *(const uint4*)(Al + (size_t)(i0 + r1) * STRIDE + ko);
            pBh0 = *(const uint4*)(Bh + (size_t)(n0t + r0) * STRIDE + ko);
            pBh1 = *(const uint4*)(Bh + (size_t)(n0t + r1) * STRIDE + ko);
            pBl0 = *(const uint4*)(Bl + (size_t)(n0t + r0) * STRIDE + ko);
            pBl1 = *(const uint4*)(Bl + (size_t)(n0t + r1) * STRIDE + ko);
        }
#pragma unroll
        for (int kk = 0; kk < 32; kk += 16) {
            uint32_t ah[2][4], al[2][4], bh[8][2], bl[8][2];
#pragma unroll
            for (int mb = 0; mb < 2; mb++) {
                int r = wy * 32 + mb * 16 + gr;
                ah[mb][0] = *(const uint32_t*)&sAh[r][kk + lc2];
                ah[mb][1] = *(const uint32_t*)&sAh[r + 8][kk + lc2];
                ah[mb][2] = *(const uint32_t*)&sAh[r][kk + lc2 + 8];
                ah[mb][3] = *(const uint32_t*)&sAh[r + 8][kk + lc2 + 8];
                al[mb][0] = *(const uint32_t*)&sAl[r][kk + lc2];
                al[mb][1] = *(const uint32_t*)&sAl[r + 8][kk + lc2];
                al[mb][2] = *(const uint32_t*)&sAl[r][kk + lc2 + 8];
                al[mb][3] = *(const uint32_t*)&sAl[r + 8][kk + lc2 + 8];
            }
#pragma unroll
            for (int nb = 0; nb < 8; nb++) {
                int bn = wx * 64 + nb * 8 + gr;
                bh[nb][0] = *(const uint32_t*)&sBh[bn][kk + lc2];
                bh[nb][1] = *(const uint32_t*)&sBh[bn][kk + lc2 + 8];
                bl[nb][0] = *(const uint32_t*)&sBl[bn][kk + lc2];
                bl[nb][1] = *(const uint32_t*)&sBl[bn][kk + lc2 + 8];
            }
#pragma unroll
            for (int mb = 0; mb < 2; mb++)
#pragma unroll
                for (int nb = 0; nb < 8; nb++) {
                    MMA16(acc[mb][nb], ah[mb], bh[nb]);
                    MMA16(acc[mb][nb], ah[mb], bl[nb]);
                    MMA16(acc[mb][nb], al[mb], bh[nb]);
                }
        }
        __syncthreads();
    }
}

#define EPILOGUE_LOOP(BODY)                                                      \
    do {                                                                         \
        int lane = threadIdx.x & 31, wid = threadIdx.x >> 5;                     \
        int wy = wid >> 1, wx = wid & 1;                                         \
        int gr = lane >> 2, lc2 = (lane & 3) * 2;                                \
        _Pragma("unroll")                                                        \
        for (int mb = 0; mb < 2; mb++)                                           \
            _Pragma("unroll")                                                    \
            for (int nb = 0; nb < 8; nb++)                                       \
                _Pragma("unroll")                                                \
                for (int q = 0; q < 4; q++) {                                    \
                    int rr = i0 + wy * 32 + mb * 16 + gr + (q >> 1) * 8;         \
                    int cc = n0t + wx * 64 + nb * 8 + lc2 + (q & 1);             \
                    float a = acc[mb][nb][q];                                    \
                    BODY                                                         \
                }                                                                \
    } while (0)

// ---------------- g_A = L @ G ----------------
__global__ void __launch_bounds__(256) k_lg_mma() {
    __shared__ __align__(16) __nv_bfloat16 sAh[128][40];
    __shared__ __align__(16) __nv_bfloat16 sAl[128][40];
    __shared__ __align__(16) __nv_bfloat16 sBh[128][40];
    __shared__ __align__(16) __nv_bfloat16 sBl[128][40];
    int i0 = blockIdx.x * 128, n0t = blockIdx.y * 128;
    float acc[2][8][4] = {};
    mma128<KDIM>(g_Lhi, g_Llo, g_Gthi, g_Gtlo, i0, n0t, 0, KDIM, acc,
                 sAh, sAl, sBh, sBl);
    EPILOGUE_LOOP({ g_A[(size_t)rr * N0 + cc] = a; });
}

// ---------------- Gram: partial C = At·Bt^T over k-chunk; sel 0=MT 1=XT ----------------
__global__ void __launch_bounds__(256) k_gram_mma(int selA, int selB) {
    __shared__ __align__(16) __nv_bfloat16 sAh[128][40];
    __shared__ __align__(16) __nv_bfloat16 sAl[128][40];
    __shared__ __align__(16) __nv_bfloat16 sBh[128][40];
    __shared__ __align__(16) __nv_bfloat16 sBl[128][40];
    int i0 = blockIdx.x * 128, n0t = blockIdx.y * 128;
    int kbeg = blockIdx.z * (KDIM / 4);
    float acc[2][8][4] = {};
    mma128<KDIM>(selA ? g_XThi : g_MThi, selA ? g_XTlo : g_MTlo,
                 selB ? g_XThi : g_MThi, selB ? g_XTlo : g_MTlo,
                 i0, n0t, kbeg, kbeg + KDIM / 4, acc, sAh, sAl, sBh, sBl);
    float* C = g_part + blockIdx.z * (N0 * N0);
    EPILOGUE_LOOP({ C[(size_t)rr * N0 + cc] = a; });
}

// -- proj; mode 0: G=G-M·Bop  1: A=M+A-M·Bop  2: G=A-Q1·Bop  3: A=A·Bop (+Q1 splits) --
__global__ void __launch_bounds__(256) k_proj_mma(int mode) {
    __shared__ __align__(16) __nv_bfloat16 sAh[128][40];
    __shared__ __align__(16) __nv_bfloat16 sAl[128][40];
    __shared__ __align__(16) __nv_bfloat16 sBh[128][40];
    __shared__ __align__(16) __nv_bfloat16 sBl[128][40];
    int i0 = blockIdx.x * 128, n0t = blockIdx.y * 128;
    float acc[2][8][4] = {};
    const __nv_bfloat16* Ah = (mode == 2) ? g_Gthi : (mode == 3) ? g_XRhi : g_MRhi;
    const __nv_bfloat16* Al = (mode == 2) ? g_Gtlo : (mode == 3) ? g_XRlo : g_MRlo;
    mma128<N0>(Ah, Al, g_Bophi, g_Boplo, i0, n0t, 0, N0, acc, sAh, sAl, sBh, sBl);
    if (mode == 0) {
        EPILOGUE_LOOP({
            size_t idx = (size_t)rr * N0 + cc;
            g_G[idx] = g_G[idx] - a;
        });
    } else if (mode == 1) {
        EPILOGUE_LOOP({
            size_t idx = (size_t)rr * N0 + cc;
            g_A[idx] = g_M[idx] + g_A[idx] - a;
        });
    } else if (mode == 2) {
        EPILOGUE_LOOP({
            size_t idx = (size_t)rr * N0 + cc;
            g_G[idx] = g_A[idx] - a;
        });
    } else {
        EPILOGUE_LOOP({
            size_t idx = (size_t)rr * N0 + cc;
            g_A[idx] = a;
            __nv_bfloat16 h = __float2bfloat16(a);
            g_Gthi[idx] = h;
            g_Gtlo[idx] = __float2bfloat16(a - __bfloat162float(h));
        });
    }
}

// ---------------- x[i] = clip(log(|rowsumsq(G)|)/10, -1, 1) ----------------
__global__ void k_rowsq() {
    int gt = blockIdx.x * 256 + threadIdx.x;
    int row = gt >> 5, lane = gt & 31;
    const float4* rp = (const float4*)&g_G[row * N0];
    float s = 0.f;
#pragma unroll 4
    for (int c = lane; c < 128; c += 32) {
        float4 v = rp[c];
        s += v.x * v.x + v.y * v.y + v.z * v.z + v.w * v.w;
    }
#pragma unroll
    for (int o = 16; o; o >>= 1) s += __shfl_xor_sync(0xffffffffu, s, o);
    if (lane == 0) {
        float x = logf(fabsf(s)) * 0.1f;
        g_x[row] = fminf(1.0f, fmaxf(-1.0f, x));
    }
}

// ---------------- 2-layer LSTM ----------------
__global__ void k_lstm(const float* __restrict__ Lh0, const float* __restrict__ Lc0,
                       const float* __restrict__ Wih0, const float* __restrict__ Whh0,
                       const float* __restrict__ bih0, const float* __restrict__ bhh0,
                       const float* __restrict__ Wih1, const float* __restrict__ Whh1,
                       const float* __restrict__ bih1, const float* __restrict__ bhh1,
                       const float* __restrict__ Wl, const float* __restrict__ bl,
                       float* __restrict__ out) {
    __shared__ float sWih0[80], sWhh0[1600], sb0[80];
    __shared__ float sWih1[1600], sWhh1[1600], sb1[80];
    __shared__ float sWl[20], sbl[1];
    int t = threadIdx.x;
    for (int i = t; i < 80; i += 256) {
        sWih0[i] = Wih0[i];
        sb0[i] = bih0[i] + bhh0[i];
        sb1[i] = bih1[i] + bhh1[i];
    }
    for (int i = t; i < 1600; i += 256) {
        sWhh0[i] = Whh0[i];
        sWih1[i] = Wih1[i];
        sWhh1[i] = Whh1[i];
    }
    if (t < 20) sWl[t] = Wl[t];
    if (t == 0) sbl[0] = bl[0];
    __syncthreads();

    int i = blockIdx.x * 256 + t;
    float x = g_x[i];
    float h0p[20], h1p[20], h0n[20];
#pragma unroll
    for (int h = 0; h < 20; h++) {
        h0p[h] = Lh0[i * 20 + h];
        h1p[h] = Lh0[92160 + i * 20 + h];
    }
#pragma unroll
    for (int h = 0; h < 20; h++) {
        float pi = sb0[h]      + x * sWih0[h];
        float pf = sb0[20 + h] + x * sWih0[20 + h];
        float pg = sb0[40 + h] + x * sWih0[40 + h];
        float po = sb0[60 + h] + x * sWih0[60 + h];
#pragma unroll
        for (int m = 0; m < 20; m++) {
            float hm = h0p[m];
            pi += hm * sWhh0[h * 20 + m];
            pf += hm * sWhh0[(20 + h) * 20 + m];
            pg += hm * sWhh0[(40 + h) * 20 + m];
            po += hm * sWhh0[(60 + h) * 20 + m];
        }
        float c0 = Lc0[i * 20 + h];
        float c = sigf(pf) * c0 + sigf(pi) * tanhf(pg);
        float hh = sigf(po) * tanhf(c);
        h0n[h] = hh;
        out[O_H + i * 20 + h] = hh;
        out[O_C + i * 20 + h] = c;
    }
    float lacc = sbl[0];
#pragma unroll
    for (int h = 0; h < 20; h++) {
        float pi = sb1[h], pf = sb1[20 + h], pg = sb1[40 + h], po = sb1[60 + h];
#pragma unroll
        for (int m = 0; m < 20; m++) {
            float a = h0n[m], b = h1p[m];
            pi += a * sWih1[h * 20 + m]        + b * sWhh1[h * 20 + m];
            pf += a * sWih1[(20 + h) * 20 + m] + b * sWhh1[(20 + h) * 20 + m];
            pg += a * sWih1[(40 + h) * 20 + m] + b * sWhh1[(40 + h) * 20 + m];
            po += a * sWih1[(60 + h) * 20 + m] + b * sWhh1[(60 + h) * 20 + m];
        }
        float c1 = Lc0[92160 + i * 20 + h];
        float c = sigf(pf) * c1 + sigf(pi) * tanhf(pg);
        float hh = sigf(po) * tanhf(c);
        out[O_H + 92160 + i * 20 + h] = hh;
        out[O_C + 92160 + i * 20 + h] = c;
        lacc += hh * sWl[h];
    }
    g_lraw[i] = lacc * 0.1f;
}

__global__ void k_mean() {
    __shared__ float sm[256];
    int t = threadIdx.x;
    float s = 0.f;
    for (int i = t; i < KDIM; i += 256) s += g_lraw[i];
    sm[t] = s;
    __syncthreads();
    for (int o = 128; o; o >>= 1) {
        if (t < o) sm[t] += sm[t + o];
        __syncthreads();
    }
    if (t == 0) g_mean = sm[0] * (1.0f / KDIM);
}

// ---------------- L (fp32 out + split-bf16) ----------------
__global__ void k_build_L(const float4* __restrict__ Lb, float4* __restrict__ outL) {
    int gid = blockIdx.x * 256 + threadIdx.x;
    int base = gid * 4;
    int i = base / KDIM;
    int j0 = base - i * KDIM;
    float dv = g_lraw[i] - g_mean + 1.0f;
    float4 lb = Lb[gid];
    float4 r;
    r.x = fmaxf((j0 + 0 == i) ? dv : 0.0f, lb.x);
    r.y = fmaxf((j0 + 1 == i) ? dv : 0.0f, lb.y);
    r.z = fmaxf((j0 + 2 == i) ? dv : 0.0f, lb.z);
    r.w = fmaxf((j0 + 3 == i) ? dv : 0.0f, lb.w);
    outL[gid] = r;
    __nv_bfloat16 hx = __float2bfloat16(r.x), hy = __float2bfloat16(r.y);
    __nv_bfloat16 hz = __float2bfloat16(r.z), hw = __float2bfloat16(r.w);
    __nv_bfloat162* ph = (__nv_bfloat162*)g_Lhi;
    __nv_bfloat162* pl = (__nv_bfloat162*)g_Llo;
    ph[2 * gid]     = __nv_bfloat162(hx, hy);
    ph[2 * gid + 1] = __nv_bfloat162(hz, hw);
    pl[2 * gid]     = __nv_bfloat162(__float2bfloat16(r.x - __bfloat162float(hx)),
                                     __float2bfloat16(r.y - __bfloat162float(hy)));
    pl[2 * gid + 1] = __nv_bfloat162(__float2bfloat16(r.z - __bfloat162float(hz)),
                                     __float2bfloat16(r.w - __bfloat162float(hw)));
}

// ---------------- left-looking blocked Cholesky: one launch per panel ----------------
__global__ void k_chol_left(int p) {
    __shared__ float S1[64][65];
    __shared__ float S2[64][65];
    int bi = p + blockIdx.x;
    int t = threadIdx.x, ty = t >> 4, tx = t & 15;
    float accC[4][4], accD[4][4];
#pragma unroll
    for (int u = 0; u < 4; u++)
#pragma unroll
        for (int v = 0; v < 4; v++) {
            accC[u][v] = g_S[(bi * 64 + ty * 4 + u) * N0 + p * 64 + tx * 4 + v];
            accD[u][v] = g_S[(p * 64 + ty * 4 + u) * N0 + p * 64 + tx * 4 + v];
        }
    for (int kb = 0; kb < p; kb++) {
        for (int idx = t; idx < 4096; idx += 256) {
            int r = idx >> 6, c = idx & 63;
            S1[r][c] = g_S[(bi * 64 + r) * N0 + kb * 64 + c];
            S2[r][c] = g_S[(p * 64 + r) * N0 + kb * 64 + c];
        }
        __syncthreads();
#pragma unroll 8
        for (int k = 0; k < 64; k++) {
            float lb_[4], lp_[4], lpr[4];
#pragma unroll
            for (int u = 0; u < 4; u++) {
                lb_[u] = S1[ty * 4 + u][k];
                lp_[u] = S2[tx * 4 + u][k];
                lpr[u] = S2[ty * 4 + u][k];
            }
#pragma unroll
            for (int u = 0; u < 4; u++)
#pragma unroll
                for (int v = 0; v < 4; v++) {
                    accC[u][v] -= lb_[u] * lp_[v];
                    accD[u][v] -= lpr[u] * lp_[v];
                }
        }
        __syncthreads();
    }
#pragma unroll
    for (int u = 0; u < 4; u++)
#pragma unroll
        for (int v = 0; v < 4; v++) {
            S1[ty * 4 + u][tx * 4 + v] = accD[u][v];
            S2[ty * 4 + u][tx * 4 + v] = accC[u][v];
        }
    __syncthreads();
    for (int j = 0; j < 64; j++) {
        if (t == 0) S1[j][j] = sqrtf(S1[j][j]);
        __syncthreads();
        float dj = S1[j][j];
        for (int r = j + 1 + t; r < 64; r += 256) S1[r][j] /= dj;
        __syncthreads();
        for (int idx = t; idx < 4096; idx += 256) {
            int r = idx >> 6, c = idx & 63;
            if (c > j && r >= c) S1[r][c] -= S1[r][j] * S1[c][j];
        }
        __syncthreads();
    }
    if (bi == p) {
        for (int idx = t; idx < 4096; idx += 256) {
            int r = idx >> 6, c = idx & 63;
            g_S[(p * 64 + r) * N0 + p * 64 + c] = S1[r][c];
        }
        return;
    }
    for (int j = 0; j < 64; j++) {
        float inv = 1.0f / S1[j][j];
        if (t < 64) S2[t][j] *= inv;
        __syncthreads();
        for (int idx = t; idx < 4096; idx += 256) {
            int r = idx >> 6, c = idx & 63;
            if (c > j) S2[r][c] -= S2[r][j] * S1[c][j];
        }
        __syncthreads();
    }
    for (int idx = t; idx < 4096; idx += 256) {
        int r = idx >> 6, c = idx & 63;
        g_S[(bi * 64 + r) * N0 + p * 64 + c] = S2[r][c];
    }
}

// ---------------- triangular inverse of L by diagonal sweep; Linv -> g_part --------
__global__ void k_trinv(int d) {
    __shared__ float S1[64][65];
    __shared__ float S2[64][65];
    int j = blockIdx.x, i = j + d;
    int t = threadIdx.x;
    if (d == 0) {
        for (int idx = t; idx < 4096; idx += 256) {
            int r = idx >> 6, c = idx & 63;
            S1[r][c] = g_S[(i * 64 + r) * N0 + i * 64 + c];
        }
        __syncthreads();
        if (t < 64) {
            int c = t;
            for (int r = 0; r < 64; r++) {
                if (r < c) { S2[r][c] = 0.0f; continue; }
                float s = (r == c) ? 1.0f : 0.0f;
                for (int k = c; k < r; k++) s -= S1[r][k] * S2[k][c];
                S2[r][c] = s / S1[r][r];
            }
        }
        __syncthreads();
        for (int idx = t; idx < 4096; idx += 256) {
            int r = idx >> 6, c = idx & 63;
            g_part[(i * 64 + r) * N0 + i * 64 + c] = S2[r][c];
        }
    } else {
        int ty = t >> 4, tx = t & 15;
        float acc[4][4] = {};
        for (int kb = j; kb < i; kb++) {
            for (int idx = t; idx < 4096; idx += 256) {
                int r = idx >> 6, c = idx & 63;
                S1[r][c] = g_S[(i * 64 + r) * N0 + kb * 64 + c];
                S2[r][c] = g_part[(kb * 64 + r) * N0 + j * 64 + c];
            }
            __syncthreads();
#pragma unroll 8
            for (int k = 0; k < 64; k++)
#pragma unroll
                for (int u = 0; u < 4; u++)
#pragma unroll
                    for (int v = 0; v < 4; v++)
                        acc[u][v] += S1[ty * 4 + u][k] * S2[k][tx * 4 + v];
            __syncthreads();
        }
#pragma unroll
        for (int u = 0; u < 4; u++)
#pragma unroll
            for (int v = 0; v < 4; v++)
                S2[ty * 4 + u][tx * 4 + v] = acc[u][v];
        for (int idx = t; idx < 4096; idx += 256) {
            int r = idx >> 6, c = idx & 63;
            S1[r][c] = g_part[(i * 64 + r) * N0 + i * 64 + c];
        }
        __syncthreads();
        float outv[4][4] = {};
#pragma unroll 8
        for (int m = 0; m < 64; m++)
#pragma unroll
            for (int u = 0; u < 4; u++)
#pragma unroll
                for (int v = 0; v < 4; v++)
                    outv[u][v] -= S1[ty * 4 + u][m] * S2[m][tx * 4 + v];
#pragma unroll
        for (int u = 0; u < 4; u++)
#pragma unroll
            for (int v = 0; v < 4; v++)
                g_part[(i * 64 + ty * 4 + u) * N0 + j * 64 + tx * 4 + v] = outv[u][v];
    }
}

// ---------------- new_s = Q2^T ----------------
__global__ void k_write_s(float* __restrict__ outS) {
    __shared__ float tile[32][33];
    int kB = blockIdx.x * 32, nB = blockIdx.y * 32;
    int tx = threadIdx.x, ty = threadIdx.y;
#pragma unroll
    for (int r = 0; r < 32; r += 8)
        tile[ty + r][tx] = g_G[(kB + ty + r) * N0 + nB + tx];
    __syncthreads();
#pragma unroll
    for (int r = 0; r < 32; r += 8)
        outS[(nB + ty + r) * KDIM + kB + tx] = tile[tx][ty + r];
}

extern "C" void kernel_launch(void* const* d_in, const int* in_sizes, int n_in,
                              void* d_out, int out_size) {
    const float* e    = (const float*)d_in[0];
    const float* eg   = (const float*)d_in[1];
    const float* s    = (const float*)d_in[2];
    const float* sg   = (const float*)d_in[3];
    const float* Lh0  = (const float*)d_in[4];
    const float* Lc0  = (const float*)d_in[5];
    const float* Lb   = (const float*)d_in[6];
    const float* Wih0 = (const float*)d_in[7];
    const float* Whh0 = (const float*)d_in[8];
    const float* bih0 = (const float*)d_in[9];
    const float* bhh0 = (const float*)d_in[10];
    const float* Wih1 = (const float*)d_in[11];
    const float* Whh1 = (const float*)d_in[12];
    const float* bih1 = (const float*)d_in[13];
    const float* bhh1 = (const float*)d_in[14];
    const float* Wl   = (const float*)d_in[15];
    const float* bl   = (const float*)d_in[16];
    const float* e_lr = (const float*)d_in[17];
    const float* s_lr = (const float*)d_in[18];
    float* out = (float*)d_out;

    k_update_e<<<16384, 256>>>((const float4*)e, (const float4*)eg, e_lr,
                               (float4*)(out + O_E));
    k_make_MMg<<<dim3(144, 16), dim3(32, 8)>>>(s, sg, s_lr);
    k_stsplit<<<2304, 256>>>((const float4*)s, s_lr, 0);   // M^T  -> MT
    k_stsplit<<<2304, 256>>>((const float4*)sg, s_lr, 1);  // Mg^T -> XT
    k_rsplit<<<2304, 256>>>(0);                            // M rows -> MR
    // Sym = sym(M^T Mg) (+Bop); G = Mg - M @ Sym
    k_gram_mma<<<dim3(4, 4, 4), 256>>>(0, 1);
    k_reduce_sym<<<512, 512>>>(0, 0);
    k_proj_mma<<<dim3(36, 4), 256>>>(0);
    // LogAndSign -> LSTM -> L
    k_rowsq<<<576, 256>>>();
    k_lstm<<<18, 256>>>(Lh0, Lc0, Wih0, Whh0, bih0, bhh0,
                        Wih1, Whh1, bih1, bhh1, Wl, bl, out);
    k_mean<<<1, 256>>>();
    k_build_L<<<20736, 256>>>((const float4*)Lb, (float4*)(out + O_L));
    // LG on tensor cores
    k_tsplit<<<dim3(144, 16), dim3(32, 8)>>>(3);           // G^T -> Gt
    k_lg_mma<<<dim3(36, 4), 256>>>();
    // A = M + LG - M @ sym(M^T LG)
    k_tsplit<<<dim3(144, 16), dim3(32, 8)>>>(1);           // LG^T -> XT
    k_gram_mma<<<dim3(4, 4, 4), 256>>>(0, 1);
    k_reduce_sym<<<512, 512>>>(0, 0);
    k_proj_mma<<<dim3(36, 4), 256>>>(1);
    // CholQR pass 1: fp32 Gram -> chol (8) -> L^{-1} (8) -> Q1 = A·Linv^T
    k_gemm_tn<<<dim3(8, 8, 4), 256>>>();
    k_reduce_sym<<<512, 512>>>(1, -1);
    for (int p = 0; p < 8; p++) k_chol_left<<<8 - p, 256>>>(p);
    for (int d = 0; d < 8; d++) k_trinv<<<8 - d, 256>>>(d);
    k_bsplit_linv<<<512, 512>>>();
    k_rsplit<<<2304, 256>>>(1);                            // A rows -> XR
    k_proj_mma<<<dim3(36, 4), 256>>>(3);                   // Q1 (+row splits into Gt)
    // Newton pass 2: E-gram (+U), Q2 = Q1 - Q1 U
    k_tsplit<<<dim3(144, 16), dim3(32, 8)>>>(1);           // Q1^T -> XT
    k_gram_mma<<<dim3(4, 4, 4), 256>>>(1, 1);
    k_reduce_sym<<<512, 512>>>(0, 1);
    k_proj_mma<<<dim3(36, 4), 256>>>(2);
    // new_s
    k_write_s<<<dim3(144, 16), dim3(32, 8)>>>(out + O_S);
}